// round 2
// baseline (speedup 1.0000x reference)
#include <cuda_runtime.h>
#include <cuda_bf16.h>
#include <math.h>

// ---------------------------------------------------------------------------
// Problem constants
// ---------------------------------------------------------------------------
#define BATCH     4
#define SEQLEN    1024
#define VOCAB     28
#define D_MODEL   1024
#define N_LAYERS  4
#define D_INNER   2048
#define D_STATE   16
#define DT_RANK   64
#define D_CONV    4
#define NUM_CLS   2
#define ROWS      (BATCH * SEQLEN)          // 4096

// ---------------------------------------------------------------------------
// Scratch buffers (device globals; no runtime allocation allowed)
// ---------------------------------------------------------------------------
__device__ float g_h    [ROWS * D_MODEL];        // residual stream        16 MB
__device__ float g_xn   [ROWS * D_MODEL];        // rmsnorm out / dec tmp  16 MB
__device__ float g_xz   [ROWS * 2 * D_INNER];    // in_proj out            64 MB
__device__ float g_xc   [ROWS * D_INNER];        // conv+silu out          32 MB
__device__ float g_dbc  [ROWS * (DT_RANK + 2*D_STATE)]; // x_proj out      1.5 MB
__device__ float g_delta[ROWS * D_INNER];        // softplus(dt)           32 MB
__device__ float g_y    [ROWS * D_INNER];        // scan out (gated)       32 MB

// ---------------------------------------------------------------------------
// Embedding + positional encoding
// ---------------------------------------------------------------------------
__global__ void embed_kernel(const int* __restrict__ x,
                             const float* __restrict__ emb,
                             const float* __restrict__ pos,
                             float* __restrict__ out)
{
    int idx = blockIdx.x * blockDim.x + threadIdx.x;           // over ROWS*D_MODEL
    if (idx >= ROWS * D_MODEL) return;
    int d = idx & (D_MODEL - 1);
    int r = idx >> 10;           // D_MODEL = 1024
    int l = r & (SEQLEN - 1);
    int tok = x[r];
    out[idx] = emb[tok * D_MODEL + d] + pos[l * D_MODEL + d];
}

// ---------------------------------------------------------------------------
// RMSNorm (one block per row)
// ---------------------------------------------------------------------------
__global__ void rmsnorm_kernel(const float* __restrict__ h,
                               const float* __restrict__ w,
                               float* __restrict__ out)
{
    int r = blockIdx.x;
    const float* row = h + (size_t)r * D_MODEL;
    int tid = threadIdx.x;

    float s = 0.f;
    #pragma unroll
    for (int i = tid; i < D_MODEL; i += 256) { float v = row[i]; s += v * v; }

    __shared__ float red[8];
    // warp reduce
    #pragma unroll
    for (int o = 16; o > 0; o >>= 1) s += __shfl_down_sync(0xffffffffu, s, o);
    if ((tid & 31) == 0) red[tid >> 5] = s;
    __syncthreads();
    __shared__ float scale;
    if (tid == 0) {
        float t = 0.f;
        #pragma unroll
        for (int i = 0; i < 8; i++) t += red[i];
        scale = rsqrtf(t * (1.0f / D_MODEL) + 1e-5f);
    }
    __syncthreads();
    float sc = scale;
    #pragma unroll
    for (int i = tid; i < D_MODEL; i += 256)
        out[(size_t)r * D_MODEL + i] = row[i] * sc * w[i];
}

// ---------------------------------------------------------------------------
// Generic NT GEMM: C[M,N] = A[M,K] (row-major, lda) * B[N,K]^T (row-major, ldb)
// Epilogue: 0 = store, 1 = C += v, 2 = relu(v+bias), 3 = v+bias, 4 = softplus(v+bias)
// ---------------------------------------------------------------------------
#define GBM 128
#define GBN 128
#define GBK 8

template <int EPI>
__global__ void __launch_bounds__(256, 2) gemm_nt(
    const float* __restrict__ A, int lda,
    const float* __restrict__ B, int ldb,
    float* __restrict__ C, int ldc,
    int M, int N, int K,
    const float* __restrict__ bias)
{
    __shared__ float As[GBK][GBM];
    __shared__ float Bs[GBK][GBN];

    int tid = threadIdx.x;
    int tx = tid & 15;
    int ty = tid >> 4;
    int bm = blockIdx.y * GBM;
    int bn = blockIdx.x * GBN;

    int lrow = tid >> 1;          // 0..127
    int lkc  = (tid & 1) * 4;     // 0 or 4

    float acc[8][8];
    #pragma unroll
    for (int i = 0; i < 8; i++)
        #pragma unroll
        for (int j = 0; j < 8; j++) acc[i][j] = 0.f;

    int nkt = (K + GBK - 1) / GBK;
    for (int kt = 0; kt < nkt; kt++) {
        int k0 = kt * GBK;
        // A tile
        {
            int gm = bm + lrow;
            float4 v = make_float4(0.f, 0.f, 0.f, 0.f);
            if (gm < M && (k0 + lkc + 3) < K)
                v = *(const float4*)(A + (size_t)gm * lda + k0 + lkc);
            As[lkc + 0][lrow] = v.x; As[lkc + 1][lrow] = v.y;
            As[lkc + 2][lrow] = v.z; As[lkc + 3][lrow] = v.w;
        }
        // B tile
        {
            int gn = bn + lrow;
            float4 v = make_float4(0.f, 0.f, 0.f, 0.f);
            if (gn < N && (k0 + lkc + 3) < K)
                v = *(const float4*)(B + (size_t)gn * ldb + k0 + lkc);
            Bs[lkc + 0][lrow] = v.x; Bs[lkc + 1][lrow] = v.y;
            Bs[lkc + 2][lrow] = v.z; Bs[lkc + 3][lrow] = v.w;
        }
        __syncthreads();

        #pragma unroll
        for (int k = 0; k < GBK; k++) {
            float4 a0 = *(const float4*)&As[k][ty * 4];
            float4 a1 = *(const float4*)&As[k][64 + ty * 4];
            float4 b0 = *(const float4*)&Bs[k][tx * 4];
            float4 b1 = *(const float4*)&Bs[k][64 + tx * 4];
            float av[8] = {a0.x, a0.y, a0.z, a0.w, a1.x, a1.y, a1.z, a1.w};
            float bv[8] = {b0.x, b0.y, b0.z, b0.w, b1.x, b1.y, b1.z, b1.w};
            #pragma unroll
            for (int i = 0; i < 8; i++)
                #pragma unroll
                for (int j = 0; j < 8; j++)
                    acc[i][j] = fmaf(av[i], bv[j], acc[i][j]);
        }
        __syncthreads();
    }

    #pragma unroll
    for (int i = 0; i < 8; i++) {
        int m = bm + ((i < 4) ? (ty * 4 + i) : (64 + ty * 4 + i - 4));
        if (m >= M) continue;
        #pragma unroll
        for (int j = 0; j < 8; j++) {
            int n = bn + ((j < 4) ? (tx * 4 + j) : (64 + tx * 4 + j - 4));
            if (n >= N) continue;
            float v = acc[i][j];
            size_t idx = (size_t)m * ldc + n;
            if (EPI == 0) {
                C[idx] = v;
            } else if (EPI == 1) {
                C[idx] += v;
            } else if (EPI == 2) {
                v += bias[n];
                C[idx] = v > 0.f ? v : 0.f;
            } else if (EPI == 3) {
                C[idx] = v + bias[n];
            } else {
                v += bias[n];
                C[idx] = (v > 20.f) ? v : log1pf(__expf(v));
            }
        }
    }
}

// ---------------------------------------------------------------------------
// Causal depthwise conv (width 4) + bias + SiLU.
// in:  g_xz[:, 0:D_INNER]  (row stride 2*D_INNER)
// out: g_xc (row stride D_INNER)
// ---------------------------------------------------------------------------
__global__ void conv_silu_kernel(const float* __restrict__ xz,
                                 const float* __restrict__ cw,
                                 const float* __restrict__ cb,
                                 float* __restrict__ xc)
{
    int idx = blockIdx.x * blockDim.x + threadIdx.x;   // over ROWS*D_INNER
    if (idx >= ROWS * D_INNER) return;
    int d = idx & (D_INNER - 1);
    int r = idx >> 11;                 // D_INNER = 2048
    int l = r & (SEQLEN - 1);
    int b = r >> 10;

    float w0 = cw[d * 4 + 0], w1 = cw[d * 4 + 1], w2 = cw[d * 4 + 2], w3 = cw[d * 4 + 3];
    size_t base = ((size_t)b * SEQLEN) * (2 * D_INNER) + d;
    float acc = cb[d];
    if (l >= 3) acc = fmaf(xz[base + (size_t)(l - 3) * (2 * D_INNER)], w0, acc);
    if (l >= 2) acc = fmaf(xz[base + (size_t)(l - 2) * (2 * D_INNER)], w1, acc);
    if (l >= 1) acc = fmaf(xz[base + (size_t)(l - 1) * (2 * D_INNER)], w2, acc);
    acc = fmaf(xz[base + (size_t)l * (2 * D_INNER)], w3, acc);
    // silu
    float s = acc / (1.f + __expf(-acc));
    xc[idx] = s;
}

// ---------------------------------------------------------------------------
// Selective scan. 16 lanes = 16 states per channel; 2 channels per warp.
// Fuses y = (scan + D*xc) * silu(z).
// ---------------------------------------------------------------------------
__global__ void scan_kernel(const float* __restrict__ delta,
                            const float* __restrict__ xc,
                            const float* __restrict__ dbc,
                            const float* __restrict__ xz,
                            const float* __restrict__ A_log,
                            const float* __restrict__ Dp,
                            float* __restrict__ yout)
{
    int gwarp = (blockIdx.x * blockDim.x + threadIdx.x) >> 5;
    int lane = threadIdx.x & 31;
    int n = lane & 15;
    int pair = gwarp * 2 + (lane >> 4);        // b * D_INNER + d
    int b = pair >> 11;
    int d = pair & (D_INNER - 1);
    if (b >= BATCH) return;

    float An = -__expf(A_log[d * D_STATE + n]);
    float Dv = Dp[d];
    float h = 0.f;

    size_t rbase = (size_t)b * SEQLEN;
    for (int l = 0; l < SEQLEN; l++) {
        size_t r = rbase + l;
        float dlt = delta[r * D_INNER + d];
        float xcv = xc[r * D_INNER + d];
        float Bv = dbc[r * 96 + DT_RANK + n];
        float Cv = dbc[r * 96 + DT_RANK + D_STATE + n];
        float dA = __expf(dlt * An);
        h = fmaf(dA, h, dlt * xcv * Bv);
        float y = h * Cv;
        y += __shfl_xor_sync(0xffffffffu, y, 1);
        y += __shfl_xor_sync(0xffffffffu, y, 2);
        y += __shfl_xor_sync(0xffffffffu, y, 4);
        y += __shfl_xor_sync(0xffffffffu, y, 8);
        if (n == 0) {
            float zv = xz[r * (2 * D_INNER) + D_INNER + d];
            float sz = zv / (1.f + __expf(-zv));
            yout[r * D_INNER + d] = (y + Dv * xcv) * sz;
        }
    }
}

// ---------------------------------------------------------------------------
// Classifier head on h[:, -1, :] (tiny: 4 rows)
// ---------------------------------------------------------------------------
__global__ void cls_kernel(const float* __restrict__ h,
                           const float* __restrict__ w1, const float* __restrict__ b1,
                           const float* __restrict__ w2, const float* __restrict__ b2,
                           float* __restrict__ out)
{
    __shared__ float sh[D_MODEL];
    __shared__ float t1[D_MODEL];
    __shared__ float red[256];
    int b = blockIdx.x, tid = threadIdx.x;
    const float* row = h + ((size_t)b * SEQLEN + (SEQLEN - 1)) * D_MODEL;
    for (int i = tid; i < D_MODEL; i += 256) sh[i] = row[i];
    __syncthreads();
    for (int e = tid; e < D_MODEL; e += 256) {
        const float* wr = w1 + (size_t)e * D_MODEL;
        float acc = b1[e];
        #pragma unroll 4
        for (int k = 0; k < D_MODEL; k += 4) {
            float4 w4 = *(const float4*)(wr + k);
            acc = fmaf(sh[k], w4.x, acc);
            acc = fmaf(sh[k + 1], w4.y, acc);
            acc = fmaf(sh[k + 2], w4.z, acc);
            acc = fmaf(sh[k + 3], w4.w, acc);
        }
        t1[e] = acc > 0.f ? acc : 0.f;
    }
    __syncthreads();
    for (int c = 0; c < NUM_CLS; c++) {
        float p = 0.f;
        for (int k = tid; k < D_MODEL; k += 256) p = fmaf(t1[k], w2[c * D_MODEL + k], p);
        red[tid] = p;
        __syncthreads();
        for (int s = 128; s > 0; s >>= 1) {
            if (tid < s) red[tid] += red[tid + s];
            __syncthreads();
        }
        if (tid == 0) out[b * NUM_CLS + c] = red[0] + b2[c];
        __syncthreads();
    }
}

// ---------------------------------------------------------------------------
// Launch
// ---------------------------------------------------------------------------
static inline dim3 gemm_grid(int M, int N)
{
    return dim3((N + GBN - 1) / GBN, (M + GBM - 1) / GBM);
}

extern "C" void kernel_launch(void* const* d_in, const int* in_sizes, int n_in,
                              void* d_out, int out_size)
{
    const int*   x_tok     = (const int*)d_in[0];
    const float* embedding = (const float*)d_in[1];
    const float* pos_enc   = (const float*)d_in[2];
    const float* norm_w    = (const float*)d_in[3];
    const float* in_proj_w = (const float*)d_in[4];
    const float* conv_w    = (const float*)d_in[5];
    const float* conv_b    = (const float*)d_in[6];
    const float* x_proj_w  = (const float*)d_in[7];
    const float* dt_proj_w = (const float*)d_in[8];
    const float* dt_proj_b = (const float*)d_in[9];
    const float* A_log     = (const float*)d_in[10];
    const float* Dp        = (const float*)d_in[11];
    const float* out_proj_w= (const float*)d_in[12];
    const float* cls_fc1_w = (const float*)d_in[13];
    const float* cls_fc1_b = (const float*)d_in[14];
    const float* cls_fc2_w = (const float*)d_in[15];
    const float* cls_fc2_b = (const float*)d_in[16];
    const float* dec_fc1_w = (const float*)d_in[17];
    const float* dec_fc1_b = (const float*)d_in[18];
    const float* dec_fc2_w = (const float*)d_in[19];
    const float* dec_fc2_b = (const float*)d_in[20];

    float *h, *xn, *xz, *xc, *dbc, *delta, *y;
    cudaGetSymbolAddress((void**)&h, g_h);
    cudaGetSymbolAddress((void**)&xn, g_xn);
    cudaGetSymbolAddress((void**)&xz, g_xz);
    cudaGetSymbolAddress((void**)&xc, g_xc);
    cudaGetSymbolAddress((void**)&dbc, g_dbc);
    cudaGetSymbolAddress((void**)&delta, g_delta);
    cudaGetSymbolAddress((void**)&y, g_y);

    float* out_dec = (float*)d_out;                       // (4,1024,28)
    float* out_cls = (float*)d_out + ROWS * VOCAB;        // (4,2)

    // Embedding + pos
    embed_kernel<<<(ROWS * D_MODEL + 255) / 256, 256>>>(x_tok, embedding, pos_enc, h);

    for (int l = 0; l < N_LAYERS; l++) {
        const float* inw = in_proj_w + (size_t)l * (2 * D_INNER) * D_MODEL;
        const float* cw  = conv_w   + (size_t)l * D_INNER * D_CONV;
        const float* cb  = conv_b   + (size_t)l * D_INNER;
        const float* xpw = x_proj_w + (size_t)l * 96 * D_INNER;
        const float* dtw = dt_proj_w+ (size_t)l * D_INNER * DT_RANK;
        const float* dtb = dt_proj_b+ (size_t)l * D_INNER;
        const float* al  = A_log    + (size_t)l * D_INNER * D_STATE;
        const float* dp  = Dp       + (size_t)l * D_INNER;
        const float* ow  = out_proj_w + (size_t)l * D_MODEL * D_INNER;
        const float* nw  = norm_w   + (size_t)l * D_MODEL;

        // 1. rmsnorm
        rmsnorm_kernel<<<ROWS, 256>>>(h, nw, xn);
        // 2. xz = xn @ in_proj_w^T
        gemm_nt<0><<<gemm_grid(ROWS, 2 * D_INNER), 256>>>(
            xn, D_MODEL, inw, D_MODEL, xz, 2 * D_INNER,
            ROWS, 2 * D_INNER, D_MODEL, nullptr);
        // 3. conv + silu
        conv_silu_kernel<<<(ROWS * D_INNER + 255) / 256, 256>>>(xz, cw, cb, xc);
        // 4. dbc = xc @ x_proj_w^T
        gemm_nt<0><<<gemm_grid(ROWS, 96), 256>>>(
            xc, D_INNER, xpw, D_INNER, dbc, 96,
            ROWS, 96, D_INNER, nullptr);
        // 5. delta = softplus(dbc[:, :64] @ dt_proj_w^T + dt_b)
        gemm_nt<4><<<gemm_grid(ROWS, D_INNER), 256>>>(
            dbc, 96, dtw, DT_RANK, delta, D_INNER,
            ROWS, D_INNER, DT_RANK, dtb);
        // 6. selective scan (+ gate)
        scan_kernel<<<(BATCH * D_INNER / 2 + 7) / 8, 256>>>(
            delta, xc, dbc, xz, al, dp, y);
        // 7. h += y @ out_proj_w^T
        gemm_nt<1><<<gemm_grid(ROWS, D_MODEL), 256>>>(
            y, D_INNER, ow, D_INNER, h, D_MODEL,
            ROWS, D_MODEL, D_INNER, nullptr);
    }

    // Decoder MLP: t = relu(h @ W1^T + b1); x_dec = t @ W2^T + b2
    gemm_nt<2><<<gemm_grid(ROWS, D_MODEL), 256>>>(
        h, D_MODEL, dec_fc1_w, D_MODEL, xn, D_MODEL,
        ROWS, D_MODEL, D_MODEL, dec_fc1_b);
    gemm_nt<3><<<gemm_grid(ROWS, VOCAB), 256>>>(
        xn, D_MODEL, dec_fc2_w, D_MODEL, out_dec, VOCAB,
        ROWS, VOCAB, D_MODEL, dec_fc2_b);

    // Classifier head
    cls_kernel<<<BATCH, 256>>>(h, cls_fc1_w, cls_fc1_b, cls_fc2_w, cls_fc2_b, out_cls);
}

// round 7
// speedup vs baseline: 1.1488x; 1.1488x over previous
#include <cuda_runtime.h>
#include <math.h>
#include <stdint.h>

#define BATCH 4
#define SEQLEN 1024
#define VOCAB 28
#define D_MODEL 1024
#define N_LAYERS 4
#define D_INNER 2048
#define D_STATE 16
#define DT_RANK 64
#define NUM_CLS 2
#define ROWS (BATCH * SEQLEN)

// ---------------------------------------------------------------------------
// Scratch (device globals)
// ---------------------------------------------------------------------------
__device__ float g_h    [ROWS * D_MODEL];
__device__ float g_xn   [ROWS * D_MODEL];
__device__ float g_xz   [ROWS * 2 * D_INNER];
__device__ float g_xc   [ROWS * D_INNER];
__device__ float g_dbc  [ROWS * 96];
__device__ float g_delta[ROWS * D_INNER];
__device__ float g_y    [ROWS * D_INNER];

// ---------------------------------------------------------------------------
// Helpers
// ---------------------------------------------------------------------------
__device__ __forceinline__ uint32_t smem_u32(const void* p) {
    uint32_t a;
    asm("{ .reg .u64 t; cvta.to.shared.u64 t, %1; cvt.u32.u64 %0, t; }" : "=r"(a) : "l"(p));
    return a;
}
__device__ __forceinline__ void split_tf32(float x, uint32_t& hi, uint32_t& lo) {
    asm("cvt.rna.tf32.f32 %0, %1;" : "=r"(hi) : "f"(x));
    float l = x - __uint_as_float(hi);
    asm("cvt.rna.tf32.f32 %0, %1;" : "=r"(lo) : "f"(l));
}
__device__ __forceinline__ void cp_async16(uint32_t s, const void* g) {
    asm volatile("cp.async.cg.shared.global [%0], [%1], 16;" :: "r"(s), "l"(g) : "memory");
}
__device__ __forceinline__ void mma_tf32_16x8x8(
    float& c0, float& c1, float& c2, float& c3,
    uint32_t a0, uint32_t a1, uint32_t a2, uint32_t a3,
    uint32_t b0, uint32_t b1)
{
    asm volatile(
        "mma.sync.aligned.m16n8k8.row.col.f32.tf32.tf32.f32 "
        "{%0,%1,%2,%3}, {%4,%5,%6,%7}, {%8,%9}, {%0,%1,%2,%3};"
        : "+f"(c0), "+f"(c1), "+f"(c2), "+f"(c3)
        : "r"(a0), "r"(a1), "r"(a2), "r"(a3), "r"(b0), "r"(b1));
}

// ---------------------------------------------------------------------------
// 3xTF32 mma.sync GEMM (fp32-accurate): C[M,N] = A[M,K] * B[N,K]^T
// CTA 128x128, 256 threads, 8 warps (warp tile 64x32), BK=32, 4 stages.
// Each operand is split hi/lo in-registers; acc += Ahi*Bhi + Alo*Bhi + Ahi*Blo.
// EPI: 0 store, 1 C+=v, 2 relu(v+bias), 3 softplus(v+bias), 4 v+bias
// Requires M%128==0, K%32==0. N arbitrary (clamped loads, guarded stores).
// ---------------------------------------------------------------------------
#define NSTG 4
#define PADK 36
#define STGF (2 * 128 * PADK)   // floats per stage (A + B)

template <int EPI>
__global__ void __launch_bounds__(256) mma_gemm(
    const float* __restrict__ A, int lda,
    const float* __restrict__ B, int ldb,
    float* __restrict__ C, int ldc,
    int N, int K, const float* __restrict__ bias)
{
    extern __shared__ float sm[];
    const int tid = threadIdx.x;
    const int wid = tid >> 5, lane = tid & 31;
    const int g = lane >> 2, t = lane & 3;
    const int warp_m = (wid & 1) * 64;
    const int warp_n = (wid >> 1) * 32;
    const int bm = blockIdx.y * 128, bn = blockIdx.x * 128;
    const int niter = K >> 5;

    float acc[4][4][4];
    #pragma unroll
    for (int i = 0; i < 4; i++)
        #pragma unroll
        for (int j = 0; j < 4; j++)
            #pragma unroll
            for (int c = 0; c < 4; c++) acc[i][j][c] = 0.f;

    auto loadStage = [&](int it) {
        int s = it & (NSTG - 1);
        float* as = sm + s * STGF;
        float* bs = as + 128 * PADK;
        int k0 = it << 5;
        #pragma unroll
        for (int i = 0; i < 4; i++) {
            int ch = (i << 8) + tid;             // 1024 chunks of 16B
            int r = ch >> 3, c = (ch & 7) << 2;
            cp_async16(smem_u32(as + r * PADK + c),
                       A + (size_t)(bm + r) * lda + k0 + c);
        }
        #pragma unroll
        for (int i = 0; i < 4; i++) {
            int ch = (i << 8) + tid;
            int r = ch >> 3, c = (ch & 7) << 2;
            int gn = bn + r; if (gn >= N) gn = N - 1;
            cp_async16(smem_u32(bs + r * PADK + c),
                       B + (size_t)gn * ldb + k0 + c);
        }
        asm volatile("cp.async.commit_group;" ::: "memory");
    };

    int npro = niter < (NSTG - 1) ? niter : (NSTG - 1);
    for (int p = 0; p < npro; p++) loadStage(p);

    for (int it = 0; it < niter; it++) {
        int allow = niter - it - 1;
        if (allow > NSTG - 2) allow = NSTG - 2;
        if (allow == 0)      asm volatile("cp.async.wait_group 0;" ::: "memory");
        else if (allow == 1) asm volatile("cp.async.wait_group 1;" ::: "memory");
        else                 asm volatile("cp.async.wait_group 2;" ::: "memory");
        __syncthreads();

        if (it + NSTG - 1 < niter) loadStage(it + NSTG - 1);

        const float* as = sm + (it & (NSTG - 1)) * STGF;
        const float* bs = as + 128 * PADK;

        #pragma unroll
        for (int ks = 0; ks < 4; ks++) {
            int k0 = ks << 3;
            uint32_t ah[4][4], al[4][4], bh[4][2], bl[4][2];
            #pragma unroll
            for (int mt = 0; mt < 4; mt++) {
                int row = warp_m + (mt << 4);
                split_tf32(as[(row + g)     * PADK + k0 + t],     ah[mt][0], al[mt][0]);
                split_tf32(as[(row + g + 8) * PADK + k0 + t],     ah[mt][1], al[mt][1]);
                split_tf32(as[(row + g)     * PADK + k0 + t + 4], ah[mt][2], al[mt][2]);
                split_tf32(as[(row + g + 8) * PADK + k0 + t + 4], ah[mt][3], al[mt][3]);
            }
            #pragma unroll
            for (int nt = 0; nt < 4; nt++) {
                int col = warp_n + (nt << 3) + g;
                split_tf32(bs[col * PADK + k0 + t],     bh[nt][0], bl[nt][0]);
                split_tf32(bs[col * PADK + k0 + t + 4], bh[nt][1], bl[nt][1]);
            }
            #pragma unroll
            for (int mt = 0; mt < 4; mt++)
                #pragma unroll
                for (int nt = 0; nt < 4; nt++) {
                    mma_tf32_16x8x8(acc[mt][nt][0], acc[mt][nt][1],
                                    acc[mt][nt][2], acc[mt][nt][3],
                                    al[mt][0], al[mt][1], al[mt][2], al[mt][3],
                                    bh[nt][0], bh[nt][1]);
                    mma_tf32_16x8x8(acc[mt][nt][0], acc[mt][nt][1],
                                    acc[mt][nt][2], acc[mt][nt][3],
                                    ah[mt][0], ah[mt][1], ah[mt][2], ah[mt][3],
                                    bl[nt][0], bl[nt][1]);
                    mma_tf32_16x8x8(acc[mt][nt][0], acc[mt][nt][1],
                                    acc[mt][nt][2], acc[mt][nt][3],
                                    ah[mt][0], ah[mt][1], ah[mt][2], ah[mt][3],
                                    bh[nt][0], bh[nt][1]);
                }
        }
    }

    // Epilogue
    #pragma unroll
    for (int mt = 0; mt < 4; mt++) {
        #pragma unroll
        for (int nt = 0; nt < 4; nt++) {
            int col = bn + warp_n + (nt << 3) + (t << 1);
            if (col >= N) continue;
            #pragma unroll
            for (int half = 0; half < 2; half++) {
                int row = bm + warp_m + (mt << 4) + g + half * 8;
                float v0 = acc[mt][nt][half * 2];
                float v1 = acc[mt][nt][half * 2 + 1];
                float* cp = C + (size_t)row * ldc + col;
                if (EPI == 0) {
                    cp[0] = v0; cp[1] = v1;
                } else if (EPI == 1) {
                    cp[0] += v0; cp[1] += v1;
                } else if (EPI == 2) {
                    cp[0] = fmaxf(v0 + bias[col], 0.f);
                    cp[1] = fmaxf(v1 + bias[col + 1], 0.f);
                } else if (EPI == 3) {
                    v0 += bias[col]; v1 += bias[col + 1];
                    v0 = (v0 > 20.f) ? v0 : log1pf(__expf(v0));
                    v1 = (v1 > 20.f) ? v1 : log1pf(__expf(v1));
                    cp[0] = v0; cp[1] = v1;
                } else {
                    cp[0] = v0 + bias[col]; cp[1] = v1 + bias[col + 1];
                }
            }
        }
    }
}

// ---------------------------------------------------------------------------
// Elementwise / small kernels
// ---------------------------------------------------------------------------
__global__ void embed_kernel(const int* __restrict__ x, const float* __restrict__ emb,
                             const float* __restrict__ pos, float* __restrict__ out) {
    int idx = blockIdx.x * blockDim.x + threadIdx.x;
    if (idx >= ROWS * D_MODEL) return;
    int d = idx & (D_MODEL - 1), r = idx >> 10, l = r & (SEQLEN - 1);
    out[idx] = emb[x[r] * D_MODEL + d] + pos[l * D_MODEL + d];
}

__global__ void rmsnorm_kernel(const float* __restrict__ h, const float* __restrict__ w,
                               float* __restrict__ out) {
    int r = blockIdx.x, tid = threadIdx.x;
    const float* row = h + (size_t)r * D_MODEL;
    float s = 0.f;
    #pragma unroll
    for (int i = tid; i < D_MODEL; i += 256) { float v = row[i]; s += v * v; }
    __shared__ float red[8];
    #pragma unroll
    for (int o = 16; o > 0; o >>= 1) s += __shfl_down_sync(0xffffffffu, s, o);
    if ((tid & 31) == 0) red[tid >> 5] = s;
    __syncthreads();
    __shared__ float scale;
    if (tid == 0) {
        float t = 0.f;
        #pragma unroll
        for (int i = 0; i < 8; i++) t += red[i];
        scale = rsqrtf(t * (1.0f / D_MODEL) + 1e-5f);
    }
    __syncthreads();
    float sc = scale;
    #pragma unroll
    for (int i = tid; i < D_MODEL; i += 256)
        out[(size_t)r * D_MODEL + i] = row[i] * sc * w[i];
}

__global__ void conv_silu_kernel(const float* __restrict__ xz, const float* __restrict__ cw,
                                 const float* __restrict__ cb, float* __restrict__ xc) {
    int idx = blockIdx.x * blockDim.x + threadIdx.x;
    if (idx >= ROWS * D_INNER / 4) return;
    int d4 = (idx & (D_INNER / 4 - 1)) << 2;
    int r = idx >> 9, l = r & (SEQLEN - 1);
    float4 wa = *(const float4*)(cw + d4 * 4);
    float4 wb = *(const float4*)(cw + d4 * 4 + 4);
    float4 wc = *(const float4*)(cw + d4 * 4 + 8);
    float4 wd = *(const float4*)(cw + d4 * 4 + 12);
    float4 acc = *(const float4*)(cb + d4);
    const float* base = xz + (size_t)r * (2 * D_INNER) + d4;
    if (l >= 3) { float4 x = *(const float4*)(base - 3 * 2 * D_INNER);
        acc.x = fmaf(x.x, wa.x, acc.x); acc.y = fmaf(x.y, wb.x, acc.y);
        acc.z = fmaf(x.z, wc.x, acc.z); acc.w = fmaf(x.w, wd.x, acc.w); }
    if (l >= 2) { float4 x = *(const float4*)(base - 2 * 2 * D_INNER);
        acc.x = fmaf(x.x, wa.y, acc.x); acc.y = fmaf(x.y, wb.y, acc.y);
        acc.z = fmaf(x.z, wc.y, acc.z); acc.w = fmaf(x.w, wd.y, acc.w); }
    if (l >= 1) { float4 x = *(const float4*)(base - 2 * D_INNER);
        acc.x = fmaf(x.x, wa.z, acc.x); acc.y = fmaf(x.y, wb.z, acc.y);
        acc.z = fmaf(x.z, wc.z, acc.z); acc.w = fmaf(x.w, wd.z, acc.w); }
    { float4 x = *(const float4*)(base);
        acc.x = fmaf(x.x, wa.w, acc.x); acc.y = fmaf(x.y, wb.w, acc.y);
        acc.z = fmaf(x.z, wc.w, acc.z); acc.w = fmaf(x.w, wd.w, acc.w); }
    acc.x = acc.x / (1.f + __expf(-acc.x));
    acc.y = acc.y / (1.f + __expf(-acc.y));
    acc.z = acc.z / (1.f + __expf(-acc.z));
    acc.w = acc.w / (1.f + __expf(-acc.w));
    *(float4*)(xc + (size_t)r * D_INNER + d4) = acc;
}

__global__ void scan_kernel(const float* __restrict__ delta, const float* __restrict__ xc,
                            const float* __restrict__ dbc, const float* __restrict__ xz,
                            const float* __restrict__ A_log, const float* __restrict__ Dp,
                            float* __restrict__ yout) {
    int gwarp = (blockIdx.x * blockDim.x + threadIdx.x) >> 5;
    int lane = threadIdx.x & 31, n = lane & 15;
    int pair = gwarp * 2 + (lane >> 4);
    int b = pair >> 11, d = pair & (D_INNER - 1);
    if (b >= BATCH) return;
    float An = -__expf(A_log[d * D_STATE + n]);
    float Dv = Dp[d], h = 0.f;
    size_t rbase = (size_t)b * SEQLEN;
    for (int l = 0; l < SEQLEN; l++) {
        size_t r = rbase + l;
        float dlt = delta[r * D_INNER + d];
        float xcv = xc[r * D_INNER + d];
        float Bv = dbc[r * 96 + DT_RANK + n];
        float Cv = dbc[r * 96 + DT_RANK + D_STATE + n];
        float dA = __expf(dlt * An);
        h = fmaf(dA, h, dlt * xcv * Bv);
        float y = h * Cv;
        y += __shfl_xor_sync(0xffffffffu, y, 1);
        y += __shfl_xor_sync(0xffffffffu, y, 2);
        y += __shfl_xor_sync(0xffffffffu, y, 4);
        y += __shfl_xor_sync(0xffffffffu, y, 8);
        if (n == 0) {
            float zv = xz[r * (2 * D_INNER) + D_INNER + d];
            float sz = zv / (1.f + __expf(-zv));
            yout[r * D_INNER + d] = (y + Dv * xcv) * sz;
        }
    }
}

__global__ void cls_kernel(const float* __restrict__ h,
                           const float* __restrict__ w1, const float* __restrict__ b1,
                           const float* __restrict__ w2, const float* __restrict__ b2,
                           float* __restrict__ out) {
    __shared__ float sh[D_MODEL];
    __shared__ float t1[D_MODEL];
    __shared__ float red[256];
    int b = blockIdx.x, tid = threadIdx.x;
    const float* row = h + ((size_t)b * SEQLEN + (SEQLEN - 1)) * D_MODEL;
    for (int i = tid; i < D_MODEL; i += 256) sh[i] = row[i];
    __syncthreads();
    for (int e = tid; e < D_MODEL; e += 256) {
        const float* wr = w1 + (size_t)e * D_MODEL;
        float acc = b1[e];
        #pragma unroll 4
        for (int k = 0; k < D_MODEL; k += 4) {
            float4 w4 = *(const float4*)(wr + k);
            acc = fmaf(sh[k], w4.x, acc); acc = fmaf(sh[k + 1], w4.y, acc);
            acc = fmaf(sh[k + 2], w4.z, acc); acc = fmaf(sh[k + 3], w4.w, acc);
        }
        t1[e] = acc > 0.f ? acc : 0.f;
    }
    __syncthreads();
    for (int c = 0; c < NUM_CLS; c++) {
        float p = 0.f;
        for (int k = tid; k < D_MODEL; k += 256) p = fmaf(t1[k], w2[c * D_MODEL + k], p);
        red[tid] = p;
        __syncthreads();
        for (int s = 128; s > 0; s >>= 1) { if (tid < s) red[tid] += red[tid + s]; __syncthreads(); }
        if (tid == 0) out[b * NUM_CLS + c] = red[0] + b2[c];
        __syncthreads();
    }
}

// ---------------------------------------------------------------------------
// Launch
// ---------------------------------------------------------------------------
#define MMA_SMEM (NSTG * STGF * 4)   // 147456 bytes

extern "C" void kernel_launch(void* const* d_in, const int* in_sizes, int n_in,
                              void* d_out, int out_size)
{
    const int*   x_tok      = (const int*)d_in[0];
    const float* embedding  = (const float*)d_in[1];
    const float* pos_enc    = (const float*)d_in[2];
    const float* norm_w     = (const float*)d_in[3];
    const float* in_proj_w  = (const float*)d_in[4];
    const float* conv_w     = (const float*)d_in[5];
    const float* conv_b     = (const float*)d_in[6];
    const float* x_proj_w   = (const float*)d_in[7];
    const float* dt_proj_w  = (const float*)d_in[8];
    const float* dt_proj_b  = (const float*)d_in[9];
    const float* A_log      = (const float*)d_in[10];
    const float* Dp         = (const float*)d_in[11];
    const float* out_proj_w = (const float*)d_in[12];
    const float* cls_fc1_w  = (const float*)d_in[13];
    const float* cls_fc1_b  = (const float*)d_in[14];
    const float* cls_fc2_w  = (const float*)d_in[15];
    const float* cls_fc2_b  = (const float*)d_in[16];
    const float* dec_fc1_w  = (const float*)d_in[17];
    const float* dec_fc1_b  = (const float*)d_in[18];
    const float* dec_fc2_w  = (const float*)d_in[19];
    const float* dec_fc2_b  = (const float*)d_in[20];

    float *h, *xn, *xz, *xc, *dbc, *delta, *y;
    cudaGetSymbolAddress((void**)&h, g_h);
    cudaGetSymbolAddress((void**)&xn, g_xn);
    cudaGetSymbolAddress((void**)&xz, g_xz);
    cudaGetSymbolAddress((void**)&xc, g_xc);
    cudaGetSymbolAddress((void**)&dbc, g_dbc);
    cudaGetSymbolAddress((void**)&delta, g_delta);
    cudaGetSymbolAddress((void**)&y, g_y);

    cudaFuncSetAttribute(mma_gemm<0>, cudaFuncAttributeMaxDynamicSharedMemorySize, MMA_SMEM);
    cudaFuncSetAttribute(mma_gemm<1>, cudaFuncAttributeMaxDynamicSharedMemorySize, MMA_SMEM);
    cudaFuncSetAttribute(mma_gemm<2>, cudaFuncAttributeMaxDynamicSharedMemorySize, MMA_SMEM);
    cudaFuncSetAttribute(mma_gemm<3>, cudaFuncAttributeMaxDynamicSharedMemorySize, MMA_SMEM);
    cudaFuncSetAttribute(mma_gemm<4>, cudaFuncAttributeMaxDynamicSharedMemorySize, MMA_SMEM);

    float* out_dec = (float*)d_out;
    float* out_cls = (float*)d_out + ROWS * VOCAB;

    embed_kernel<<<(ROWS * D_MODEL + 255) / 256, 256>>>(x_tok, embedding, pos_enc, h);

    for (int l = 0; l < N_LAYERS; l++) {
        const float* inw = in_proj_w + (size_t)l * 2 * D_INNER * D_MODEL;
        const float* cw  = conv_w + (size_t)l * D_INNER * 4;
        const float* cb  = conv_b + (size_t)l * D_INNER;
        const float* xpw = x_proj_w + (size_t)l * 96 * D_INNER;
        const float* dtw = dt_proj_w + (size_t)l * D_INNER * DT_RANK;
        const float* dtb = dt_proj_b + (size_t)l * D_INNER;
        const float* al  = A_log + (size_t)l * D_INNER * D_STATE;
        const float* dp  = Dp + (size_t)l * D_INNER;
        const float* ow  = out_proj_w + (size_t)l * D_MODEL * D_INNER;
        const float* nw  = norm_w + (size_t)l * D_MODEL;

        rmsnorm_kernel<<<ROWS, 256>>>(h, nw, xn);
        // xz = xn @ in_w^T      (4096 x 4096 x 1024)
        mma_gemm<0><<<dim3(2 * D_INNER / 128, ROWS / 128), 256, MMA_SMEM>>>(
            xn, D_MODEL, inw, D_MODEL, xz, 2 * D_INNER, 2 * D_INNER, D_MODEL, nullptr);
        conv_silu_kernel<<<(ROWS * D_INNER / 4 + 255) / 256, 256>>>(xz, cw, cb, xc);
        // dbc = xc @ xp_w^T     (4096 x 96 x 2048)
        mma_gemm<0><<<dim3(1, ROWS / 128), 256, MMA_SMEM>>>(
            xc, D_INNER, xpw, D_INNER, dbc, 96, 96, D_INNER, nullptr);
        // delta = softplus(dbc[:, :64] @ dt_w^T + dtb)   (4096 x 2048 x 64)
        mma_gemm<3><<<dim3(D_INNER / 128, ROWS / 128), 256, MMA_SMEM>>>(
            dbc, 96, dtw, DT_RANK, delta, D_INNER, D_INNER, DT_RANK, dtb);
        scan_kernel<<<(BATCH * D_INNER / 2) / 8, 256>>>(delta, xc, dbc, xz, al, dp, y);
        // h += y @ out_w^T      (4096 x 1024 x 2048)
        mma_gemm<1><<<dim3(D_MODEL / 128, ROWS / 128), 256, MMA_SMEM>>>(
            y, D_INNER, ow, D_INNER, h, D_MODEL, D_MODEL, D_INNER, nullptr);
    }

    // dec MLP
    mma_gemm<2><<<dim3(D_MODEL / 128, ROWS / 128), 256, MMA_SMEM>>>(
        h, D_MODEL, dec_fc1_w, D_MODEL, xn, D_MODEL, D_MODEL, D_MODEL, dec_fc1_b);
    mma_gemm<4><<<dim3(1, ROWS / 128), 256, MMA_SMEM>>>(
        xn, D_MODEL, dec_fc2_w, D_MODEL, out_dec, VOCAB, VOCAB, D_MODEL, dec_fc2_b);

    cls_kernel<<<BATCH, 256>>>(h, cls_fc1_w, cls_fc1_b, cls_fc2_w, cls_fc2_b, out_cls);
}

// round 8
// speedup vs baseline: 1.4923x; 1.2991x over previous
#include <cuda_runtime.h>
#include <cuda_bf16.h>
#include <math.h>
#include <stdint.h>

#define BATCH 4
#define SEQLEN 1024
#define VOCAB 28
#define D_MODEL 1024
#define N_LAYERS 4
#define D_INNER 2048
#define D_STATE 16
#define DT_RANK 64
#define NUM_CLS 2
#define ROWS (BATCH * SEQLEN)

typedef __nv_bfloat16 bf16;
typedef __nv_bfloat162 bf162;

// ---------------------------------------------------------------------------
// Scratch (device globals)
// ---------------------------------------------------------------------------
__device__ float g_h    [ROWS * D_MODEL];
__device__ float g_xz   [ROWS * 2 * D_INNER];
__device__ float g_xc   [ROWS * D_INNER];
__device__ float g_dbc  [ROWS * 96];
__device__ float g_delta[ROWS * D_INNER];

__device__ bf16 g_xn_h[ROWS * D_MODEL],  g_xn_l[ROWS * D_MODEL];
__device__ bf16 g_xc_h[ROWS * D_INNER],  g_xc_l[ROWS * D_INNER];
__device__ bf16 g_dbc_h[ROWS * 96],      g_dbc_l[ROWS * 96];
__device__ bf16 g_y_h [ROWS * D_INNER],  g_y_l [ROWS * D_INNER];
__device__ bf16 g_hs_h[ROWS * D_MODEL],  g_hs_l[ROWS * D_MODEL];
__device__ bf16 g_t_h [ROWS * D_MODEL],  g_t_l [ROWS * D_MODEL];

__device__ bf16 g_win_h [N_LAYERS * 2 * D_INNER * D_MODEL], g_win_l [N_LAYERS * 2 * D_INNER * D_MODEL];
__device__ bf16 g_wout_h[N_LAYERS * D_MODEL * D_INNER],     g_wout_l[N_LAYERS * D_MODEL * D_INNER];
__device__ bf16 g_wxp_h [N_LAYERS * 96 * D_INNER],          g_wxp_l [N_LAYERS * 96 * D_INNER];
__device__ bf16 g_wdt_h [N_LAYERS * D_INNER * DT_RANK],     g_wdt_l [N_LAYERS * D_INNER * DT_RANK];
__device__ bf16 g_wd1_h [D_MODEL * D_MODEL],                g_wd1_l [D_MODEL * D_MODEL];
__device__ bf16 g_wd2_h [VOCAB * D_MODEL],                  g_wd2_l [VOCAB * D_MODEL];

// ---------------------------------------------------------------------------
// Helpers
// ---------------------------------------------------------------------------
__device__ __forceinline__ uint32_t smem_u32(const void* p) {
    uint32_t a;
    asm("{ .reg .u64 t; cvta.to.shared.u64 t, %1; cvt.u32.u64 %0, t; }" : "=r"(a) : "l"(p));
    return a;
}
__device__ __forceinline__ void bsplit(float v, bf16& hi, bf16& lo) {
    hi = __float2bfloat16(v);
    lo = __float2bfloat16(v - __bfloat162float(hi));
}
__device__ __forceinline__ void cp_async16(uint32_t s, const void* g) {
    asm volatile("cp.async.cg.shared.global [%0], [%1], 16;" :: "r"(s), "l"(g) : "memory");
}
__device__ __forceinline__ void mma_bf16(
    float& c0, float& c1, float& c2, float& c3,
    uint32_t a0, uint32_t a1, uint32_t a2, uint32_t a3,
    uint32_t b0, uint32_t b1)
{
    asm volatile(
        "mma.sync.aligned.m16n8k16.row.col.f32.bf16.bf16.f32 "
        "{%0,%1,%2,%3}, {%4,%5,%6,%7}, {%8,%9}, {%0,%1,%2,%3};"
        : "+f"(c0), "+f"(c1), "+f"(c2), "+f"(c3)
        : "r"(a0), "r"(a1), "r"(a2), "r"(a3), "r"(b0), "r"(b1));
}

// ---------------------------------------------------------------------------
// 3-term bf16 mma GEMM (fp32-accurate): C[M,N] = A[M,K] * B[N,K]^T
// A,B given as precomputed bf16 hi/lo pairs. CTA 128x128, 256 threads,
// 8 warps (warp tile 64x32), BK=32, 4 stages, XOR-swizzled smem.
// acc += Ahi*Bhi + Alo*Bhi + Ahi*Blo   (lo*lo dropped, ~2^-18)
// EPI: 0 C store | 1 C += | 2 relu(v+bias)->split | 3 softplus(v+bias)->C
//      4 v+bias->C | 5 v->C and split
// Requires M%128==0, K%32==0. N arbitrary (clamped loads, guarded stores).
// ---------------------------------------------------------------------------
#define NSTG 4
#define STGW 8192            // 32-bit words per stage (4 tiles x 2048)
#define T_AH 0
#define T_AL 2048
#define T_BH 4096
#define T_BL 6144

template <int EPI>
__global__ void __launch_bounds__(256) mma_gemm(
    const bf16* __restrict__ Ahi, const bf16* __restrict__ Alo, int lda,
    const bf16* __restrict__ Bhi, const bf16* __restrict__ Blo, int ldb,
    float* __restrict__ C, bf16* __restrict__ Chi, bf16* __restrict__ Clo,
    int ldc, int N, int K, const float* __restrict__ bias)
{
    extern __shared__ float smf[];
    uint32_t* sm32 = (uint32_t*)smf;
    const uint32_t smb = smem_u32(smf);

    const int tid = threadIdx.x;
    const int wid = tid >> 5, lane = tid & 31;
    const int g = lane >> 2, t = lane & 3;
    const int warp_m = (wid & 1) * 64;
    const int warp_n = (wid >> 1) * 32;
    const int bm = blockIdx.y * 128, bn = blockIdx.x * 128;
    const int niter = K >> 5;

    float acc[4][4][4];
    #pragma unroll
    for (int i = 0; i < 4; i++)
        #pragma unroll
        for (int j = 0; j < 4; j++)
            #pragma unroll
            for (int c = 0; c < 4; c++) acc[i][j][c] = 0.f;

    // 16B chunk store: tile row r (0..127), word-block w4 (0..3)
    // swizzled word = (w4*4) ^ ((r&6)<<1); load word w -> w ^ ((r&6)<<1)
    auto loadStage = [&](int it) {
        int s = it & (NSTG - 1);
        uint32_t sb = (uint32_t)s * STGW;
        int k0 = it << 5;
        #pragma unroll
        for (int i = 0; i < 2; i++) {
            int c = (i << 8) + tid;         // 512 chunks per tile
            int r = c >> 2, w4 = c & 3;
            int sw = (w4 << 2) ^ ((r & 6) << 1);
            int gn = bn + r; if (gn >= N) gn = N - 1;
            const bf16* ga_h = Ahi + (size_t)(bm + r) * lda + k0 + (w4 << 3);
            const bf16* ga_l = Alo + (size_t)(bm + r) * lda + k0 + (w4 << 3);
            const bf16* gb_h = Bhi + (size_t)gn * ldb + k0 + (w4 << 3);
            const bf16* gb_l = Blo + (size_t)gn * ldb + k0 + (w4 << 3);
            uint32_t wbase = sb + (uint32_t)(r * 16 + sw);
            cp_async16(smb + (wbase + T_AH) * 4, ga_h);
            cp_async16(smb + (wbase + T_AL) * 4, ga_l);
            cp_async16(smb + (wbase + T_BH) * 4, gb_h);
            cp_async16(smb + (wbase + T_BL) * 4, gb_l);
        }
        asm volatile("cp.async.commit_group;" ::: "memory");
    };

    int npro = niter < (NSTG - 1) ? niter : (NSTG - 1);
    for (int p = 0; p < npro; p++) loadStage(p);

    for (int it = 0; it < niter; it++) {
        int allow = niter - it - 1;
        if (allow > NSTG - 2) allow = NSTG - 2;
        if (allow == 0)      asm volatile("cp.async.wait_group 0;" ::: "memory");
        else if (allow == 1) asm volatile("cp.async.wait_group 1;" ::: "memory");
        else                 asm volatile("cp.async.wait_group 2;" ::: "memory");
        __syncthreads();

        if (it + NSTG - 1 < niter) loadStage(it + NSTG - 1);

        uint32_t sb = (uint32_t)(it & (NSTG - 1)) * STGW;
        auto ldw = [&](int tile, int r, int w) -> uint32_t {
            return sm32[sb + tile + r * 16 + (w ^ ((r & 6) << 1))];
        };

        #pragma unroll
        for (int ch = 0; ch < 2; ch++) {       // two k16 chunks per BK=32
            int kw = ch << 3;                  // word offset in row
            uint32_t ah[4][4], al[4][4], bh[4][2], bl[4][2];
            #pragma unroll
            for (int mt = 0; mt < 4; mt++) {
                int r0 = warp_m + (mt << 4);
                ah[mt][0] = ldw(T_AH, r0 + g,     kw + t);
                ah[mt][1] = ldw(T_AH, r0 + 8 + g, kw + t);
                ah[mt][2] = ldw(T_AH, r0 + g,     kw + t + 4);
                ah[mt][3] = ldw(T_AH, r0 + 8 + g, kw + t + 4);
                al[mt][0] = ldw(T_AL, r0 + g,     kw + t);
                al[mt][1] = ldw(T_AL, r0 + 8 + g, kw + t);
                al[mt][2] = ldw(T_AL, r0 + g,     kw + t + 4);
                al[mt][3] = ldw(T_AL, r0 + 8 + g, kw + t + 4);
            }
            #pragma unroll
            for (int nt = 0; nt < 4; nt++) {
                int c0 = warp_n + (nt << 3) + g;
                bh[nt][0] = ldw(T_BH, c0, kw + t);
                bh[nt][1] = ldw(T_BH, c0, kw + t + 4);
                bl[nt][0] = ldw(T_BL, c0, kw + t);
                bl[nt][1] = ldw(T_BL, c0, kw + t + 4);
            }
            #pragma unroll
            for (int mt = 0; mt < 4; mt++)
                #pragma unroll
                for (int nt = 0; nt < 4; nt++) {
                    mma_bf16(acc[mt][nt][0], acc[mt][nt][1],
                             acc[mt][nt][2], acc[mt][nt][3],
                             al[mt][0], al[mt][1], al[mt][2], al[mt][3],
                             bh[nt][0], bh[nt][1]);
                    mma_bf16(acc[mt][nt][0], acc[mt][nt][1],
                             acc[mt][nt][2], acc[mt][nt][3],
                             ah[mt][0], ah[mt][1], ah[mt][2], ah[mt][3],
                             bl[nt][0], bl[nt][1]);
                    mma_bf16(acc[mt][nt][0], acc[mt][nt][1],
                             acc[mt][nt][2], acc[mt][nt][3],
                             ah[mt][0], ah[mt][1], ah[mt][2], ah[mt][3],
                             bh[nt][0], bh[nt][1]);
                }
        }
    }

    // Epilogue: c0=C[g][2t], c1=C[g][2t+1], c2=C[g+8][2t], c3=C[g+8][2t+1]
    #pragma unroll
    for (int mt = 0; mt < 4; mt++) {
        #pragma unroll
        for (int nt = 0; nt < 4; nt++) {
            int col = bn + warp_n + (nt << 3) + (t << 1);
            if (col >= N) continue;
            #pragma unroll
            for (int half = 0; half < 2; half++) {
                int row = bm + warp_m + (mt << 4) + g + half * 8;
                float v0 = acc[mt][nt][half * 2];
                float v1 = acc[mt][nt][half * 2 + 1];
                size_t idx = (size_t)row * ldc + col;
                if (EPI == 0) {
                    C[idx] = v0; C[idx + 1] = v1;
                } else if (EPI == 1) {
                    C[idx] += v0; C[idx + 1] += v1;
                } else if (EPI == 2) {
                    v0 = fmaxf(v0 + bias[col], 0.f);
                    v1 = fmaxf(v1 + bias[col + 1], 0.f);
                    bf16 h0, l0, h1, l1;
                    bsplit(v0, h0, l0); bsplit(v1, h1, l1);
                    Chi[idx] = h0; Chi[idx + 1] = h1;
                    Clo[idx] = l0; Clo[idx + 1] = l1;
                } else if (EPI == 3) {
                    v0 += bias[col]; v1 += bias[col + 1];
                    v0 = (v0 > 20.f) ? v0 : log1pf(__expf(v0));
                    v1 = (v1 > 20.f) ? v1 : log1pf(__expf(v1));
                    C[idx] = v0; C[idx + 1] = v1;
                } else if (EPI == 4) {
                    C[idx] = v0 + bias[col]; C[idx + 1] = v1 + bias[col + 1];
                } else {
                    C[idx] = v0; C[idx + 1] = v1;
                    bf16 h0, l0, h1, l1;
                    bsplit(v0, h0, l0); bsplit(v1, h1, l1);
                    Chi[idx] = h0; Chi[idx + 1] = h1;
                    Clo[idx] = l0; Clo[idx + 1] = l1;
                }
            }
        }
    }
}

// ---------------------------------------------------------------------------
// Elementwise / small kernels
// ---------------------------------------------------------------------------
__global__ void split_kernel(const float4* __restrict__ src,
                             bf162* __restrict__ hi2, bf162* __restrict__ lo2, int n4) {
    int i = blockIdx.x * blockDim.x + threadIdx.x;
    if (i >= n4) return;
    float4 v = src[i];
    bf16 h0, l0, h1, l1, h2, l2, h3, l3;
    bsplit(v.x, h0, l0); bsplit(v.y, h1, l1);
    bsplit(v.z, h2, l2); bsplit(v.w, h3, l3);
    bf162 a; a.x = h0; a.y = h1;
    bf162 b; b.x = h2; b.y = h3;
    bf162 c; c.x = l0; c.y = l1;
    bf162 d; d.x = l2; d.y = l3;
    hi2[i * 2] = a; hi2[i * 2 + 1] = b;
    lo2[i * 2] = c; lo2[i * 2 + 1] = d;
}

__global__ void embed_kernel(const int* __restrict__ x, const float* __restrict__ emb,
                             const float* __restrict__ pos, float* __restrict__ out) {
    int idx = blockIdx.x * blockDim.x + threadIdx.x;
    if (idx >= ROWS * D_MODEL) return;
    int d = idx & (D_MODEL - 1), r = idx >> 10, l = r & (SEQLEN - 1);
    out[idx] = emb[x[r] * D_MODEL + d] + pos[l * D_MODEL + d];
}

__global__ void rmsnorm_kernel(const float* __restrict__ h, const float* __restrict__ w,
                               bf16* __restrict__ oh, bf16* __restrict__ ol) {
    int r = blockIdx.x, tid = threadIdx.x;
    const float* row = h + (size_t)r * D_MODEL;
    float s = 0.f;
    #pragma unroll
    for (int i = tid; i < D_MODEL; i += 256) { float v = row[i]; s += v * v; }
    __shared__ float red[8];
    #pragma unroll
    for (int o = 16; o > 0; o >>= 1) s += __shfl_down_sync(0xffffffffu, s, o);
    if ((tid & 31) == 0) red[tid >> 5] = s;
    __syncthreads();
    __shared__ float scale;
    if (tid == 0) {
        float tt = 0.f;
        #pragma unroll
        for (int i = 0; i < 8; i++) tt += red[i];
        scale = rsqrtf(tt * (1.0f / D_MODEL) + 1e-5f);
    }
    __syncthreads();
    float sc = scale;
    #pragma unroll
    for (int i = tid; i < D_MODEL; i += 256) {
        bf16 hh, ll;
        bsplit(row[i] * sc * w[i], hh, ll);
        oh[(size_t)r * D_MODEL + i] = hh;
        ol[(size_t)r * D_MODEL + i] = ll;
    }
}

__global__ void conv_silu_kernel(const float* __restrict__ xz, const float* __restrict__ cw,
                                 const float* __restrict__ cb, float* __restrict__ xc,
                                 bf16* __restrict__ xch, bf16* __restrict__ xcl) {
    int idx = blockIdx.x * blockDim.x + threadIdx.x;
    if (idx >= ROWS * D_INNER / 4) return;
    int d4 = (idx & (D_INNER / 4 - 1)) << 2;
    int r = idx >> 9, l = r & (SEQLEN - 1);
    float4 wa = *(const float4*)(cw + d4 * 4);
    float4 wb = *(const float4*)(cw + d4 * 4 + 4);
    float4 wc = *(const float4*)(cw + d4 * 4 + 8);
    float4 wd = *(const float4*)(cw + d4 * 4 + 12);
    float4 acc = *(const float4*)(cb + d4);
    const float* base = xz + (size_t)r * (2 * D_INNER) + d4;
    if (l >= 3) { float4 x = *(const float4*)(base - 3 * 2 * D_INNER);
        acc.x = fmaf(x.x, wa.x, acc.x); acc.y = fmaf(x.y, wb.x, acc.y);
        acc.z = fmaf(x.z, wc.x, acc.z); acc.w = fmaf(x.w, wd.x, acc.w); }
    if (l >= 2) { float4 x = *(const float4*)(base - 2 * 2 * D_INNER);
        acc.x = fmaf(x.x, wa.y, acc.x); acc.y = fmaf(x.y, wb.y, acc.y);
        acc.z = fmaf(x.z, wc.y, acc.z); acc.w = fmaf(x.w, wd.y, acc.w); }
    if (l >= 1) { float4 x = *(const float4*)(base - 2 * D_INNER);
        acc.x = fmaf(x.x, wa.z, acc.x); acc.y = fmaf(x.y, wb.z, acc.y);
        acc.z = fmaf(x.z, wc.z, acc.z); acc.w = fmaf(x.w, wd.z, acc.w); }
    { float4 x = *(const float4*)(base);
        acc.x = fmaf(x.x, wa.w, acc.x); acc.y = fmaf(x.y, wb.w, acc.y);
        acc.z = fmaf(x.z, wc.w, acc.z); acc.w = fmaf(x.w, wd.w, acc.w); }
    acc.x = acc.x / (1.f + __expf(-acc.x));
    acc.y = acc.y / (1.f + __expf(-acc.y));
    acc.z = acc.z / (1.f + __expf(-acc.z));
    acc.w = acc.w / (1.f + __expf(-acc.w));
    size_t o = (size_t)r * D_INNER + d4;
    *(float4*)(xc + o) = acc;
    bf16 h0, l0, h1, l1, h2, l2, h3, l3;
    bsplit(acc.x, h0, l0); bsplit(acc.y, h1, l1);
    bsplit(acc.z, h2, l2); bsplit(acc.w, h3, l3);
    bf162 ph0; ph0.x = h0; ph0.y = h1;
    bf162 ph1; ph1.x = h2; ph1.y = h3;
    bf162 pl0; pl0.x = l0; pl0.y = l1;
    bf162 pl1; pl1.x = l2; pl1.y = l3;
    *(bf162*)(xch + o) = ph0; *(bf162*)(xch + o + 2) = ph1;
    *(bf162*)(xcl + o) = pl0; *(bf162*)(xcl + o + 2) = pl1;
}

__global__ void scan_kernel(const float* __restrict__ delta, const float* __restrict__ xc,
                            const float* __restrict__ dbc, const float* __restrict__ xz,
                            const float* __restrict__ A_log, const float* __restrict__ Dp,
                            bf16* __restrict__ yh, bf16* __restrict__ yl) {
    int gwarp = (blockIdx.x * blockDim.x + threadIdx.x) >> 5;
    int lane = threadIdx.x & 31, n = lane & 15;
    int pair = gwarp * 2 + (lane >> 4);
    int b = pair >> 11, d = pair & (D_INNER - 1);
    if (b >= BATCH) return;
    float An = -__expf(A_log[d * D_STATE + n]);
    float Dv = Dp[d], h = 0.f;
    size_t rbase = (size_t)b * SEQLEN;
    for (int l = 0; l < SEQLEN; l++) {
        size_t r = rbase + l;
        float dlt = delta[r * D_INNER + d];
        float xcv = xc[r * D_INNER + d];
        float Bv = dbc[r * 96 + DT_RANK + n];
        float Cv = dbc[r * 96 + DT_RANK + D_STATE + n];
        float dA = __expf(dlt * An);
        h = fmaf(dA, h, dlt * xcv * Bv);
        float y = h * Cv;
        y += __shfl_xor_sync(0xffffffffu, y, 1);
        y += __shfl_xor_sync(0xffffffffu, y, 2);
        y += __shfl_xor_sync(0xffffffffu, y, 4);
        y += __shfl_xor_sync(0xffffffffu, y, 8);
        if (n == 0) {
            float zv = xz[r * (2 * D_INNER) + D_INNER + d];
            float sz = zv / (1.f + __expf(-zv));
            bf16 hh, ll;
            bsplit((y + Dv * xcv) * sz, hh, ll);
            yh[r * D_INNER + d] = hh;
            yl[r * D_INNER + d] = ll;
        }
    }
}

__global__ void cls_kernel(const float* __restrict__ h,
                           const float* __restrict__ w1, const float* __restrict__ b1,
                           const float* __restrict__ w2, const float* __restrict__ b2,
                           float* __restrict__ out) {
    __shared__ float sh[D_MODEL];
    __shared__ float t1[D_MODEL];
    __shared__ float red[256];
    int b = blockIdx.x, tid = threadIdx.x;
    const float* row = h + ((size_t)b * SEQLEN + (SEQLEN - 1)) * D_MODEL;
    for (int i = tid; i < D_MODEL; i += 256) sh[i] = row[i];
    __syncthreads();
    for (int e = tid; e < D_MODEL; e += 256) {
        const float* wr = w1 + (size_t)e * D_MODEL;
        float acc = b1[e];
        #pragma unroll 4
        for (int k = 0; k < D_MODEL; k += 4) {
            float4 w4 = *(const float4*)(wr + k);
            acc = fmaf(sh[k], w4.x, acc); acc = fmaf(sh[k + 1], w4.y, acc);
            acc = fmaf(sh[k + 2], w4.z, acc); acc = fmaf(sh[k + 3], w4.w, acc);
        }
        t1[e] = acc > 0.f ? acc : 0.f;
    }
    __syncthreads();
    for (int c = 0; c < NUM_CLS; c++) {
        float p = 0.f;
        for (int k = tid; k < D_MODEL; k += 256) p = fmaf(t1[k], w2[c * D_MODEL + k], p);
        red[tid] = p;
        __syncthreads();
        for (int s = 128; s > 0; s >>= 1) { if (tid < s) red[tid] += red[tid + s]; __syncthreads(); }
        if (tid == 0) out[b * NUM_CLS + c] = red[0] + b2[c];
        __syncthreads();
    }
}

// ---------------------------------------------------------------------------
// Launch
// ---------------------------------------------------------------------------
#define MMA_SMEM (NSTG * STGW * 4)   // 131072 bytes

extern "C" void kernel_launch(void* const* d_in, const int* in_sizes, int n_in,
                              void* d_out, int out_size)
{
    const int*   x_tok      = (const int*)d_in[0];
    const float* embedding  = (const float*)d_in[1];
    const float* pos_enc    = (const float*)d_in[2];
    const float* norm_w     = (const float*)d_in[3];
    const float* in_proj_w  = (const float*)d_in[4];
    const float* conv_w     = (const float*)d_in[5];
    const float* conv_b     = (const float*)d_in[6];
    const float* x_proj_w   = (const float*)d_in[7];
    const float* dt_proj_w  = (const float*)d_in[8];
    const float* dt_proj_b  = (const float*)d_in[9];
    const float* A_log      = (const float*)d_in[10];
    const float* Dp         = (const float*)d_in[11];
    const float* out_proj_w = (const float*)d_in[12];
    const float* cls_fc1_w  = (const float*)d_in[13];
    const float* cls_fc1_b  = (const float*)d_in[14];
    const float* cls_fc2_w  = (const float*)d_in[15];
    const float* cls_fc2_b  = (const float*)d_in[16];
    const float* dec_fc1_w  = (const float*)d_in[17];
    const float* dec_fc1_b  = (const float*)d_in[18];
    const float* dec_fc2_w  = (const float*)d_in[19];
    const float* dec_fc2_b  = (const float*)d_in[20];

    float *h, *xz, *xc, *dbc, *delta;
    bf16 *xn_h, *xn_l, *xc_h, *xc_l, *dbc_h, *dbc_l, *y_h, *y_l, *hs_h, *hs_l, *t_h, *t_l;
    bf16 *win_h, *win_l, *wout_h, *wout_l, *wxp_h, *wxp_l, *wdt_h, *wdt_l, *wd1_h, *wd1_l, *wd2_h, *wd2_l;
    cudaGetSymbolAddress((void**)&h, g_h);
    cudaGetSymbolAddress((void**)&xz, g_xz);
    cudaGetSymbolAddress((void**)&xc, g_xc);
    cudaGetSymbolAddress((void**)&dbc, g_dbc);
    cudaGetSymbolAddress((void**)&delta, g_delta);
    cudaGetSymbolAddress((void**)&xn_h, g_xn_h);  cudaGetSymbolAddress((void**)&xn_l, g_xn_l);
    cudaGetSymbolAddress((void**)&xc_h, g_xc_h);  cudaGetSymbolAddress((void**)&xc_l, g_xc_l);
    cudaGetSymbolAddress((void**)&dbc_h, g_dbc_h); cudaGetSymbolAddress((void**)&dbc_l, g_dbc_l);
    cudaGetSymbolAddress((void**)&y_h, g_y_h);    cudaGetSymbolAddress((void**)&y_l, g_y_l);
    cudaGetSymbolAddress((void**)&hs_h, g_hs_h);  cudaGetSymbolAddress((void**)&hs_l, g_hs_l);
    cudaGetSymbolAddress((void**)&t_h, g_t_h);    cudaGetSymbolAddress((void**)&t_l, g_t_l);
    cudaGetSymbolAddress((void**)&win_h, g_win_h);   cudaGetSymbolAddress((void**)&win_l, g_win_l);
    cudaGetSymbolAddress((void**)&wout_h, g_wout_h); cudaGetSymbolAddress((void**)&wout_l, g_wout_l);
    cudaGetSymbolAddress((void**)&wxp_h, g_wxp_h);   cudaGetSymbolAddress((void**)&wxp_l, g_wxp_l);
    cudaGetSymbolAddress((void**)&wdt_h, g_wdt_h);   cudaGetSymbolAddress((void**)&wdt_l, g_wdt_l);
    cudaGetSymbolAddress((void**)&wd1_h, g_wd1_h);   cudaGetSymbolAddress((void**)&wd1_l, g_wd1_l);
    cudaGetSymbolAddress((void**)&wd2_h, g_wd2_h);   cudaGetSymbolAddress((void**)&wd2_l, g_wd2_l);

    cudaFuncSetAttribute(mma_gemm<0>, cudaFuncAttributeMaxDynamicSharedMemorySize, MMA_SMEM);
    cudaFuncSetAttribute(mma_gemm<1>, cudaFuncAttributeMaxDynamicSharedMemorySize, MMA_SMEM);
    cudaFuncSetAttribute(mma_gemm<2>, cudaFuncAttributeMaxDynamicSharedMemorySize, MMA_SMEM);
    cudaFuncSetAttribute(mma_gemm<3>, cudaFuncAttributeMaxDynamicSharedMemorySize, MMA_SMEM);
    cudaFuncSetAttribute(mma_gemm<4>, cudaFuncAttributeMaxDynamicSharedMemorySize, MMA_SMEM);
    cudaFuncSetAttribute(mma_gemm<5>, cudaFuncAttributeMaxDynamicSharedMemorySize, MMA_SMEM);

    float* out_dec = (float*)d_out;
    float* out_cls = (float*)d_out + ROWS * VOCAB;

    // Split weights to bf16 hi/lo (once per launch)
    int n;
    n = N_LAYERS * 2 * D_INNER * D_MODEL / 4;
    split_kernel<<<(n + 255) / 256, 256>>>((const float4*)in_proj_w, (bf162*)win_h, (bf162*)win_l, n);
    n = N_LAYERS * D_MODEL * D_INNER / 4;
    split_kernel<<<(n + 255) / 256, 256>>>((const float4*)out_proj_w, (bf162*)wout_h, (bf162*)wout_l, n);
    n = N_LAYERS * 96 * D_INNER / 4;
    split_kernel<<<(n + 255) / 256, 256>>>((const float4*)x_proj_w, (bf162*)wxp_h, (bf162*)wxp_l, n);
    n = N_LAYERS * D_INNER * DT_RANK / 4;
    split_kernel<<<(n + 255) / 256, 256>>>((const float4*)dt_proj_w, (bf162*)wdt_h, (bf162*)wdt_l, n);
    n = D_MODEL * D_MODEL / 4;
    split_kernel<<<(n + 255) / 256, 256>>>((const float4*)dec_fc1_w, (bf162*)wd1_h, (bf162*)wd1_l, n);
    n = VOCAB * D_MODEL / 4;
    split_kernel<<<(n + 255) / 256, 256>>>((const float4*)dec_fc2_w, (bf162*)wd2_h, (bf162*)wd2_l, n);

    embed_kernel<<<(ROWS * D_MODEL + 255) / 256, 256>>>(x_tok, embedding, pos_enc, h);

    for (int l = 0; l < N_LAYERS; l++) {
        const bf16* inw_h = win_h + (size_t)l * 2 * D_INNER * D_MODEL;
        const bf16* inw_l = win_l + (size_t)l * 2 * D_INNER * D_MODEL;
        const float* cw  = conv_w + (size_t)l * D_INNER * 4;
        const float* cb  = conv_b + (size_t)l * D_INNER;
        const bf16* xpw_h = wxp_h + (size_t)l * 96 * D_INNER;
        const bf16* xpw_l = wxp_l + (size_t)l * 96 * D_INNER;
        const bf16* dtw_h = wdt_h + (size_t)l * D_INNER * DT_RANK;
        const bf16* dtw_l = wdt_l + (size_t)l * D_INNER * DT_RANK;
        const float* dtb = dt_proj_b + (size_t)l * D_INNER;
        const float* al  = A_log + (size_t)l * D_INNER * D_STATE;
        const float* dp  = Dp + (size_t)l * D_INNER;
        const bf16* ow_h = wout_h + (size_t)l * D_MODEL * D_INNER;
        const bf16* ow_l = wout_l + (size_t)l * D_MODEL * D_INNER;
        const float* nw  = norm_w + (size_t)l * D_MODEL;

        rmsnorm_kernel<<<ROWS, 256>>>(h, nw, xn_h, xn_l);
        // xz = xn @ in_w^T      (4096 x 4096 x 1024)
        mma_gemm<0><<<dim3(2 * D_INNER / 128, ROWS / 128), 256, MMA_SMEM>>>(
            xn_h, xn_l, D_MODEL, inw_h, inw_l, D_MODEL,
            xz, nullptr, nullptr, 2 * D_INNER, 2 * D_INNER, D_MODEL, nullptr);
        conv_silu_kernel<<<(ROWS * D_INNER / 4 + 255) / 256, 256>>>(xz, cw, cb, xc, xc_h, xc_l);
        // dbc = xc @ xp_w^T     (4096 x 96 x 2048) -> fp32 + split
        mma_gemm<5><<<dim3(1, ROWS / 128), 256, MMA_SMEM>>>(
            xc_h, xc_l, D_INNER, xpw_h, xpw_l, D_INNER,
            dbc, dbc_h, dbc_l, 96, 96, D_INNER, nullptr);
        // delta = softplus(dbc[:, :64] @ dt_w^T + dtb)   (4096 x 2048 x 64)
        mma_gemm<3><<<dim3(D_INNER / 128, ROWS / 128), 256, MMA_SMEM>>>(
            dbc_h, dbc_l, 96, dtw_h, dtw_l, DT_RANK,
            delta, nullptr, nullptr, D_INNER, D_INNER, DT_RANK, dtb);
        scan_kernel<<<(BATCH * D_INNER / 2) / 8, 256>>>(delta, xc, dbc, xz, al, dp, y_h, y_l);
        // h += y @ out_w^T      (4096 x 1024 x 2048)
        mma_gemm<1><<<dim3(D_MODEL / 128, ROWS / 128), 256, MMA_SMEM>>>(
            y_h, y_l, D_INNER, ow_h, ow_l, D_INNER,
            h, nullptr, nullptr, D_MODEL, D_MODEL, D_INNER, nullptr);
    }

    // dec MLP: split h, fc1 (relu+bias -> split), fc2 (+bias)
    n = ROWS * D_MODEL / 4;
    split_kernel<<<(n + 255) / 256, 256>>>((const float4*)h, (bf162*)hs_h, (bf162*)hs_l, n);
    mma_gemm<2><<<dim3(D_MODEL / 128, ROWS / 128), 256, MMA_SMEM>>>(
        hs_h, hs_l, D_MODEL, wd1_h, wd1_l, D_MODEL,
        nullptr, t_h, t_l, D_MODEL, D_MODEL, D_MODEL, dec_fc1_b);
    mma_gemm<4><<<dim3(1, ROWS / 128), 256, MMA_SMEM>>>(
        t_h, t_l, D_MODEL, wd2_h, wd2_l, D_MODEL,
        out_dec, nullptr, nullptr, VOCAB, VOCAB, D_MODEL, dec_fc2_b);

    cls_kernel<<<BATCH, 256>>>(h, cls_fc1_w, cls_fc1_b, cls_fc2_w, cls_fc2_b, out_cls);
}

// round 9
// speedup vs baseline: 1.4960x; 1.0024x over previous
#include <cuda_runtime.h>
#include <cuda_bf16.h>
#include <math.h>
#include <stdint.h>

#define BATCH 4
#define SEQLEN 1024
#define VOCAB 28
#define D_MODEL 1024
#define N_LAYERS 4
#define D_INNER 2048
#define D_STATE 16
#define DT_RANK 64
#define NUM_CLS 2
#define ROWS (BATCH * SEQLEN)

typedef __nv_bfloat16 bf16;
typedef __nv_bfloat162 bf162;

// ---------------------------------------------------------------------------
// Scratch (device globals)
// ---------------------------------------------------------------------------
__device__ float g_h    [ROWS * D_MODEL];
__device__ float g_xz   [ROWS * 2 * D_INNER];
__device__ float g_xc   [ROWS * D_INNER];
__device__ float g_dbc  [ROWS * 96];
__device__ float g_delta[ROWS * D_INNER];

__device__ bf16 g_xn_h[ROWS * D_MODEL],  g_xn_l[ROWS * D_MODEL];
__device__ bf16 g_xc_h[ROWS * D_INNER],  g_xc_l[ROWS * D_INNER];
__device__ bf16 g_dbc_h[ROWS * 96],      g_dbc_l[ROWS * 96];
__device__ bf16 g_y_h [ROWS * D_INNER],  g_y_l [ROWS * D_INNER];
__device__ bf16 g_hs_h[ROWS * D_MODEL],  g_hs_l[ROWS * D_MODEL];
__device__ bf16 g_t_h [ROWS * D_MODEL],  g_t_l [ROWS * D_MODEL];

__device__ bf16 g_win_h [N_LAYERS * 2 * D_INNER * D_MODEL], g_win_l [N_LAYERS * 2 * D_INNER * D_MODEL];
__device__ bf16 g_wout_h[N_LAYERS * D_MODEL * D_INNER],     g_wout_l[N_LAYERS * D_MODEL * D_INNER];
__device__ bf16 g_wxp_h [N_LAYERS * 96 * D_INNER],          g_wxp_l [N_LAYERS * 96 * D_INNER];
__device__ bf16 g_wdt_h [N_LAYERS * D_INNER * DT_RANK],     g_wdt_l [N_LAYERS * D_INNER * DT_RANK];
__device__ bf16 g_wd1_h [D_MODEL * D_MODEL],                g_wd1_l [D_MODEL * D_MODEL];
__device__ bf16 g_wd2_h [VOCAB * D_MODEL],                  g_wd2_l [VOCAB * D_MODEL];

// ---------------------------------------------------------------------------
// Helpers
// ---------------------------------------------------------------------------
__device__ __forceinline__ uint32_t smem_u32(const void* p) {
    uint32_t a;
    asm("{ .reg .u64 t; cvta.to.shared.u64 t, %1; cvt.u32.u64 %0, t; }" : "=r"(a) : "l"(p));
    return a;
}
__device__ __forceinline__ void bsplit(float v, bf16& hi, bf16& lo) {
    hi = __float2bfloat16(v);
    lo = __float2bfloat16(v - __bfloat162float(hi));
}
__device__ __forceinline__ void cp_async16(uint32_t s, const void* g) {
    asm volatile("cp.async.cg.shared.global [%0], [%1], 16;" :: "r"(s), "l"(g) : "memory");
}
__device__ __forceinline__ void mma_bf16(
    float& c0, float& c1, float& c2, float& c3,
    uint32_t a0, uint32_t a1, uint32_t a2, uint32_t a3,
    uint32_t b0, uint32_t b1)
{
    asm volatile(
        "mma.sync.aligned.m16n8k16.row.col.f32.bf16.bf16.f32 "
        "{%0,%1,%2,%3}, {%4,%5,%6,%7}, {%8,%9}, {%0,%1,%2,%3};"
        : "+f"(c0), "+f"(c1), "+f"(c2), "+f"(c3)
        : "r"(a0), "r"(a1), "r"(a2), "r"(a3), "r"(b0), "r"(b1));
}
#define LDSM4(r0, r1, r2, r3, addr) \
    asm volatile("ldmatrix.sync.aligned.m8n8.x4.shared.b16 {%0,%1,%2,%3}, [%4];" \
        : "=r"(r0), "=r"(r1), "=r"(r2), "=r"(r3) : "r"(addr))

// ---------------------------------------------------------------------------
// 3-term bf16 mma GEMM (fp32-accurate): C[M,N] = A[M,K] * B[N,K]^T
// A,B given as precomputed bf16 hi/lo pairs. CTA 128x128, 256 threads,
// 8 warps (warp tile 64x32), BK=32, 4 stages, SW128 swizzle, ldmatrix loads.
// SMEM stage layout: A tile then B tile, each 128 rows x 128B.
//   Row r: chunks 0-3 = hi k[0..31], chunks 4-7 = lo k[0..31]; phys = c^(r&7).
// acc += Ahi*Bhi + Alo*Bhi + Ahi*Blo   (lo*lo dropped, ~2^-18)
// EPI: 0 C store | 1 C += | 2 relu(v+bias)->split | 3 softplus(v+bias)->C
//      4 v+bias->C | 5 v->C and split
// Requires M%128==0, K%32==0. N arbitrary (clamped loads, guarded stores).
// ---------------------------------------------------------------------------
#define NSTG 4
#define STGB 32768           // bytes per stage (A 16KB + B 16KB)

template <int EPI>
__global__ void __launch_bounds__(256) mma_gemm(
    const bf16* __restrict__ Ahi, const bf16* __restrict__ Alo, int lda,
    const bf16* __restrict__ Bhi, const bf16* __restrict__ Blo, int ldb,
    float* __restrict__ C, bf16* __restrict__ Chi, bf16* __restrict__ Clo,
    int ldc, int N, int K, const float* __restrict__ bias)
{
    extern __shared__ char smc[];
    const uint32_t smb = smem_u32(smc);

    const int tid = threadIdx.x;
    const int wid = tid >> 5, lane = tid & 31;
    const int g = lane >> 2, t = lane & 3;
    const int warp_m = (wid & 1) * 64;
    const int warp_n = (wid >> 1) * 32;
    const int bm = blockIdx.y * 128, bn = blockIdx.x * 128;
    const int niter = K >> 5;

    float acc[4][4][4];
    #pragma unroll
    for (int i = 0; i < 4; i++)
        #pragma unroll
        for (int j = 0; j < 4; j++)
            #pragma unroll
            for (int c = 0; c < 4; c++) acc[i][j][c] = 0.f;

    auto loadStage = [&](int it) {
        int s = it & (NSTG - 1);
        uint32_t sb = smb + (uint32_t)s * STGB;
        int k0 = it << 5;
        #pragma unroll
        for (int i = 0; i < 8; i++) {
            int cid = (i << 8) + tid;        // 0..2047
            int tile = cid >> 10;            // 0=A, 1=B
            int rc = cid & 1023;
            int r = rc >> 3, c = rc & 7;
            int ko = k0 + ((c & 3) << 3);
            const bf16* gp;
            if (tile == 0) {
                gp = ((c < 4) ? Ahi : Alo) + (size_t)(bm + r) * lda + ko;
            } else {
                int gn = bn + r; if (gn >= N) gn = N - 1;
                gp = ((c < 4) ? Bhi : Blo) + (size_t)gn * ldb + ko;
            }
            uint32_t sa = sb + ((uint32_t)tile << 14)
                        + (uint32_t)(r * 128 + ((c ^ (r & 7)) << 4));
            cp_async16(sa, gp);
        }
        asm volatile("cp.async.commit_group;" ::: "memory");
    };

    int npro = niter < (NSTG - 1) ? niter : (NSTG - 1);
    for (int p = 0; p < npro; p++) loadStage(p);

    // ldmatrix lane addressing (row bases are multiples of 8 -> xor mask = lane&7)
    const uint32_t aRow = (uint32_t)(warp_m + (lane & 15)) * 128;
    const uint32_t bRow = (uint32_t)(warp_n + ((lane >> 4) << 3) + (lane & 7)) * 128;
    const uint32_t aCs = (uint32_t)(lane >> 4);
    const uint32_t bCs = (uint32_t)((lane >> 3) & 1);
    const uint32_t xm = (uint32_t)(lane & 7);

    for (int it = 0; it < niter; it++) {
        int allow = niter - it - 1;
        if (allow > NSTG - 2) allow = NSTG - 2;
        if (allow == 0)      asm volatile("cp.async.wait_group 0;" ::: "memory");
        else if (allow == 1) asm volatile("cp.async.wait_group 1;" ::: "memory");
        else                 asm volatile("cp.async.wait_group 2;" ::: "memory");
        __syncthreads();

        if (it + NSTG - 1 < niter) loadStage(it + NSTG - 1);

        uint32_t sA = smb + (uint32_t)(it & (NSTG - 1)) * STGB;
        uint32_t sB = sA + 16384;

        #pragma unroll
        for (int ch = 0; ch < 2; ch++) {       // two k16 chunks per BK=32
            uint32_t ah[4][4], al[4][4], bh[4][2], bl[4][2];
            uint32_t ca = (uint32_t)(ch << 1) + aCs;
            uint32_t cb = (uint32_t)(ch << 1) + bCs;
            #pragma unroll
            for (int mt = 0; mt < 4; mt++) {
                uint32_t base = sA + aRow + (uint32_t)(mt * 2048);
                LDSM4(ah[mt][0], ah[mt][1], ah[mt][2], ah[mt][3],
                      base + ((ca ^ xm) << 4));
                LDSM4(al[mt][0], al[mt][1], al[mt][2], al[mt][3],
                      base + (((ca + 4) ^ xm) << 4));
            }
            #pragma unroll
            for (int ntp = 0; ntp < 2; ntp++) {
                uint32_t base = sB + bRow + (uint32_t)(ntp * 2048);
                LDSM4(bh[2 * ntp][0], bh[2 * ntp][1],
                      bh[2 * ntp + 1][0], bh[2 * ntp + 1][1],
                      base + ((cb ^ xm) << 4));
                LDSM4(bl[2 * ntp][0], bl[2 * ntp][1],
                      bl[2 * ntp + 1][0], bl[2 * ntp + 1][1],
                      base + (((cb + 4) ^ xm) << 4));
            }
            #pragma unroll
            for (int mt = 0; mt < 4; mt++)
                #pragma unroll
                for (int nt = 0; nt < 4; nt++) {
                    mma_bf16(acc[mt][nt][0], acc[mt][nt][1],
                             acc[mt][nt][2], acc[mt][nt][3],
                             al[mt][0], al[mt][1], al[mt][2], al[mt][3],
                             bh[nt][0], bh[nt][1]);
                    mma_bf16(acc[mt][nt][0], acc[mt][nt][1],
                             acc[mt][nt][2], acc[mt][nt][3],
                             ah[mt][0], ah[mt][1], ah[mt][2], ah[mt][3],
                             bl[nt][0], bl[nt][1]);
                    mma_bf16(acc[mt][nt][0], acc[mt][nt][1],
                             acc[mt][nt][2], acc[mt][nt][3],
                             ah[mt][0], ah[mt][1], ah[mt][2], ah[mt][3],
                             bh[nt][0], bh[nt][1]);
                }
        }
    }

    // Epilogue: c0=C[g][2t], c1=C[g][2t+1], c2=C[g+8][2t], c3=C[g+8][2t+1]
    #pragma unroll
    for (int mt = 0; mt < 4; mt++) {
        #pragma unroll
        for (int nt = 0; nt < 4; nt++) {
            int col = bn + warp_n + (nt << 3) + (t << 1);
            if (col >= N) continue;
            #pragma unroll
            for (int half = 0; half < 2; half++) {
                int row = bm + warp_m + (mt << 4) + g + half * 8;
                float v0 = acc[mt][nt][half * 2];
                float v1 = acc[mt][nt][half * 2 + 1];
                size_t idx = (size_t)row * ldc + col;
                if (EPI == 0) {
                    C[idx] = v0; C[idx + 1] = v1;
                } else if (EPI == 1) {
                    C[idx] += v0; C[idx + 1] += v1;
                } else if (EPI == 2) {
                    v0 = fmaxf(v0 + bias[col], 0.f);
                    v1 = fmaxf(v1 + bias[col + 1], 0.f);
                    bf16 h0, l0, h1, l1;
                    bsplit(v0, h0, l0); bsplit(v1, h1, l1);
                    Chi[idx] = h0; Chi[idx + 1] = h1;
                    Clo[idx] = l0; Clo[idx + 1] = l1;
                } else if (EPI == 3) {
                    v0 += bias[col]; v1 += bias[col + 1];
                    v0 = (v0 > 20.f) ? v0 : log1pf(__expf(v0));
                    v1 = (v1 > 20.f) ? v1 : log1pf(__expf(v1));
                    C[idx] = v0; C[idx + 1] = v1;
                } else if (EPI == 4) {
                    C[idx] = v0 + bias[col]; C[idx + 1] = v1 + bias[col + 1];
                } else {
                    C[idx] = v0; C[idx + 1] = v1;
                    bf16 h0, l0, h1, l1;
                    bsplit(v0, h0, l0); bsplit(v1, h1, l1);
                    Chi[idx] = h0; Chi[idx + 1] = h1;
                    Clo[idx] = l0; Clo[idx + 1] = l1;
                }
            }
        }
    }
}

// ---------------------------------------------------------------------------
// Elementwise / small kernels
// ---------------------------------------------------------------------------
__global__ void split_kernel(const float4* __restrict__ src,
                             bf162* __restrict__ hi2, bf162* __restrict__ lo2, int n4) {
    int i = blockIdx.x * blockDim.x + threadIdx.x;
    if (i >= n4) return;
    float4 v = src[i];
    bf16 h0, l0, h1, l1, h2, l2, h3, l3;
    bsplit(v.x, h0, l0); bsplit(v.y, h1, l1);
    bsplit(v.z, h2, l2); bsplit(v.w, h3, l3);
    bf162 a; a.x = h0; a.y = h1;
    bf162 b; b.x = h2; b.y = h3;
    bf162 c; c.x = l0; c.y = l1;
    bf162 d; d.x = l2; d.y = l3;
    hi2[i * 2] = a; hi2[i * 2 + 1] = b;
    lo2[i * 2] = c; lo2[i * 2 + 1] = d;
}

__global__ void embed_kernel(const int* __restrict__ x, const float* __restrict__ emb,
                             const float* __restrict__ pos, float* __restrict__ out) {
    int idx = blockIdx.x * blockDim.x + threadIdx.x;
    if (idx >= ROWS * D_MODEL) return;
    int d = idx & (D_MODEL - 1), r = idx >> 10, l = r & (SEQLEN - 1);
    out[idx] = emb[x[r] * D_MODEL + d] + pos[l * D_MODEL + d];
}

__global__ void rmsnorm_kernel(const float* __restrict__ h, const float* __restrict__ w,
                               bf16* __restrict__ oh, bf16* __restrict__ ol) {
    int r = blockIdx.x, tid = threadIdx.x;
    const float* row = h + (size_t)r * D_MODEL;
    float s = 0.f;
    #pragma unroll
    for (int i = tid; i < D_MODEL; i += 256) { float v = row[i]; s += v * v; }
    __shared__ float red[8];
    #pragma unroll
    for (int o = 16; o > 0; o >>= 1) s += __shfl_down_sync(0xffffffffu, s, o);
    if ((tid & 31) == 0) red[tid >> 5] = s;
    __syncthreads();
    __shared__ float scale;
    if (tid == 0) {
        float tt = 0.f;
        #pragma unroll
        for (int i = 0; i < 8; i++) tt += red[i];
        scale = rsqrtf(tt * (1.0f / D_MODEL) + 1e-5f);
    }
    __syncthreads();
    float sc = scale;
    #pragma unroll
    for (int i = tid; i < D_MODEL; i += 256) {
        bf16 hh, ll;
        bsplit(row[i] * sc * w[i], hh, ll);
        oh[(size_t)r * D_MODEL + i] = hh;
        ol[(size_t)r * D_MODEL + i] = ll;
    }
}

__global__ void conv_silu_kernel(const float* __restrict__ xz, const float* __restrict__ cw,
                                 const float* __restrict__ cb, float* __restrict__ xc,
                                 bf16* __restrict__ xch, bf16* __restrict__ xcl) {
    int idx = blockIdx.x * blockDim.x + threadIdx.x;
    if (idx >= ROWS * D_INNER / 4) return;
    int d4 = (idx & (D_INNER / 4 - 1)) << 2;
    int r = idx >> 9, l = r & (SEQLEN - 1);
    float4 wa = *(const float4*)(cw + d4 * 4);
    float4 wb = *(const float4*)(cw + d4 * 4 + 4);
    float4 wc = *(const float4*)(cw + d4 * 4 + 8);
    float4 wd = *(const float4*)(cw + d4 * 4 + 12);
    float4 acc = *(const float4*)(cb + d4);
    const float* base = xz + (size_t)r * (2 * D_INNER) + d4;
    if (l >= 3) { float4 x = *(const float4*)(base - 3 * 2 * D_INNER);
        acc.x = fmaf(x.x, wa.x, acc.x); acc.y = fmaf(x.y, wb.x, acc.y);
        acc.z = fmaf(x.z, wc.x, acc.z); acc.w = fmaf(x.w, wd.x, acc.w); }
    if (l >= 2) { float4 x = *(const float4*)(base - 2 * 2 * D_INNER);
        acc.x = fmaf(x.x, wa.y, acc.x); acc.y = fmaf(x.y, wb.y, acc.y);
        acc.z = fmaf(x.z, wc.y, acc.z); acc.w = fmaf(x.w, wd.y, acc.w); }
    if (l >= 1) { float4 x = *(const float4*)(base - 2 * D_INNER);
        acc.x = fmaf(x.x, wa.z, acc.x); acc.y = fmaf(x.y, wb.z, acc.y);
        acc.z = fmaf(x.z, wc.z, acc.z); acc.w = fmaf(x.w, wd.z, acc.w); }
    { float4 x = *(const float4*)(base);
        acc.x = fmaf(x.x, wa.w, acc.x); acc.y = fmaf(x.y, wb.w, acc.y);
        acc.z = fmaf(x.z, wc.w, acc.z); acc.w = fmaf(x.w, wd.w, acc.w); }
    acc.x = acc.x / (1.f + __expf(-acc.x));
    acc.y = acc.y / (1.f + __expf(-acc.y));
    acc.z = acc.z / (1.f + __expf(-acc.z));
    acc.w = acc.w / (1.f + __expf(-acc.w));
    size_t o = (size_t)r * D_INNER + d4;
    *(float4*)(xc + o) = acc;
    bf16 h0, l0, h1, l1, h2, l2, h3, l3;
    bsplit(acc.x, h0, l0); bsplit(acc.y, h1, l1);
    bsplit(acc.z, h2, l2); bsplit(acc.w, h3, l3);
    bf162 ph0; ph0.x = h0; ph0.y = h1;
    bf162 ph1; ph1.x = h2; ph1.y = h3;
    bf162 pl0; pl0.x = l0; pl0.y = l1;
    bf162 pl1; pl1.x = l2; pl1.y = l3;
    *(bf162*)(xch + o) = ph0; *(bf162*)(xch + o + 2) = ph1;
    *(bf162*)(xcl + o) = pl0; *(bf162*)(xcl + o + 2) = pl1;
}

__global__ void scan_kernel(const float* __restrict__ delta, const float* __restrict__ xc,
                            const float* __restrict__ dbc, const float* __restrict__ xz,
                            const float* __restrict__ A_log, const float* __restrict__ Dp,
                            bf16* __restrict__ yh, bf16* __restrict__ yl) {
    int gwarp = (blockIdx.x * blockDim.x + threadIdx.x) >> 5;
    int lane = threadIdx.x & 31, n = lane & 15;
    int pair = gwarp * 2 + (lane >> 4);
    int b = pair >> 11, d = pair & (D_INNER - 1);
    if (b >= BATCH) return;
    float An = -__expf(A_log[d * D_STATE + n]);
    float Dv = Dp[d], h = 0.f;
    size_t rbase = (size_t)b * SEQLEN;
    for (int l = 0; l < SEQLEN; l++) {
        size_t r = rbase + l;
        float dlt = delta[r * D_INNER + d];
        float xcv = xc[r * D_INNER + d];
        float Bv = dbc[r * 96 + DT_RANK + n];
        float Cv = dbc[r * 96 + DT_RANK + D_STATE + n];
        float dA = __expf(dlt * An);
        h = fmaf(dA, h, dlt * xcv * Bv);
        float y = h * Cv;
        y += __shfl_xor_sync(0xffffffffu, y, 1);
        y += __shfl_xor_sync(0xffffffffu, y, 2);
        y += __shfl_xor_sync(0xffffffffu, y, 4);
        y += __shfl_xor_sync(0xffffffffu, y, 8);
        if (n == 0) {
            float zv = xz[r * (2 * D_INNER) + D_INNER + d];
            float sz = zv / (1.f + __expf(-zv));
            bf16 hh, ll;
            bsplit((y + Dv * xcv) * sz, hh, ll);
            yh[r * D_INNER + d] = hh;
            yl[r * D_INNER + d] = ll;
        }
    }
}

__global__ void cls_kernel(const float* __restrict__ h,
                           const float* __restrict__ w1, const float* __restrict__ b1,
                           const float* __restrict__ w2, const float* __restrict__ b2,
                           float* __restrict__ out) {
    __shared__ float sh[D_MODEL];
    __shared__ float t1[D_MODEL];
    __shared__ float red[256];
    int b = blockIdx.x, tid = threadIdx.x;
    const float* row = h + ((size_t)b * SEQLEN + (SEQLEN - 1)) * D_MODEL;
    for (int i = tid; i < D_MODEL; i += 256) sh[i] = row[i];
    __syncthreads();
    for (int e = tid; e < D_MODEL; e += 256) {
        const float* wr = w1 + (size_t)e * D_MODEL;
        float acc = b1[e];
        #pragma unroll 4
        for (int k = 0; k < D_MODEL; k += 4) {
            float4 w4 = *(const float4*)(wr + k);
            acc = fmaf(sh[k], w4.x, acc); acc = fmaf(sh[k + 1], w4.y, acc);
            acc = fmaf(sh[k + 2], w4.z, acc); acc = fmaf(sh[k + 3], w4.w, acc);
        }
        t1[e] = acc > 0.f ? acc : 0.f;
    }
    __syncthreads();
    for (int c = 0; c < NUM_CLS; c++) {
        float p = 0.f;
        for (int k = tid; k < D_MODEL; k += 256) p = fmaf(t1[k], w2[c * D_MODEL + k], p);
        red[tid] = p;
        __syncthreads();
        for (int s = 128; s > 0; s >>= 1) { if (tid < s) red[tid] += red[tid + s]; __syncthreads(); }
        if (tid == 0) out[b * NUM_CLS + c] = red[0] + b2[c];
        __syncthreads();
    }
}

// ---------------------------------------------------------------------------
// Launch
// ---------------------------------------------------------------------------
#define MMA_SMEM (NSTG * STGB)   // 131072 bytes

extern "C" void kernel_launch(void* const* d_in, const int* in_sizes, int n_in,
                              void* d_out, int out_size)
{
    const int*   x_tok      = (const int*)d_in[0];
    const float* embedding  = (const float*)d_in[1];
    const float* pos_enc    = (const float*)d_in[2];
    const float* norm_w     = (const float*)d_in[3];
    const float* in_proj_w  = (const float*)d_in[4];
    const float* conv_w     = (const float*)d_in[5];
    const float* conv_b     = (const float*)d_in[6];
    const float* x_proj_w   = (const float*)d_in[7];
    const float* dt_proj_w  = (const float*)d_in[8];
    const float* dt_proj_b  = (const float*)d_in[9];
    const float* A_log      = (const float*)d_in[10];
    const float* Dp         = (const float*)d_in[11];
    const float* out_proj_w = (const float*)d_in[12];
    const float* cls_fc1_w  = (const float*)d_in[13];
    const float* cls_fc1_b  = (const float*)d_in[14];
    const float* cls_fc2_w  = (const float*)d_in[15];
    const float* cls_fc2_b  = (const float*)d_in[16];
    const float* dec_fc1_w  = (const float*)d_in[17];
    const float* dec_fc1_b  = (const float*)d_in[18];
    const float* dec_fc2_w  = (const float*)d_in[19];
    const float* dec_fc2_b  = (const float*)d_in[20];

    float *h, *xz, *xc, *dbc, *delta;
    bf16 *xn_h, *xn_l, *xc_h, *xc_l, *dbc_h, *dbc_l, *y_h, *y_l, *hs_h, *hs_l, *t_h, *t_l;
    bf16 *win_h, *win_l, *wout_h, *wout_l, *wxp_h, *wxp_l, *wdt_h, *wdt_l, *wd1_h, *wd1_l, *wd2_h, *wd2_l;
    cudaGetSymbolAddress((void**)&h, g_h);
    cudaGetSymbolAddress((void**)&xz, g_xz);
    cudaGetSymbolAddress((void**)&xc, g_xc);
    cudaGetSymbolAddress((void**)&dbc, g_dbc);
    cudaGetSymbolAddress((void**)&delta, g_delta);
    cudaGetSymbolAddress((void**)&xn_h, g_xn_h);  cudaGetSymbolAddress((void**)&xn_l, g_xn_l);
    cudaGetSymbolAddress((void**)&xc_h, g_xc_h);  cudaGetSymbolAddress((void**)&xc_l, g_xc_l);
    cudaGetSymbolAddress((void**)&dbc_h, g_dbc_h); cudaGetSymbolAddress((void**)&dbc_l, g_dbc_l);
    cudaGetSymbolAddress((void**)&y_h, g_y_h);    cudaGetSymbolAddress((void**)&y_l, g_y_l);
    cudaGetSymbolAddress((void**)&hs_h, g_hs_h);  cudaGetSymbolAddress((void**)&hs_l, g_hs_l);
    cudaGetSymbolAddress((void**)&t_h, g_t_h);    cudaGetSymbolAddress((void**)&t_l, g_t_l);
    cudaGetSymbolAddress((void**)&win_h, g_win_h);   cudaGetSymbolAddress((void**)&win_l, g_win_l);
    cudaGetSymbolAddress((void**)&wout_h, g_wout_h); cudaGetSymbolAddress((void**)&wout_l, g_wout_l);
    cudaGetSymbolAddress((void**)&wxp_h, g_wxp_h);   cudaGetSymbolAddress((void**)&wxp_l, g_wxp_l);
    cudaGetSymbolAddress((void**)&wdt_h, g_wdt_h);   cudaGetSymbolAddress((void**)&wdt_l, g_wdt_l);
    cudaGetSymbolAddress((void**)&wd1_h, g_wd1_h);   cudaGetSymbolAddress((void**)&wd1_l, g_wd1_l);
    cudaGetSymbolAddress((void**)&wd2_h, g_wd2_h);   cudaGetSymbolAddress((void**)&wd2_l, g_wd2_l);

    cudaFuncSetAttribute(mma_gemm<0>, cudaFuncAttributeMaxDynamicSharedMemorySize, MMA_SMEM);
    cudaFuncSetAttribute(mma_gemm<1>, cudaFuncAttributeMaxDynamicSharedMemorySize, MMA_SMEM);
    cudaFuncSetAttribute(mma_gemm<2>, cudaFuncAttributeMaxDynamicSharedMemorySize, MMA_SMEM);
    cudaFuncSetAttribute(mma_gemm<3>, cudaFuncAttributeMaxDynamicSharedMemorySize, MMA_SMEM);
    cudaFuncSetAttribute(mma_gemm<4>, cudaFuncAttributeMaxDynamicSharedMemorySize, MMA_SMEM);
    cudaFuncSetAttribute(mma_gemm<5>, cudaFuncAttributeMaxDynamicSharedMemorySize, MMA_SMEM);

    float* out_dec = (float*)d_out;
    float* out_cls = (float*)d_out + ROWS * VOCAB;

    // Split weights to bf16 hi/lo (once per launch)
    int n;
    n = N_LAYERS * 2 * D_INNER * D_MODEL / 4;
    split_kernel<<<(n + 255) / 256, 256>>>((const float4*)in_proj_w, (bf162*)win_h, (bf162*)win_l, n);
    n = N_LAYERS * D_MODEL * D_INNER / 4;
    split_kernel<<<(n + 255) / 256, 256>>>((const float4*)out_proj_w, (bf162*)wout_h, (bf162*)wout_l, n);
    n = N_LAYERS * 96 * D_INNER / 4;
    split_kernel<<<(n + 255) / 256, 256>>>((const float4*)x_proj_w, (bf162*)wxp_h, (bf162*)wxp_l, n);
    n = N_LAYERS * D_INNER * DT_RANK / 4;
    split_kernel<<<(n + 255) / 256, 256>>>((const float4*)dt_proj_w, (bf162*)wdt_h, (bf162*)wdt_l, n);
    n = D_MODEL * D_MODEL / 4;
    split_kernel<<<(n + 255) / 256, 256>>>((const float4*)dec_fc1_w, (bf162*)wd1_h, (bf162*)wd1_l, n);
    n = VOCAB * D_MODEL / 4;
    split_kernel<<<(n + 255) / 256, 256>>>((const float4*)dec_fc2_w, (bf162*)wd2_h, (bf162*)wd2_l, n);

    embed_kernel<<<(ROWS * D_MODEL + 255) / 256, 256>>>(x_tok, embedding, pos_enc, h);

    for (int l = 0; l < N_LAYERS; l++) {
        const bf16* inw_h = win_h + (size_t)l * 2 * D_INNER * D_MODEL;
        const bf16* inw_l = win_l + (size_t)l * 2 * D_INNER * D_MODEL;
        const float* cw  = conv_w + (size_t)l * D_INNER * 4;
        const float* cb  = conv_b + (size_t)l * D_INNER;
        const bf16* xpw_h = wxp_h + (size_t)l * 96 * D_INNER;
        const bf16* xpw_l = wxp_l + (size_t)l * 96 * D_INNER;
        const bf16* dtw_h = wdt_h + (size_t)l * D_INNER * DT_RANK;
        const bf16* dtw_l = wdt_l + (size_t)l * D_INNER * DT_RANK;
        const float* dtb = dt_proj_b + (size_t)l * D_INNER;
        const float* al  = A_log + (size_t)l * D_INNER * D_STATE;
        const float* dp  = Dp + (size_t)l * D_INNER;
        const bf16* ow_h = wout_h + (size_t)l * D_MODEL * D_INNER;
        const bf16* ow_l = wout_l + (size_t)l * D_MODEL * D_INNER;
        const float* nw  = norm_w + (size_t)l * D_MODEL;

        rmsnorm_kernel<<<ROWS, 256>>>(h, nw, xn_h, xn_l);
        // xz = xn @ in_w^T      (4096 x 4096 x 1024)
        mma_gemm<0><<<dim3(2 * D_INNER / 128, ROWS / 128), 256, MMA_SMEM>>>(
            xn_h, xn_l, D_MODEL, inw_h, inw_l, D_MODEL,
            xz, nullptr, nullptr, 2 * D_INNER, 2 * D_INNER, D_MODEL, nullptr);
        conv_silu_kernel<<<(ROWS * D_INNER / 4 + 255) / 256, 256>>>(xz, cw, cb, xc, xc_h, xc_l);
        // dbc = xc @ xp_w^T     (4096 x 96 x 2048) -> fp32 + split
        mma_gemm<5><<<dim3(1, ROWS / 128), 256, MMA_SMEM>>>(
            xc_h, xc_l, D_INNER, xpw_h, xpw_l, D_INNER,
            dbc, dbc_h, dbc_l, 96, 96, D_INNER, nullptr);
        // delta = softplus(dbc[:, :64] @ dt_w^T + dtb)   (4096 x 2048 x 64)
        mma_gemm<3><<<dim3(D_INNER / 128, ROWS / 128), 256, MMA_SMEM>>>(
            dbc_h, dbc_l, 96, dtw_h, dtw_l, DT_RANK,
            delta, nullptr, nullptr, D_INNER, D_INNER, DT_RANK, dtb);
        scan_kernel<<<(BATCH * D_INNER / 2) / 8, 256>>>(delta, xc, dbc, xz, al, dp, y_h, y_l);
        // h += y @ out_w^T      (4096 x 1024 x 2048)
        mma_gemm<1><<<dim3(D_MODEL / 128, ROWS / 128), 256, MMA_SMEM>>>(
            y_h, y_l, D_INNER, ow_h, ow_l, D_INNER,
            h, nullptr, nullptr, D_MODEL, D_MODEL, D_INNER, nullptr);
    }

    // dec MLP: split h, fc1 (relu+bias -> split), fc2 (+bias)
    n = ROWS * D_MODEL / 4;
    split_kernel<<<(n + 255) / 256, 256>>>((const float4*)h, (bf162*)hs_h, (bf162*)hs_l, n);
    mma_gemm<2><<<dim3(D_MODEL / 128, ROWS / 128), 256, MMA_SMEM>>>(
        hs_h, hs_l, D_MODEL, wd1_h, wd1_l, D_MODEL,
        nullptr, t_h, t_l, D_MODEL, D_MODEL, D_MODEL, dec_fc1_b);
    mma_gemm<4><<<dim3(1, ROWS / 128), 256, MMA_SMEM>>>(
        t_h, t_l, D_MODEL, wd2_h, wd2_l, D_MODEL,
        out_dec, nullptr, nullptr, VOCAB, VOCAB, D_MODEL, dec_fc2_b);

    cls_kernel<<<BATCH, 256>>>(h, cls_fc1_w, cls_fc1_b, cls_fc2_w, cls_fc2_b, out_cls);
}

// round 11
// speedup vs baseline: 1.5836x; 1.0586x over previous
#include <cuda_runtime.h>
#include <cuda_bf16.h>
#include <math.h>
#include <stdint.h>

#define BATCH 4
#define SEQLEN 1024
#define VOCAB 28
#define D_MODEL 1024
#define N_LAYERS 4
#define D_INNER 2048
#define D_STATE 16
#define DT_RANK 64
#define NUM_CLS 2
#define ROWS (BATCH * SEQLEN)

typedef __nv_bfloat16 bf16;
typedef __nv_bfloat162 bf162;

// ---------------------------------------------------------------------------
// Scratch (device globals)
// ---------------------------------------------------------------------------
__device__ float g_h    [ROWS * D_MODEL];
__device__ float g_xz   [ROWS * 2 * D_INNER];
__device__ float g_xc   [ROWS * D_INNER];
__device__ float g_dbc  [ROWS * 96];
__device__ float g_delta[ROWS * D_INNER];

__device__ bf16 g_xn_h[ROWS * D_MODEL],  g_xn_l[ROWS * D_MODEL];
__device__ bf16 g_xc_h[ROWS * D_INNER],  g_xc_l[ROWS * D_INNER];
__device__ bf16 g_dbc_h[ROWS * 96],      g_dbc_l[ROWS * 96];
__device__ bf16 g_y_h [ROWS * D_INNER],  g_y_l [ROWS * D_INNER];
__device__ bf16 g_hs_h[ROWS * D_MODEL],  g_hs_l[ROWS * D_MODEL];
__device__ bf16 g_t_h [ROWS * D_MODEL],  g_t_l [ROWS * D_MODEL];

__device__ bf16 g_win_h [N_LAYERS * 2 * D_INNER * D_MODEL], g_win_l [N_LAYERS * 2 * D_INNER * D_MODEL];
__device__ bf16 g_wout_h[N_LAYERS * D_MODEL * D_INNER],     g_wout_l[N_LAYERS * D_MODEL * D_INNER];
__device__ bf16 g_wxp_h [N_LAYERS * 96 * D_INNER],          g_wxp_l [N_LAYERS * 96 * D_INNER];
__device__ bf16 g_wdt_h [N_LAYERS * D_INNER * DT_RANK],     g_wdt_l [N_LAYERS * D_INNER * DT_RANK];
__device__ bf16 g_wd1_h [D_MODEL * D_MODEL],                g_wd1_l [D_MODEL * D_MODEL];
__device__ bf16 g_wd2_h [VOCAB * D_MODEL],                  g_wd2_l [VOCAB * D_MODEL];

// ---------------------------------------------------------------------------
// Helpers
// ---------------------------------------------------------------------------
__device__ __forceinline__ uint32_t smem_u32(const void* p) {
    uint32_t a;
    asm("{ .reg .u64 t; cvta.to.shared.u64 t, %1; cvt.u32.u64 %0, t; }" : "=r"(a) : "l"(p));
    return a;
}
__device__ __forceinline__ void bsplit(float v, bf16& hi, bf16& lo) {
    hi = __float2bfloat16(v);
    lo = __float2bfloat16(v - __bfloat162float(hi));
}
__device__ __forceinline__ void cp_async16(uint32_t s, const void* g) {
    asm volatile("cp.async.cg.shared.global [%0], [%1], 16;" :: "r"(s), "l"(g) : "memory");
}
__device__ __forceinline__ void mma_bf16(
    float& c0, float& c1, float& c2, float& c3,
    uint32_t a0, uint32_t a1, uint32_t a2, uint32_t a3,
    uint32_t b0, uint32_t b1)
{
    asm volatile(
        "mma.sync.aligned.m16n8k16.row.col.f32.bf16.bf16.f32 "
        "{%0,%1,%2,%3}, {%4,%5,%6,%7}, {%8,%9}, {%0,%1,%2,%3};"
        : "+f"(c0), "+f"(c1), "+f"(c2), "+f"(c3)
        : "r"(a0), "r"(a1), "r"(a2), "r"(a3), "r"(b0), "r"(b1));
}
#define LDSM4(r0, r1, r2, r3, addr) \
    asm volatile("ldmatrix.sync.aligned.m8n8.x4.shared.b16 {%0,%1,%2,%3}, [%4];" \
        : "=r"(r0), "=r"(r1), "=r"(r2), "=r"(r3) : "r"(addr))

// ---------------------------------------------------------------------------
// 3-term bf16 mma GEMM (fp32-accurate): C[M,N] = A[M,K] * B[N,K]^T
// A,B given as precomputed bf16 hi/lo pairs. CTA 128x128, 256 threads,
// 8 warps (warp tile 64x32), BK=32, 3 stages (96KB -> 2 CTAs/SM), SW128
// swizzle, ldmatrix loads.
// SMEM stage layout: A tile then B tile, each 128 rows x 128B.
//   Row r: chunks 0-3 = hi k[0..31], chunks 4-7 = lo k[0..31]; phys = c^(r&7).
// acc += Ahi*Bhi + Alo*Bhi + Ahi*Blo   (lo*lo dropped, ~2^-18)
// EPI: 0 C store | 1 C += | 2 relu(v+bias)->split | 3 softplus(v+bias)->C
//      4 v+bias->C | 5 v->C and split
// Requires M%128==0, K%32==0. N arbitrary (clamped loads, guarded stores).
// ---------------------------------------------------------------------------
#define NSTG 3
#define STGB 32768           // bytes per stage (A 16KB + B 16KB)

template <int EPI>
__global__ void __launch_bounds__(256, 2) mma_gemm(
    const bf16* __restrict__ Ahi, const bf16* __restrict__ Alo, int lda,
    const bf16* __restrict__ Bhi, const bf16* __restrict__ Blo, int ldb,
    float* __restrict__ C, bf16* __restrict__ Chi, bf16* __restrict__ Clo,
    int ldc, int N, int K, const float* __restrict__ bias)
{
    extern __shared__ char smc[];
    const uint32_t smb = smem_u32(smc);

    const int tid = threadIdx.x;
    const int wid = tid >> 5, lane = tid & 31;
    const int g = lane >> 2, t = lane & 3;
    const int warp_m = (wid & 1) * 64;
    const int warp_n = (wid >> 1) * 32;
    const int bm = blockIdx.y * 128, bn = blockIdx.x * 128;
    const int niter = K >> 5;

    float acc[4][4][4];
    #pragma unroll
    for (int i = 0; i < 4; i++)
        #pragma unroll
        for (int j = 0; j < 4; j++)
            #pragma unroll
            for (int c = 0; c < 4; c++) acc[i][j][c] = 0.f;

    auto loadStage = [&](int it) {
        int s = it % NSTG;
        uint32_t sb = smb + (uint32_t)s * STGB;
        int k0 = it << 5;
        #pragma unroll
        for (int i = 0; i < 8; i++) {
            int cid = (i << 8) + tid;        // 0..2047
            int tile = cid >> 10;            // 0=A, 1=B
            int rc = cid & 1023;
            int r = rc >> 3, c = rc & 7;
            int ko = k0 + ((c & 3) << 3);
            const bf16* gp;
            if (tile == 0) {
                gp = ((c < 4) ? Ahi : Alo) + (size_t)(bm + r) * lda + ko;
            } else {
                int gn = bn + r; if (gn >= N) gn = N - 1;
                gp = ((c < 4) ? Bhi : Blo) + (size_t)gn * ldb + ko;
            }
            uint32_t sa = sb + ((uint32_t)tile << 14)
                        + (uint32_t)(r * 128 + ((c ^ (r & 7)) << 4));
            cp_async16(sa, gp);
        }
        asm volatile("cp.async.commit_group;" ::: "memory");
    };

    int npro = niter < (NSTG - 1) ? niter : (NSTG - 1);
    for (int p = 0; p < npro; p++) loadStage(p);

    // ldmatrix lane addressing (row bases are multiples of 8 -> xor mask = lane&7)
    const uint32_t aRow = (uint32_t)(warp_m + (lane & 15)) * 128;
    const uint32_t bRow = (uint32_t)(warp_n + ((lane >> 4) << 3) + (lane & 7)) * 128;
    const uint32_t aCs = (uint32_t)(lane >> 4);
    const uint32_t bCs = (uint32_t)((lane >> 3) & 1);
    const uint32_t xm = (uint32_t)(lane & 7);

    for (int it = 0; it < niter; it++) {
        int allow = niter - it - 1;
        if (allow > NSTG - 2) allow = NSTG - 2;
        if (allow == 0)      asm volatile("cp.async.wait_group 0;" ::: "memory");
        else                 asm volatile("cp.async.wait_group 1;" ::: "memory");
        __syncthreads();

        if (it + NSTG - 1 < niter) loadStage(it + NSTG - 1);

        uint32_t sA = smb + (uint32_t)(it % NSTG) * STGB;
        uint32_t sB = sA + 16384;

        #pragma unroll
        for (int ch = 0; ch < 2; ch++) {       // two k16 chunks per BK=32
            uint32_t ah[4][4], al[4][4], bh[4][2], bl[4][2];
            uint32_t ca = (uint32_t)(ch << 1) + aCs;
            uint32_t cb = (uint32_t)(ch << 1) + bCs;
            #pragma unroll
            for (int mt = 0; mt < 4; mt++) {
                uint32_t base = sA + aRow + (uint32_t)(mt * 2048);
                LDSM4(ah[mt][0], ah[mt][1], ah[mt][2], ah[mt][3],
                      base + ((ca ^ xm) << 4));
                LDSM4(al[mt][0], al[mt][1], al[mt][2], al[mt][3],
                      base + (((ca + 4) ^ xm) << 4));
            }
            #pragma unroll
            for (int ntp = 0; ntp < 2; ntp++) {
                uint32_t base = sB + bRow + (uint32_t)(ntp * 2048);
                LDSM4(bh[2 * ntp][0], bh[2 * ntp][1],
                      bh[2 * ntp + 1][0], bh[2 * ntp + 1][1],
                      base + ((cb ^ xm) << 4));
                LDSM4(bl[2 * ntp][0], bl[2 * ntp][1],
                      bl[2 * ntp + 1][0], bl[2 * ntp + 1][1],
                      base + (((cb + 4) ^ xm) << 4));
            }
            #pragma unroll
            for (int mt = 0; mt < 4; mt++)
                #pragma unroll
                for (int nt = 0; nt < 4; nt++) {
                    mma_bf16(acc[mt][nt][0], acc[mt][nt][1],
                             acc[mt][nt][2], acc[mt][nt][3],
                             al[mt][0], al[mt][1], al[mt][2], al[mt][3],
                             bh[nt][0], bh[nt][1]);
                    mma_bf16(acc[mt][nt][0], acc[mt][nt][1],
                             acc[mt][nt][2], acc[mt][nt][3],
                             ah[mt][0], ah[mt][1], ah[mt][2], ah[mt][3],
                             bl[nt][0], bl[nt][1]);
                    mma_bf16(acc[mt][nt][0], acc[mt][nt][1],
                             acc[mt][nt][2], acc[mt][nt][3],
                             ah[mt][0], ah[mt][1], ah[mt][2], ah[mt][3],
                             bh[nt][0], bh[nt][1]);
                }
        }
    }

    // Epilogue: c0=C[g][2t], c1=C[g][2t+1], c2=C[g+8][2t], c3=C[g+8][2t+1]
    #pragma unroll
    for (int mt = 0; mt < 4; mt++) {
        #pragma unroll
        for (int nt = 0; nt < 4; nt++) {
            int col = bn + warp_n + (nt << 3) + (t << 1);
            if (col >= N) continue;
            #pragma unroll
            for (int half = 0; half < 2; half++) {
                int row = bm + warp_m + (mt << 4) + g + half * 8;
                float v0 = acc[mt][nt][half * 2];
                float v1 = acc[mt][nt][half * 2 + 1];
                size_t idx = (size_t)row * ldc + col;
                if (EPI == 0) {
                    C[idx] = v0; C[idx + 1] = v1;
                } else if (EPI == 1) {
                    C[idx] += v0; C[idx + 1] += v1;
                } else if (EPI == 2) {
                    v0 = fmaxf(v0 + bias[col], 0.f);
                    v1 = fmaxf(v1 + bias[col + 1], 0.f);
                    bf16 h0, l0, h1, l1;
                    bsplit(v0, h0, l0); bsplit(v1, h1, l1);
                    Chi[idx] = h0; Chi[idx + 1] = h1;
                    Clo[idx] = l0; Clo[idx + 1] = l1;
                } else if (EPI == 3) {
                    v0 += bias[col]; v1 += bias[col + 1];
                    v0 = (v0 > 20.f) ? v0 : log1pf(__expf(v0));
                    v1 = (v1 > 20.f) ? v1 : log1pf(__expf(v1));
                    C[idx] = v0; C[idx + 1] = v1;
                } else if (EPI == 4) {
                    C[idx] = v0 + bias[col]; C[idx + 1] = v1 + bias[col + 1];
                } else {
                    C[idx] = v0; C[idx + 1] = v1;
                    bf16 h0, l0, h1, l1;
                    bsplit(v0, h0, l0); bsplit(v1, h1, l1);
                    Chi[idx] = h0; Chi[idx + 1] = h1;
                    Clo[idx] = l0; Clo[idx + 1] = l1;
                }
            }
        }
    }
}

// ---------------------------------------------------------------------------
// Elementwise / small kernels
// ---------------------------------------------------------------------------
__global__ void split_kernel(const float4* __restrict__ src,
                             bf162* __restrict__ hi2, bf162* __restrict__ lo2, int n4) {
    int i = blockIdx.x * blockDim.x + threadIdx.x;
    if (i >= n4) return;
    float4 v = src[i];
    bf16 h0, l0, h1, l1, h2, l2, h3, l3;
    bsplit(v.x, h0, l0); bsplit(v.y, h1, l1);
    bsplit(v.z, h2, l2); bsplit(v.w, h3, l3);
    bf162 a; a.x = h0; a.y = h1;
    bf162 b; b.x = h2; b.y = h3;
    bf162 c; c.x = l0; c.y = l1;
    bf162 d; d.x = l2; d.y = l3;
    hi2[i * 2] = a; hi2[i * 2 + 1] = b;
    lo2[i * 2] = c; lo2[i * 2 + 1] = d;
}

__global__ void embed_kernel(const int* __restrict__ x, const float* __restrict__ emb,
                             const float* __restrict__ pos, float* __restrict__ out) {
    int idx = blockIdx.x * blockDim.x + threadIdx.x;
    if (idx >= ROWS * D_MODEL) return;
    int d = idx & (D_MODEL - 1), r = idx >> 10, l = r & (SEQLEN - 1);
    out[idx] = emb[x[r] * D_MODEL + d] + pos[l * D_MODEL + d];
}

__global__ void rmsnorm_kernel(const float* __restrict__ h, const float* __restrict__ w,
                               bf16* __restrict__ oh, bf16* __restrict__ ol) {
    int r = blockIdx.x, tid = threadIdx.x;
    const float* row = h + (size_t)r * D_MODEL;
    float s = 0.f;
    #pragma unroll
    for (int i = tid; i < D_MODEL; i += 256) { float v = row[i]; s += v * v; }
    __shared__ float red[8];
    #pragma unroll
    for (int o = 16; o > 0; o >>= 1) s += __shfl_down_sync(0xffffffffu, s, o);
    if ((tid & 31) == 0) red[tid >> 5] = s;
    __syncthreads();
    __shared__ float scale;
    if (tid == 0) {
        float tt = 0.f;
        #pragma unroll
        for (int i = 0; i < 8; i++) tt += red[i];
        scale = rsqrtf(tt * (1.0f / D_MODEL) + 1e-5f);
    }
    __syncthreads();
    float sc = scale;
    #pragma unroll
    for (int i = tid; i < D_MODEL; i += 256) {
        bf16 hh, ll;
        bsplit(row[i] * sc * w[i], hh, ll);
        oh[(size_t)r * D_MODEL + i] = hh;
        ol[(size_t)r * D_MODEL + i] = ll;
    }
}

__global__ void conv_silu_kernel(const float* __restrict__ xz, const float* __restrict__ cw,
                                 const float* __restrict__ cb, float* __restrict__ xc,
                                 bf16* __restrict__ xch, bf16* __restrict__ xcl) {
    int idx = blockIdx.x * blockDim.x + threadIdx.x;
    if (idx >= ROWS * D_INNER / 4) return;
    int d4 = (idx & (D_INNER / 4 - 1)) << 2;
    int r = idx >> 9, l = r & (SEQLEN - 1);
    float4 wa = *(const float4*)(cw + d4 * 4);
    float4 wb = *(const float4*)(cw + d4 * 4 + 4);
    float4 wc = *(const float4*)(cw + d4 * 4 + 8);
    float4 wd = *(const float4*)(cw + d4 * 4 + 12);
    float4 acc = *(const float4*)(cb + d4);
    const float* base = xz + (size_t)r * (2 * D_INNER) + d4;
    if (l >= 3) { float4 x = *(const float4*)(base - 3 * 2 * D_INNER);
        acc.x = fmaf(x.x, wa.x, acc.x); acc.y = fmaf(x.y, wb.x, acc.y);
        acc.z = fmaf(x.z, wc.x, acc.z); acc.w = fmaf(x.w, wd.x, acc.w); }
    if (l >= 2) { float4 x = *(const float4*)(base - 2 * 2 * D_INNER);
        acc.x = fmaf(x.x, wa.y, acc.x); acc.y = fmaf(x.y, wb.y, acc.y);
        acc.z = fmaf(x.z, wc.y, acc.z); acc.w = fmaf(x.w, wd.y, acc.w); }
    if (l >= 1) { float4 x = *(const float4*)(base - 2 * D_INNER);
        acc.x = fmaf(x.x, wa.z, acc.x); acc.y = fmaf(x.y, wb.z, acc.y);
        acc.z = fmaf(x.z, wc.z, acc.z); acc.w = fmaf(x.w, wd.z, acc.w); }
    { float4 x = *(const float4*)(base);
        acc.x = fmaf(x.x, wa.w, acc.x); acc.y = fmaf(x.y, wb.w, acc.y);
        acc.z = fmaf(x.z, wc.w, acc.z); acc.w = fmaf(x.w, wd.w, acc.w); }
    acc.x = acc.x / (1.f + __expf(-acc.x));
    acc.y = acc.y / (1.f + __expf(-acc.y));
    acc.z = acc.z / (1.f + __expf(-acc.z));
    acc.w = acc.w / (1.f + __expf(-acc.w));
    size_t o = (size_t)r * D_INNER + d4;
    *(float4*)(xc + o) = acc;
    bf16 h0, l0, h1, l1, h2, l2, h3, l3;
    bsplit(acc.x, h0, l0); bsplit(acc.y, h1, l1);
    bsplit(acc.z, h2, l2); bsplit(acc.w, h3, l3);
    bf162 ph0; ph0.x = h0; ph0.y = h1;
    bf162 ph1; ph1.x = h2; ph1.y = h3;
    bf162 pl0; pl0.x = l0; pl0.y = l1;
    bf162 pl1; pl1.x = l2; pl1.y = l3;
    *(bf162*)(xch + o) = ph0; *(bf162*)(xch + o + 2) = ph1;
    *(bf162*)(xcl + o) = pl0; *(bf162*)(xcl + o + 2) = pl1;
}

__global__ void scan_kernel(const float* __restrict__ delta, const float* __restrict__ xc,
                            const float* __restrict__ dbc, const float* __restrict__ xz,
                            const float* __restrict__ A_log, const float* __restrict__ Dp,
                            bf16* __restrict__ yh, bf16* __restrict__ yl) {
    int gwarp = (blockIdx.x * blockDim.x + threadIdx.x) >> 5;
    int lane = threadIdx.x & 31, n = lane & 15;
    int pair = gwarp * 2 + (lane >> 4);
    int b = pair >> 11, d = pair & (D_INNER - 1);
    if (b >= BATCH) return;
    float An = -__expf(A_log[d * D_STATE + n]);
    float Dv = Dp[d], h = 0.f;
    size_t rbase = (size_t)b * SEQLEN;
    for (int l = 0; l < SEQLEN; l++) {
        size_t r = rbase + l;
        float dlt = delta[r * D_INNER + d];
        float xcv = xc[r * D_INNER + d];
        float Bv = dbc[r * 96 + DT_RANK + n];
        float Cv = dbc[r * 96 + DT_RANK + D_STATE + n];
        float dA = __expf(dlt * An);
        h = fmaf(dA, h, dlt * xcv * Bv);
        float y = h * Cv;
        y += __shfl_xor_sync(0xffffffffu, y, 1);
        y += __shfl_xor_sync(0xffffffffu, y, 2);
        y += __shfl_xor_sync(0xffffffffu, y, 4);
        y += __shfl_xor_sync(0xffffffffu, y, 8);
        if (n == 0) {
            float zv = xz[r * (2 * D_INNER) + D_INNER + d];
            float sz = zv / (1.f + __expf(-zv));
            bf16 hh, ll;
            bsplit((y + Dv * xcv) * sz, hh, ll);
            yh[r * D_INNER + d] = hh;
            yl[r * D_INNER + d] = ll;
        }
    }
}

__global__ void cls_kernel(const float* __restrict__ h,
                           const float* __restrict__ w1, const float* __restrict__ b1,
                           const float* __restrict__ w2, const float* __restrict__ b2,
                           float* __restrict__ out) {
    __shared__ float sh[D_MODEL];
    __shared__ float t1[D_MODEL];
    __shared__ float red[256];
    int b = blockIdx.x, tid = threadIdx.x;
    const float* row = h + ((size_t)b * SEQLEN + (SEQLEN - 1)) * D_MODEL;
    for (int i = tid; i < D_MODEL; i += 256) sh[i] = row[i];
    __syncthreads();
    for (int e = tid; e < D_MODEL; e += 256) {
        const float* wr = w1 + (size_t)e * D_MODEL;
        float acc = b1[e];
        #pragma unroll 4
        for (int k = 0; k < D_MODEL; k += 4) {
            float4 w4 = *(const float4*)(wr + k);
            acc = fmaf(sh[k], w4.x, acc); acc = fmaf(sh[k + 1], w4.y, acc);
            acc = fmaf(sh[k + 2], w4.z, acc); acc = fmaf(sh[k + 3], w4.w, acc);
        }
        t1[e] = acc > 0.f ? acc : 0.f;
    }
    __syncthreads();
    for (int c = 0; c < NUM_CLS; c++) {
        float p = 0.f;
        for (int k = tid; k < D_MODEL; k += 256) p = fmaf(t1[k], w2[c * D_MODEL + k], p);
        red[tid] = p;
        __syncthreads();
        for (int s = 128; s > 0; s >>= 1) { if (tid < s) red[tid] += red[tid + s]; __syncthreads(); }
        if (tid == 0) out[b * NUM_CLS + c] = red[0] + b2[c];
        __syncthreads();
    }
}

// ---------------------------------------------------------------------------
// Launch
// ---------------------------------------------------------------------------
#define MMA_SMEM (NSTG * STGB)   // 98304 bytes -> 2 CTAs/SM

extern "C" void kernel_launch(void* const* d_in, const int* in_sizes, int n_in,
                              void* d_out, int out_size)
{
    const int*   x_tok      = (const int*)d_in[0];
    const float* embedding  = (const float*)d_in[1];
    const float* pos_enc    = (const float*)d_in[2];
    const float* norm_w     = (const float*)d_in[3];
    const float* in_proj_w  = (const float*)d_in[4];
    const float* conv_w     = (const float*)d_in[5];
    const float* conv_b     = (const float*)d_in[6];
    const float* x_proj_w   = (const float*)d_in[7];
    const float* dt_proj_w  = (const float*)d_in[8];
    const float* dt_proj_b  = (const float*)d_in[9];
    const float* A_log      = (const float*)d_in[10];
    const float* Dp         = (const float*)d_in[11];
    const float* out_proj_w = (const float*)d_in[12];
    const float* cls_fc1_w  = (const float*)d_in[13];
    const float* cls_fc1_b  = (const float*)d_in[14];
    const float* cls_fc2_w  = (const float*)d_in[15];
    const float* cls_fc2_b  = (const float*)d_in[16];
    const float* dec_fc1_w  = (const float*)d_in[17];
    const float* dec_fc1_b  = (const float*)d_in[18];
    const float* dec_fc2_w  = (const float*)d_in[19];
    const float* dec_fc2_b  = (const float*)d_in[20];

    float *h, *xz, *xc, *dbc, *delta;
    bf16 *xn_h, *xn_l, *xc_h, *xc_l, *dbc_h, *dbc_l, *y_h, *y_l, *hs_h, *hs_l, *t_h, *t_l;
    bf16 *win_h, *win_l, *wout_h, *wout_l, *wxp_h, *wxp_l, *wdt_h, *wdt_l, *wd1_h, *wd1_l, *wd2_h, *wd2_l;
    cudaGetSymbolAddress((void**)&h, g_h);
    cudaGetSymbolAddress((void**)&xz, g_xz);
    cudaGetSymbolAddress((void**)&xc, g_xc);
    cudaGetSymbolAddress((void**)&dbc, g_dbc);
    cudaGetSymbolAddress((void**)&delta, g_delta);
    cudaGetSymbolAddress((void**)&xn_h, g_xn_h);  cudaGetSymbolAddress((void**)&xn_l, g_xn_l);
    cudaGetSymbolAddress((void**)&xc_h, g_xc_h);  cudaGetSymbolAddress((void**)&xc_l, g_xc_l);
    cudaGetSymbolAddress((void**)&dbc_h, g_dbc_h); cudaGetSymbolAddress((void**)&dbc_l, g_dbc_l);
    cudaGetSymbolAddress((void**)&y_h, g_y_h);    cudaGetSymbolAddress((void**)&y_l, g_y_l);
    cudaGetSymbolAddress((void**)&hs_h, g_hs_h);  cudaGetSymbolAddress((void**)&hs_l, g_hs_l);
    cudaGetSymbolAddress((void**)&t_h, g_t_h);    cudaGetSymbolAddress((void**)&t_l, g_t_l);
    cudaGetSymbolAddress((void**)&win_h, g_win_h);   cudaGetSymbolAddress((void**)&win_l, g_win_l);
    cudaGetSymbolAddress((void**)&wout_h, g_wout_h); cudaGetSymbolAddress((void**)&wout_l, g_wout_l);
    cudaGetSymbolAddress((void**)&wxp_h, g_wxp_h);   cudaGetSymbolAddress((void**)&wxp_l, g_wxp_l);
    cudaGetSymbolAddress((void**)&wdt_h, g_wdt_h);   cudaGetSymbolAddress((void**)&wdt_l, g_wdt_l);
    cudaGetSymbolAddress((void**)&wd1_h, g_wd1_h);   cudaGetSymbolAddress((void**)&wd1_l, g_wd1_l);
    cudaGetSymbolAddress((void**)&wd2_h, g_wd2_h);   cudaGetSymbolAddress((void**)&wd2_l, g_wd2_l);

    cudaFuncSetAttribute(mma_gemm<0>, cudaFuncAttributeMaxDynamicSharedMemorySize, MMA_SMEM);
    cudaFuncSetAttribute(mma_gemm<1>, cudaFuncAttributeMaxDynamicSharedMemorySize, MMA_SMEM);
    cudaFuncSetAttribute(mma_gemm<2>, cudaFuncAttributeMaxDynamicSharedMemorySize, MMA_SMEM);
    cudaFuncSetAttribute(mma_gemm<3>, cudaFuncAttributeMaxDynamicSharedMemorySize, MMA_SMEM);
    cudaFuncSetAttribute(mma_gemm<4>, cudaFuncAttributeMaxDynamicSharedMemorySize, MMA_SMEM);
    cudaFuncSetAttribute(mma_gemm<5>, cudaFuncAttributeMaxDynamicSharedMemorySize, MMA_SMEM);

    float* out_dec = (float*)d_out;
    float* out_cls = (float*)d_out + ROWS * VOCAB;

    // Split weights to bf16 hi/lo (once per launch)
    int n;
    n = N_LAYERS * 2 * D_INNER * D_MODEL / 4;
    split_kernel<<<(n + 255) / 256, 256>>>((const float4*)in_proj_w, (bf162*)win_h, (bf162*)win_l, n);
    n = N_LAYERS * D_MODEL * D_INNER / 4;
    split_kernel<<<(n + 255) / 256, 256>>>((const float4*)out_proj_w, (bf162*)wout_h, (bf162*)wout_l, n);
    n = N_LAYERS * 96 * D_INNER / 4;
    split_kernel<<<(n + 255) / 256, 256>>>((const float4*)x_proj_w, (bf162*)wxp_h, (bf162*)wxp_l, n);
    n = N_LAYERS * D_INNER * DT_RANK / 4;
    split_kernel<<<(n + 255) / 256, 256>>>((const float4*)dt_proj_w, (bf162*)wdt_h, (bf162*)wdt_l, n);
    n = D_MODEL * D_MODEL / 4;
    split_kernel<<<(n + 255) / 256, 256>>>((const float4*)dec_fc1_w, (bf162*)wd1_h, (bf162*)wd1_l, n);
    n = VOCAB * D_MODEL / 4;
    split_kernel<<<(n + 255) / 256, 256>>>((const float4*)dec_fc2_w, (bf162*)wd2_h, (bf162*)wd2_l, n);

    embed_kernel<<<(ROWS * D_MODEL + 255) / 256, 256>>>(x_tok, embedding, pos_enc, h);

    for (int l = 0; l < N_LAYERS; l++) {
        const bf16* inw_h = win_h + (size_t)l * 2 * D_INNER * D_MODEL;
        const bf16* inw_l = win_l + (size_t)l * 2 * D_INNER * D_MODEL;
        const float* cw  = conv_w + (size_t)l * D_INNER * 4;
        const float* cb  = conv_b + (size_t)l * D_INNER;
        const bf16* xpw_h = wxp_h + (size_t)l * 96 * D_INNER;
        const bf16* xpw_l = wxp_l + (size_t)l * 96 * D_INNER;
        const bf16* dtw_h = wdt_h + (size_t)l * D_INNER * DT_RANK;
        const bf16* dtw_l = wdt_l + (size_t)l * D_INNER * DT_RANK;
        const float* dtb = dt_proj_b + (size_t)l * D_INNER;
        const float* al  = A_log + (size_t)l * D_INNER * D_STATE;
        const float* dp  = Dp + (size_t)l * D_INNER;
        const bf16* ow_h = wout_h + (size_t)l * D_MODEL * D_INNER;
        const bf16* ow_l = wout_l + (size_t)l * D_MODEL * D_INNER;
        const float* nw  = norm_w + (size_t)l * D_MODEL;

        rmsnorm_kernel<<<ROWS, 256>>>(h, nw, xn_h, xn_l);
        // xz = xn @ in_w^T      (4096 x 4096 x 1024)
        mma_gemm<0><<<dim3(2 * D_INNER / 128, ROWS / 128), 256, MMA_SMEM>>>(
            xn_h, xn_l, D_MODEL, inw_h, inw_l, D_MODEL,
            xz, nullptr, nullptr, 2 * D_INNER, 2 * D_INNER, D_MODEL, nullptr);
        conv_silu_kernel<<<(ROWS * D_INNER / 4 + 255) / 256, 256>>>(xz, cw, cb, xc, xc_h, xc_l);
        // dbc = xc @ xp_w^T     (4096 x 96 x 2048) -> fp32 + split
        mma_gemm<5><<<dim3(1, ROWS / 128), 256, MMA_SMEM>>>(
            xc_h, xc_l, D_INNER, xpw_h, xpw_l, D_INNER,
            dbc, dbc_h, dbc_l, 96, 96, D_INNER, nullptr);
        // delta = softplus(dbc[:, :64] @ dt_w^T + dtb)   (4096 x 2048 x 64)
        mma_gemm<3><<<dim3(D_INNER / 128, ROWS / 128), 256, MMA_SMEM>>>(
            dbc_h, dbc_l, 96, dtw_h, dtw_l, DT_RANK,
            delta, nullptr, nullptr, D_INNER, D_INNER, DT_RANK, dtb);
        scan_kernel<<<(BATCH * D_INNER / 2) / 8, 256>>>(delta, xc, dbc, xz, al, dp, y_h, y_l);
        // h += y @ out_w^T      (4096 x 1024 x 2048)
        mma_gemm<1><<<dim3(D_MODEL / 128, ROWS / 128), 256, MMA_SMEM>>>(
            y_h, y_l, D_INNER, ow_h, ow_l, D_INNER,
            h, nullptr, nullptr, D_MODEL, D_MODEL, D_INNER, nullptr);
    }

    // dec MLP: split h, fc1 (relu+bias -> split), fc2 (+bias)
    n = ROWS * D_MODEL / 4;
    split_kernel<<<(n + 255) / 256, 256>>>((const float4*)h, (bf162*)hs_h, (bf162*)hs_l, n);
    mma_gemm<2><<<dim3(D_MODEL / 128, ROWS / 128), 256, MMA_SMEM>>>(
        hs_h, hs_l, D_MODEL, wd1_h, wd1_l, D_MODEL,
        nullptr, t_h, t_l, D_MODEL, D_MODEL, D_MODEL, dec_fc1_b);
    mma_gemm<4><<<dim3(1, ROWS / 128), 256, MMA_SMEM>>>(
        t_h, t_l, D_MODEL, wd2_h, wd2_l, D_MODEL,
        out_dec, nullptr, nullptr, VOCAB, VOCAB, D_MODEL, dec_fc2_b);

    cls_kernel<<<BATCH, 256>>>(h, cls_fc1_w, cls_fc1_b, cls_fc2_w, cls_fc2_b, out_cls);
}

// round 14
// speedup vs baseline: 1.7250x; 1.0893x over previous
#include <cuda_runtime.h>
#include <cuda_fp16.h>
#include <math.h>
#include <stdint.h>

#define BATCH 4
#define SEQLEN 1024
#define VOCAB 28
#define D_MODEL 1024
#define N_LAYERS 4
#define D_INNER 2048
#define D_STATE 16
#define DT_RANK 64
#define NUM_CLS 2
#define ROWS (BATCH * SEQLEN)

typedef __half h16;
typedef __half2 h162;

// ---------------------------------------------------------------------------
// Scratch (device globals)
// ---------------------------------------------------------------------------
__device__ float g_h    [ROWS * D_MODEL];
__device__ float g_xz   [ROWS * 2 * D_INNER];
__device__ float g_xc   [ROWS * D_INNER];
__device__ float g_dbc  [ROWS * 96];
__device__ float g_delta[ROWS * D_INNER];

__device__ h16 g_xn_h[ROWS * D_MODEL],  g_xn_l[ROWS * D_MODEL];
__device__ h16 g_xc_h[ROWS * D_INNER],  g_xc_l[ROWS * D_INNER];
__device__ h16 g_dbc_h[ROWS * 96],      g_dbc_l[ROWS * 96];
__device__ h16 g_y_h [ROWS * D_INNER],  g_y_l [ROWS * D_INNER];
__device__ h16 g_hs_h[ROWS * D_MODEL],  g_hs_l[ROWS * D_MODEL];
__device__ h16 g_t_h [ROWS * D_MODEL],  g_t_l [ROWS * D_MODEL];

__device__ h16 g_win_h [N_LAYERS * 2 * D_INNER * D_MODEL], g_win_l [N_LAYERS * 2 * D_INNER * D_MODEL];
__device__ h16 g_wout_h[N_LAYERS * D_MODEL * D_INNER],     g_wout_l[N_LAYERS * D_MODEL * D_INNER];
__device__ h16 g_wxp_h [N_LAYERS * 96 * D_INNER],          g_wxp_l [N_LAYERS * 96 * D_INNER];
__device__ h16 g_wdt_h [N_LAYERS * D_INNER * DT_RANK],     g_wdt_l [N_LAYERS * D_INNER * DT_RANK];
__device__ h16 g_wd1_h [D_MODEL * D_MODEL],                g_wd1_l [D_MODEL * D_MODEL];
__device__ h16 g_wd2_h [VOCAB * D_MODEL],                  g_wd2_l [VOCAB * D_MODEL];

// ---------------------------------------------------------------------------
// Helpers
// ---------------------------------------------------------------------------
__device__ __forceinline__ uint32_t smem_u32(const void* p) {
    uint32_t a;
    asm("{ .reg .u64 t; cvta.to.shared.u64 t, %1; cvt.u32.u64 %0, t; }" : "=r"(a) : "l"(p));
    return a;
}
__device__ __forceinline__ void hsplit(float v, h16& hi, h16& lo) {
    hi = __float2half(v);
    lo = __float2half(v - __half2float(hi));
}
__device__ __forceinline__ void cp_async16(uint32_t s, const void* g) {
    asm volatile("cp.async.cg.shared.global [%0], [%1], 16;" :: "r"(s), "l"(g) : "memory");
}
__device__ __forceinline__ void mma_f16(
    float& c0, float& c1, float& c2, float& c3,
    uint32_t a0, uint32_t a1, uint32_t a2, uint32_t a3,
    uint32_t b0, uint32_t b1)
{
    asm volatile(
        "mma.sync.aligned.m16n8k16.row.col.f32.f16.f16.f32 "
        "{%0,%1,%2,%3}, {%4,%5,%6,%7}, {%8,%9}, {%0,%1,%2,%3};"
        : "+f"(c0), "+f"(c1), "+f"(c2), "+f"(c3)
        : "r"(a0), "r"(a1), "r"(a2), "r"(a3), "r"(b0), "r"(b1));
}
#define LDSM4(r0, r1, r2, r3, addr) \
    asm volatile("ldmatrix.sync.aligned.m8n8.x4.shared.b16 {%0,%1,%2,%3}, [%4];" \
        : "=r"(r0), "=r"(r1), "=r"(r2), "=r"(r3) : "r"(addr))

// ---------------------------------------------------------------------------
// Error-corrected fp16 mma GEMM: C[M,N] = A[M,K] * B[N,K]^T
// A,B given as precomputed fp16 hi/lo pairs. CTA 128x128, 256 threads,
// 8 warps (warp tile 64x32), BK=32, 3 stages (96KB -> 2 CTAs/SM), SW128
// swizzle, ldmatrix loads.
// NTERMS=3: acc += Alo*Bhi + Ahi*Blo + Ahi*Bhi  (~fp32-exact)
// NTERMS=2: acc += Alo*Bhi + Ahi*Bhi = A*Bhi    (err ~2^-12, B-side only)
// SMEM stage: A tile then B tile, each 128 rows x 128B.
//   Row r: chunks 0-3 = hi k[0..31], chunks 4-7 = lo k[0..31]; phys = c^(r&7).
// EPI: 0 C store | 1 C += | 2 relu(v+bias)->split | 3 softplus(v+bias)->C
//      4 v+bias->C | 5 v->C and split
// Requires M%128==0, K%32==0. N arbitrary (clamped loads, guarded stores).
// ---------------------------------------------------------------------------
#define NSTG 3
#define STGB 32768           // bytes per stage (A 16KB + B 16KB)

template <int EPI, int NTERMS>
__global__ void __launch_bounds__(256, 2) mma_gemm(
    const h16* __restrict__ Ahi, const h16* __restrict__ Alo, int lda,
    const h16* __restrict__ Bhi, const h16* __restrict__ Blo, int ldb,
    float* __restrict__ C, h16* __restrict__ Chi, h16* __restrict__ Clo,
    int ldc, int N, int K, const float* __restrict__ bias)
{
    extern __shared__ char smc[];
    const uint32_t smb = smem_u32(smc);

    const int tid = threadIdx.x;
    const int wid = tid >> 5, lane = tid & 31;
    const int g = lane >> 2, t = lane & 3;
    const int warp_m = (wid & 1) * 64;
    const int warp_n = (wid >> 1) * 32;
    const int bm = blockIdx.y * 128, bn = blockIdx.x * 128;
    const int niter = K >> 5;

    float acc[4][4][4];
    #pragma unroll
    for (int i = 0; i < 4; i++)
        #pragma unroll
        for (int j = 0; j < 4; j++)
            #pragma unroll
            for (int c = 0; c < 4; c++) acc[i][j][c] = 0.f;

    auto loadStage = [&](int it) {
        int s = it % NSTG;
        uint32_t sb = smb + (uint32_t)s * STGB;
        int k0 = it << 5;
        #pragma unroll
        for (int i = 0; i < 8; i++) {
            int cid = (i << 8) + tid;        // 0..2047
            int tile = cid >> 10;            // 0=A, 1=B
            int rc = cid & 1023;
            int r = rc >> 3, c = rc & 7;
            if (NTERMS == 2 && tile == 1 && c >= 4) continue;   // Blo unused
            int ko = k0 + ((c & 3) << 3);
            const h16* gp;
            if (tile == 0) {
                gp = ((c < 4) ? Ahi : Alo) + (size_t)(bm + r) * lda + ko;
            } else {
                int gn = bn + r; if (gn >= N) gn = N - 1;
                gp = ((c < 4) ? Bhi : Blo) + (size_t)gn * ldb + ko;
            }
            uint32_t sa = sb + ((uint32_t)tile << 14)
                        + (uint32_t)(r * 128 + ((c ^ (r & 7)) << 4));
            cp_async16(sa, gp);
        }
        asm volatile("cp.async.commit_group;" ::: "memory");
    };

    int npro = niter < (NSTG - 1) ? niter : (NSTG - 1);
    for (int p = 0; p < npro; p++) loadStage(p);

    // ldmatrix lane addressing (row bases are multiples of 8 -> xor mask = lane&7)
    const uint32_t aRow = (uint32_t)(warp_m + (lane & 15)) * 128;
    const uint32_t bRow = (uint32_t)(warp_n + ((lane >> 4) << 3) + (lane & 7)) * 128;
    const uint32_t aCs = (uint32_t)(lane >> 4);
    const uint32_t bCs = (uint32_t)((lane >> 3) & 1);
    const uint32_t xm = (uint32_t)(lane & 7);

    for (int it = 0; it < niter; it++) {
        int allow = niter - it - 1;
        if (allow > NSTG - 2) allow = NSTG - 2;
        if (allow == 0)      asm volatile("cp.async.wait_group 0;" ::: "memory");
        else                 asm volatile("cp.async.wait_group 1;" ::: "memory");
        __syncthreads();

        if (it + NSTG - 1 < niter) loadStage(it + NSTG - 1);

        uint32_t sA = smb + (uint32_t)(it % NSTG) * STGB;
        uint32_t sB = sA + 16384;

        #pragma unroll
        for (int ch = 0; ch < 2; ch++) {       // two k16 chunks per BK=32
            uint32_t ah[4][4], al[4][4], bh[4][2], bl[4][2];
            uint32_t ca = (uint32_t)(ch << 1) + aCs;
            uint32_t cb = (uint32_t)(ch << 1) + bCs;
            #pragma unroll
            for (int mt = 0; mt < 4; mt++) {
                uint32_t base = sA + aRow + (uint32_t)(mt * 2048);
                LDSM4(ah[mt][0], ah[mt][1], ah[mt][2], ah[mt][3],
                      base + ((ca ^ xm) << 4));
                LDSM4(al[mt][0], al[mt][1], al[mt][2], al[mt][3],
                      base + (((ca + 4) ^ xm) << 4));
            }
            #pragma unroll
            for (int ntp = 0; ntp < 2; ntp++) {
                uint32_t base = sB + bRow + (uint32_t)(ntp * 2048);
                LDSM4(bh[2 * ntp][0], bh[2 * ntp][1],
                      bh[2 * ntp + 1][0], bh[2 * ntp + 1][1],
                      base + ((cb ^ xm) << 4));
                if (NTERMS == 3) {
                    LDSM4(bl[2 * ntp][0], bl[2 * ntp][1],
                          bl[2 * ntp + 1][0], bl[2 * ntp + 1][1],
                          base + (((cb + 4) ^ xm) << 4));
                }
            }
            #pragma unroll
            for (int mt = 0; mt < 4; mt++)
                #pragma unroll
                for (int nt = 0; nt < 4; nt++) {
                    mma_f16(acc[mt][nt][0], acc[mt][nt][1],
                            acc[mt][nt][2], acc[mt][nt][3],
                            al[mt][0], al[mt][1], al[mt][2], al[mt][3],
                            bh[nt][0], bh[nt][1]);
                    if (NTERMS == 3) {
                        mma_f16(acc[mt][nt][0], acc[mt][nt][1],
                                acc[mt][nt][2], acc[mt][nt][3],
                                ah[mt][0], ah[mt][1], ah[mt][2], ah[mt][3],
                                bl[nt][0], bl[nt][1]);
                    }
                    mma_f16(acc[mt][nt][0], acc[mt][nt][1],
                            acc[mt][nt][2], acc[mt][nt][3],
                            ah[mt][0], ah[mt][1], ah[mt][2], ah[mt][3],
                            bh[nt][0], bh[nt][1]);
                }
        }
    }

    // Epilogue: c0=C[g][2t], c1=C[g][2t+1], c2=C[g+8][2t], c3=C[g+8][2t+1]
    #pragma unroll
    for (int mt = 0; mt < 4; mt++) {
        #pragma unroll
        for (int nt = 0; nt < 4; nt++) {
            int col = bn + warp_n + (nt << 3) + (t << 1);
            if (col >= N) continue;
            #pragma unroll
            for (int half = 0; half < 2; half++) {
                int row = bm + warp_m + (mt << 4) + g + half * 8;
                float v0 = acc[mt][nt][half * 2];
                float v1 = acc[mt][nt][half * 2 + 1];
                size_t idx = (size_t)row * ldc + col;
                if (EPI == 0) {
                    C[idx] = v0; C[idx + 1] = v1;
                } else if (EPI == 1) {
                    C[idx] += v0; C[idx + 1] += v1;
                } else if (EPI == 2) {
                    v0 = fmaxf(v0 + bias[col], 0.f);
                    v1 = fmaxf(v1 + bias[col + 1], 0.f);
                    h16 h0, l0, h1, l1;
                    hsplit(v0, h0, l0); hsplit(v1, h1, l1);
                    Chi[idx] = h0; Chi[idx + 1] = h1;
                    Clo[idx] = l0; Clo[idx + 1] = l1;
                } else if (EPI == 3) {
                    v0 += bias[col]; v1 += bias[col + 1];
                    v0 = (v0 > 20.f) ? v0 : log1pf(__expf(v0));
                    v1 = (v1 > 20.f) ? v1 : log1pf(__expf(v1));
                    C[idx] = v0; C[idx + 1] = v1;
                } else if (EPI == 4) {
                    C[idx] = v0 + bias[col]; C[idx + 1] = v1 + bias[col + 1];
                } else {
                    C[idx] = v0; C[idx + 1] = v1;
                    h16 h0, l0, h1, l1;
                    hsplit(v0, h0, l0); hsplit(v1, h1, l1);
                    Chi[idx] = h0; Chi[idx + 1] = h1;
                    Clo[idx] = l0; Clo[idx + 1] = l1;
                }
            }
        }
    }
}

// ---------------------------------------------------------------------------
// Elementwise / small kernels
// ---------------------------------------------------------------------------
__global__ void split_kernel(const float4* __restrict__ src,
                             h162* __restrict__ hi2, h162* __restrict__ lo2, int n4) {
    int i = blockIdx.x * blockDim.x + threadIdx.x;
    if (i >= n4) return;
    float4 v = src[i];
    h16 h0, l0, h1, l1, h2, l2, h3, l3;
    hsplit(v.x, h0, l0); hsplit(v.y, h1, l1);
    hsplit(v.z, h2, l2); hsplit(v.w, h3, l3);
    h162 a; a.x = h0; a.y = h1;
    h162 b; b.x = h2; b.y = h3;
    h162 c; c.x = l0; c.y = l1;
    h162 d; d.x = l2; d.y = l3;
    hi2[i * 2] = a; hi2[i * 2 + 1] = b;
    lo2[i * 2] = c; lo2[i * 2 + 1] = d;
}

__global__ void embed_kernel(const int* __restrict__ x, const float* __restrict__ emb,
                             const float* __restrict__ pos, float* __restrict__ out) {
    int idx = blockIdx.x * blockDim.x + threadIdx.x;
    if (idx >= ROWS * D_MODEL) return;
    int d = idx & (D_MODEL - 1), r = idx >> 10, l = r & (SEQLEN - 1);
    out[idx] = emb[x[r] * D_MODEL + d] + pos[l * D_MODEL + d];
}

__global__ void rmsnorm_kernel(const float* __restrict__ h, const float* __restrict__ w,
                               h16* __restrict__ oh, h16* __restrict__ ol) {
    int r = blockIdx.x, tid = threadIdx.x;
    const float* row = h + (size_t)r * D_MODEL;
    float s = 0.f;
    #pragma unroll
    for (int i = tid; i < D_MODEL; i += 256) { float v = row[i]; s += v * v; }
    __shared__ float red[8];
    #pragma unroll
    for (int o = 16; o > 0; o >>= 1) s += __shfl_down_sync(0xffffffffu, s, o);
    if ((tid & 31) == 0) red[tid >> 5] = s;
    __syncthreads();
    __shared__ float scale;
    if (tid == 0) {
        float tt = 0.f;
        #pragma unroll
        for (int i = 0; i < 8; i++) tt += red[i];
        scale = rsqrtf(tt * (1.0f / D_MODEL) + 1e-5f);
    }
    __syncthreads();
    float sc = scale;
    #pragma unroll
    for (int i = tid; i < D_MODEL; i += 256) {
        h16 hh, ll;
        hsplit(row[i] * sc * w[i], hh, ll);
        oh[(size_t)r * D_MODEL + i] = hh;
        ol[(size_t)r * D_MODEL + i] = ll;
    }
}

__global__ void conv_silu_kernel(const float* __restrict__ xz, const float* __restrict__ cw,
                                 const float* __restrict__ cb, float* __restrict__ xc,
                                 h16* __restrict__ xch, h16* __restrict__ xcl) {
    int idx = blockIdx.x * blockDim.x + threadIdx.x;
    if (idx >= ROWS * D_INNER / 4) return;
    int d4 = (idx & (D_INNER / 4 - 1)) << 2;
    int r = idx >> 9, l = r & (SEQLEN - 1);
    float4 wa = *(const float4*)(cw + d4 * 4);
    float4 wb = *(const float4*)(cw + d4 * 4 + 4);
    float4 wc = *(const float4*)(cw + d4 * 4 + 8);
    float4 wd = *(const float4*)(cw + d4 * 4 + 12);
    float4 acc = *(const float4*)(cb + d4);
    const float* base = xz + (size_t)r * (2 * D_INNER) + d4;
    if (l >= 3) { float4 x = *(const float4*)(base - 3 * 2 * D_INNER);
        acc.x = fmaf(x.x, wa.x, acc.x); acc.y = fmaf(x.y, wb.x, acc.y);
        acc.z = fmaf(x.z, wc.x, acc.z); acc.w = fmaf(x.w, wd.x, acc.w); }
    if (l >= 2) { float4 x = *(const float4*)(base - 2 * 2 * D_INNER);
        acc.x = fmaf(x.x, wa.y, acc.x); acc.y = fmaf(x.y, wb.y, acc.y);
        acc.z = fmaf(x.z, wc.y, acc.z); acc.w = fmaf(x.w, wd.y, acc.w); }
    if (l >= 1) { float4 x = *(const float4*)(base - 2 * D_INNER);
        acc.x = fmaf(x.x, wa.z, acc.x); acc.y = fmaf(x.y, wb.z, acc.y);
        acc.z = fmaf(x.z, wc.z, acc.z); acc.w = fmaf(x.w, wd.z, acc.w); }
    { float4 x = *(const float4*)(base);
        acc.x = fmaf(x.x, wa.w, acc.x); acc.y = fmaf(x.y, wb.w, acc.y);
        acc.z = fmaf(x.z, wc.w, acc.z); acc.w = fmaf(x.w, wd.w, acc.w); }
    acc.x = acc.x / (1.f + __expf(-acc.x));
    acc.y = acc.y / (1.f + __expf(-acc.y));
    acc.z = acc.z / (1.f + __expf(-acc.z));
    acc.w = acc.w / (1.f + __expf(-acc.w));
    size_t o = (size_t)r * D_INNER + d4;
    *(float4*)(xc + o) = acc;
    h16 h0, l0, h1, l1, h2, l2, h3, l3;
    hsplit(acc.x, h0, l0); hsplit(acc.y, h1, l1);
    hsplit(acc.z, h2, l2); hsplit(acc.w, h3, l3);
    h162 ph0; ph0.x = h0; ph0.y = h1;
    h162 ph1; ph1.x = h2; ph1.y = h3;
    h162 pl0; pl0.x = l0; pl0.y = l1;
    h162 pl1; pl1.x = l2; pl1.y = l3;
    *(h162*)(xch + o) = ph0; *(h162*)(xch + o + 2) = ph1;
    *(h162*)(xcl + o) = pl0; *(h162*)(xcl + o + 2) = pl1;
}

__global__ void scan_kernel(const float* __restrict__ delta, const float* __restrict__ xc,
                            const float* __restrict__ dbc, const float* __restrict__ xz,
                            const float* __restrict__ A_log, const float* __restrict__ Dp,
                            h16* __restrict__ yh, h16* __restrict__ yl) {
    int gwarp = (blockIdx.x * blockDim.x + threadIdx.x) >> 5;
    int lane = threadIdx.x & 31, n = lane & 15;
    int pair = gwarp * 2 + (lane >> 4);
    int b = pair >> 11, d = pair & (D_INNER - 1);
    if (b >= BATCH) return;
    float An = -__expf(A_log[d * D_STATE + n]);
    float Dv = Dp[d], h = 0.f;
    size_t rbase = (size_t)b * SEQLEN;
    for (int l = 0; l < SEQLEN; l++) {
        size_t r = rbase + l;
        float dlt = delta[r * D_INNER + d];
        float xcv = xc[r * D_INNER + d];
        float Bv = dbc[r * 96 + DT_RANK + n];
        float Cv = dbc[r * 96 + DT_RANK + D_STATE + n];
        float dA = __expf(dlt * An);
        h = fmaf(dA, h, dlt * xcv * Bv);
        float y = h * Cv;
        y += __shfl_xor_sync(0xffffffffu, y, 1);
        y += __shfl_xor_sync(0xffffffffu, y, 2);
        y += __shfl_xor_sync(0xffffffffu, y, 4);
        y += __shfl_xor_sync(0xffffffffu, y, 8);
        if (n == 0) {
            float zv = xz[r * (2 * D_INNER) + D_INNER + d];
            float sz = zv / (1.f + __expf(-zv));
            h16 hh, ll;
            hsplit((y + Dv * xcv) * sz, hh, ll);
            yh[r * D_INNER + d] = hh;
            yl[r * D_INNER + d] = ll;
        }
    }
}

__global__ void cls_kernel(const float* __restrict__ h,
                           const float* __restrict__ w1, const float* __restrict__ b1,
                           const float* __restrict__ w2, const float* __restrict__ b2,
                           float* __restrict__ out) {
    __shared__ float sh[D_MODEL];
    __shared__ float t1[D_MODEL];
    __shared__ float red[256];
    int b = blockIdx.x, tid = threadIdx.x;
    const float* row = h + ((size_t)b * SEQLEN + (SEQLEN - 1)) * D_MODEL;
    for (int i = tid; i < D_MODEL; i += 256) sh[i] = row[i];
    __syncthreads();
    for (int e = tid; e < D_MODEL; e += 256) {
        const float* wr = w1 + (size_t)e * D_MODEL;
        float acc = b1[e];
        #pragma unroll 4
        for (int k = 0; k < D_MODEL; k += 4) {
            float4 w4 = *(const float4*)(wr + k);
            acc = fmaf(sh[k], w4.x, acc); acc = fmaf(sh[k + 1], w4.y, acc);
            acc = fmaf(sh[k + 2], w4.z, acc); acc = fmaf(sh[k + 3], w4.w, acc);
        }
        t1[e] = acc > 0.f ? acc : 0.f;
    }
    __syncthreads();
    for (int c = 0; c < NUM_CLS; c++) {
        float p = 0.f;
        for (int k = tid; k < D_MODEL; k += 256) p = fmaf(t1[k], w2[c * D_MODEL + k], p);
        red[tid] = p;
        __syncthreads();
        for (int s = 128; s > 0; s >>= 1) { if (tid < s) red[tid] += red[tid + s]; __syncthreads(); }
        if (tid == 0) out[b * NUM_CLS + c] = red[0] + b2[c];
        __syncthreads();
    }
}

// ---------------------------------------------------------------------------
// Launch
// ---------------------------------------------------------------------------
#define MMA_SMEM (NSTG * STGB)   // 98304 bytes -> 2 CTAs/SM

extern "C" void kernel_launch(void* const* d_in, const int* in_sizes, int n_in,
                              void* d_out, int out_size)
{
    const int*   x_tok      = (const int*)d_in[0];
    const float* embedding  = (const float*)d_in[1];
    const float* pos_enc    = (const float*)d_in[2];
    const float* norm_w     = (const float*)d_in[3];
    const float* in_proj_w  = (const float*)d_in[4];
    const float* conv_w     = (const float*)d_in[5];
    const float* conv_b     = (const float*)d_in[6];
    const float* x_proj_w   = (const float*)d_in[7];
    const float* dt_proj_w  = (const float*)d_in[8];
    const float* dt_proj_b  = (const float*)d_in[9];
    const float* A_log      = (const float*)d_in[10];
    const float* Dp         = (const float*)d_in[11];
    const float* out_proj_w = (const float*)d_in[12];
    const float* cls_fc1_w  = (const float*)d_in[13];
    const float* cls_fc1_b  = (const float*)d_in[14];
    const float* cls_fc2_w  = (const float*)d_in[15];
    const float* cls_fc2_b  = (const float*)d_in[16];
    const float* dec_fc1_w  = (const float*)d_in[17];
    const float* dec_fc1_b  = (const float*)d_in[18];
    const float* dec_fc2_w  = (const float*)d_in[19];
    const float* dec_fc2_b  = (const float*)d_in[20];

    float *h, *xz, *xc, *dbc, *delta;
    h16 *xn_h, *xn_l, *xc_h, *xc_l, *dbc_h, *dbc_l, *y_h, *y_l, *hs_h, *hs_l, *t_h, *t_l;
    h16 *win_h, *win_l, *wout_h, *wout_l, *wxp_h, *wxp_l, *wdt_h, *wdt_l, *wd1_h, *wd1_l, *wd2_h, *wd2_l;
    cudaGetSymbolAddress((void**)&h, g_h);
    cudaGetSymbolAddress((void**)&xz, g_xz);
    cudaGetSymbolAddress((void**)&xc, g_xc);
    cudaGetSymbolAddress((void**)&dbc, g_dbc);
    cudaGetSymbolAddress((void**)&delta, g_delta);
    cudaGetSymbolAddress((void**)&xn_h, g_xn_h);  cudaGetSymbolAddress((void**)&xn_l, g_xn_l);
    cudaGetSymbolAddress((void**)&xc_h, g_xc_h);  cudaGetSymbolAddress((void**)&xc_l, g_xc_l);
    cudaGetSymbolAddress((void**)&dbc_h, g_dbc_h); cudaGetSymbolAddress((void**)&dbc_l, g_dbc_l);
    cudaGetSymbolAddress((void**)&y_h, g_y_h);    cudaGetSymbolAddress((void**)&y_l, g_y_l);
    cudaGetSymbolAddress((void**)&hs_h, g_hs_h);  cudaGetSymbolAddress((void**)&hs_l, g_hs_l);
    cudaGetSymbolAddress((void**)&t_h, g_t_h);    cudaGetSymbolAddress((void**)&t_l, g_t_l);
    cudaGetSymbolAddress((void**)&win_h, g_win_h);   cudaGetSymbolAddress((void**)&win_l, g_win_l);
    cudaGetSymbolAddress((void**)&wout_h, g_wout_h); cudaGetSymbolAddress((void**)&wout_l, g_wout_l);
    cudaGetSymbolAddress((void**)&wxp_h, g_wxp_h);   cudaGetSymbolAddress((void**)&wxp_l, g_wxp_l);
    cudaGetSymbolAddress((void**)&wdt_h, g_wdt_h);   cudaGetSymbolAddress((void**)&wdt_l, g_wdt_l);
    cudaGetSymbolAddress((void**)&wd1_h, g_wd1_h);   cudaGetSymbolAddress((void**)&wd1_l, g_wd1_l);
    cudaGetSymbolAddress((void**)&wd2_h, g_wd2_h);   cudaGetSymbolAddress((void**)&wd2_l, g_wd2_l);

    cudaFuncSetAttribute(mma_gemm<0, 2>, cudaFuncAttributeMaxDynamicSharedMemorySize, MMA_SMEM);
    cudaFuncSetAttribute(mma_gemm<1, 2>, cudaFuncAttributeMaxDynamicSharedMemorySize, MMA_SMEM);
    cudaFuncSetAttribute(mma_gemm<2, 2>, cudaFuncAttributeMaxDynamicSharedMemorySize, MMA_SMEM);
    cudaFuncSetAttribute(mma_gemm<5, 3>, cudaFuncAttributeMaxDynamicSharedMemorySize, MMA_SMEM);
    cudaFuncSetAttribute(mma_gemm<3, 3>, cudaFuncAttributeMaxDynamicSharedMemorySize, MMA_SMEM);
    cudaFuncSetAttribute(mma_gemm<4, 3>, cudaFuncAttributeMaxDynamicSharedMemorySize, MMA_SMEM);

    float* out_dec = (float*)d_out;
    float* out_cls = (float*)d_out + ROWS * VOCAB;

    // Split weights to fp16 hi/lo (once per launch)
    int n;
    n = N_LAYERS * 2 * D_INNER * D_MODEL / 4;
    split_kernel<<<(n + 255) / 256, 256>>>((const float4*)in_proj_w, (h162*)win_h, (h162*)win_l, n);
    n = N_LAYERS * D_MODEL * D_INNER / 4;
    split_kernel<<<(n + 255) / 256, 256>>>((const float4*)out_proj_w, (h162*)wout_h, (h162*)wout_l, n);
    n = N_LAYERS * 96 * D_INNER / 4;
    split_kernel<<<(n + 255) / 256, 256>>>((const float4*)x_proj_w, (h162*)wxp_h, (h162*)wxp_l, n);
    n = N_LAYERS * D_INNER * DT_RANK / 4;
    split_kernel<<<(n + 255) / 256, 256>>>((const float4*)dt_proj_w, (h162*)wdt_h, (h162*)wdt_l, n);
    n = D_MODEL * D_MODEL / 4;
    split_kernel<<<(n + 255) / 256, 256>>>((const float4*)dec_fc1_w, (h162*)wd1_h, (h162*)wd1_l, n);
    n = VOCAB * D_MODEL / 4;
    split_kernel<<<(n + 255) / 256, 256>>>((const float4*)dec_fc2_w, (h162*)wd2_h, (h162*)wd2_l, n);

    embed_kernel<<<(ROWS * D_MODEL + 255) / 256, 256>>>(x_tok, embedding, pos_enc, h);

    for (int l = 0; l < N_LAYERS; l++) {
        const h16* inw_h = win_h + (size_t)l * 2 * D_INNER * D_MODEL;
        const h16* inw_l = win_l + (size_t)l * 2 * D_INNER * D_MODEL;
        const float* cw  = conv_w + (size_t)l * D_INNER * 4;
        const float* cb  = conv_b + (size_t)l * D_INNER;
        const h16* xpw_h = wxp_h + (size_t)l * 96 * D_INNER;
        const h16* xpw_l = wxp_l + (size_t)l * 96 * D_INNER;
        const h16* dtw_h = wdt_h + (size_t)l * D_INNER * DT_RANK;
        const h16* dtw_l = wdt_l + (size_t)l * D_INNER * DT_RANK;
        const float* dtb = dt_proj_b + (size_t)l * D_INNER;
        const float* al  = A_log + (size_t)l * D_INNER * D_STATE;
        const float* dp  = Dp + (size_t)l * D_INNER;
        const h16* ow_h = wout_h + (size_t)l * D_MODEL * D_INNER;
        const h16* ow_l = wout_l + (size_t)l * D_MODEL * D_INNER;
        const float* nw  = norm_w + (size_t)l * D_MODEL;

        rmsnorm_kernel<<<ROWS, 256>>>(h, nw, xn_h, xn_l);
        // xz = xn @ in_w^T      (4096 x 4096 x 1024)  2-term
        mma_gemm<0, 2><<<dim3(2 * D_INNER / 128, ROWS / 128), 256, MMA_SMEM>>>(
            xn_h, xn_l, D_MODEL, inw_h, inw_l, D_MODEL,
            xz, nullptr, nullptr, 2 * D_INNER, 2 * D_INNER, D_MODEL, nullptr);
        conv_silu_kernel<<<(ROWS * D_INNER / 4 + 255) / 256, 256>>>(xz, cw, cb, xc, xc_h, xc_l);
        // dbc = xc @ xp_w^T     (4096 x 96 x 2048) -> fp32 + split  3-term
        mma_gemm<5, 3><<<dim3(1, ROWS / 128), 256, MMA_SMEM>>>(
            xc_h, xc_l, D_INNER, xpw_h, xpw_l, D_INNER,
            dbc, dbc_h, dbc_l, 96, 96, D_INNER, nullptr);
        // delta = softplus(dbc[:, :64] @ dt_w^T + dtb)   (4096 x 2048 x 64)  3-term
        mma_gemm<3, 3><<<dim3(D_INNER / 128, ROWS / 128), 256, MMA_SMEM>>>(
            dbc_h, dbc_l, 96, dtw_h, dtw_l, DT_RANK,
            delta, nullptr, nullptr, D_INNER, D_INNER, DT_RANK, dtb);
        scan_kernel<<<(BATCH * D_INNER / 2) / 8, 256>>>(delta, xc, dbc, xz, al, dp, y_h, y_l);
        // h += y @ out_w^T      (4096 x 1024 x 2048)  2-term
        mma_gemm<1, 2><<<dim3(D_MODEL / 128, ROWS / 128), 256, MMA_SMEM>>>(
            y_h, y_l, D_INNER, ow_h, ow_l, D_INNER,
            h, nullptr, nullptr, D_MODEL, D_MODEL, D_INNER, nullptr);
    }

    // dec MLP: split h, fc1 (relu+bias -> split, 2-term), fc2 (+bias, 3-term)
    n = ROWS * D_MODEL / 4;
    split_kernel<<<(n + 255) / 256, 256>>>((const float4*)h, (h162*)hs_h, (h162*)hs_l, n);
    mma_gemm<2, 2><<<dim3(D_MODEL / 128, ROWS / 128), 256, MMA_SMEM>>>(
        hs_h, hs_l, D_MODEL, wd1_h, wd1_l, D_MODEL,
        nullptr, t_h, t_l, D_MODEL, D_MODEL, D_MODEL, dec_fc1_b);
    mma_gemm<4, 3><<<dim3(1, ROWS / 128), 256, MMA_SMEM>>>(
        t_h, t_l, D_MODEL, wd2_h, wd2_l, D_MODEL,
        out_dec, nullptr, nullptr, VOCAB, VOCAB, D_MODEL, dec_fc2_b);

    cls_kernel<<<BATCH, 256>>>(h, cls_fc1_w, cls_fc1_b, cls_fc2_w, cls_fc2_b, out_cls);
}

// round 16
// speedup vs baseline: 2.2047x; 1.2781x over previous
#include <cuda_runtime.h>
#include <cuda_fp16.h>
#include <math.h>
#include <stdint.h>

#define BATCH 4
#define SEQLEN 1024
#define VOCAB 28
#define D_MODEL 1024
#define N_LAYERS 4
#define D_INNER 2048
#define D_STATE 16
#define DT_RANK 64
#define NUM_CLS 2
#define ROWS (BATCH * SEQLEN)

typedef __half h16;
typedef __half2 h162;

// ---------------------------------------------------------------------------
// Scratch (device globals)
// ---------------------------------------------------------------------------
__device__ float g_h    [ROWS * D_MODEL];
__device__ float g_xz   [ROWS * 2 * D_INNER];
__device__ float g_xc   [ROWS * D_INNER];
__device__ float g_dbc  [ROWS * 96];
__device__ float g_delta[ROWS * D_INNER];

__device__ h16 g_xn_h[ROWS * D_MODEL],  g_xn_l[ROWS * D_MODEL];
__device__ h16 g_xc_h[ROWS * D_INNER],  g_xc_l[ROWS * D_INNER];
__device__ h16 g_dbc_h[ROWS * 96],      g_dbc_l[ROWS * 96];
__device__ h16 g_y_h [ROWS * D_INNER],  g_y_l [ROWS * D_INNER];
__device__ h16 g_hs_h[ROWS * D_MODEL],  g_hs_l[ROWS * D_MODEL];
__device__ h16 g_t_h [ROWS * D_MODEL],  g_t_l [ROWS * D_MODEL];

__device__ h16 g_win_h [N_LAYERS * 2 * D_INNER * D_MODEL], g_win_l [N_LAYERS * 2 * D_INNER * D_MODEL];
__device__ h16 g_wout_h[N_LAYERS * D_MODEL * D_INNER],     g_wout_l[N_LAYERS * D_MODEL * D_INNER];
__device__ h16 g_wxp_h [N_LAYERS * 96 * D_INNER],          g_wxp_l [N_LAYERS * 96 * D_INNER];
__device__ h16 g_wdt_h [N_LAYERS * D_INNER * DT_RANK],     g_wdt_l [N_LAYERS * D_INNER * DT_RANK];
__device__ h16 g_wd1_h [D_MODEL * D_MODEL],                g_wd1_l [D_MODEL * D_MODEL];
__device__ h16 g_wd2_h [VOCAB * D_MODEL],                  g_wd2_l [VOCAB * D_MODEL];

// ---------------------------------------------------------------------------
// Helpers
// ---------------------------------------------------------------------------
__device__ __forceinline__ uint32_t smem_u32(const void* p) {
    uint32_t a;
    asm("{ .reg .u64 t; cvta.to.shared.u64 t, %1; cvt.u32.u64 %0, t; }" : "=r"(a) : "l"(p));
    return a;
}
__device__ __forceinline__ void hsplit(float v, h16& hi, h16& lo) {
    hi = __float2half(v);
    lo = __float2half(v - __half2float(hi));
}
__device__ __forceinline__ void cp_async16(uint32_t s, const void* g) {
    asm volatile("cp.async.cg.shared.global [%0], [%1], 16;" :: "r"(s), "l"(g) : "memory");
}
__device__ __forceinline__ void mma_f16(
    float& c0, float& c1, float& c2, float& c3,
    uint32_t a0, uint32_t a1, uint32_t a2, uint32_t a3,
    uint32_t b0, uint32_t b1)
{
    asm volatile(
        "mma.sync.aligned.m16n8k16.row.col.f32.f16.f16.f32 "
        "{%0,%1,%2,%3}, {%4,%5,%6,%7}, {%8,%9}, {%0,%1,%2,%3};"
        : "+f"(c0), "+f"(c1), "+f"(c2), "+f"(c3)
        : "r"(a0), "r"(a1), "r"(a2), "r"(a3), "r"(b0), "r"(b1));
}
#define LDSM4(r0, r1, r2, r3, addr) \
    asm volatile("ldmatrix.sync.aligned.m8n8.x4.shared.b16 {%0,%1,%2,%3}, [%4];" \
        : "=r"(r0), "=r"(r1), "=r"(r2), "=r"(r3) : "r"(addr))

// ---------------------------------------------------------------------------
// Error-corrected fp16 mma GEMM (unchanged from R14; proven 7.67e-4)
// ---------------------------------------------------------------------------
#define NSTG 3
#define STGB 32768

template <int EPI, int NTERMS>
__global__ void __launch_bounds__(256, 2) mma_gemm(
    const h16* __restrict__ Ahi, const h16* __restrict__ Alo, int lda,
    const h16* __restrict__ Bhi, const h16* __restrict__ Blo, int ldb,
    float* __restrict__ C, h16* __restrict__ Chi, h16* __restrict__ Clo,
    int ldc, int N, int K, const float* __restrict__ bias)
{
    extern __shared__ char smc[];
    const uint32_t smb = smem_u32(smc);

    const int tid = threadIdx.x;
    const int wid = tid >> 5, lane = tid & 31;
    const int g = lane >> 2, t = lane & 3;
    const int warp_m = (wid & 1) * 64;
    const int warp_n = (wid >> 1) * 32;
    const int bm = blockIdx.y * 128, bn = blockIdx.x * 128;
    const int niter = K >> 5;

    float acc[4][4][4];
    #pragma unroll
    for (int i = 0; i < 4; i++)
        #pragma unroll
        for (int j = 0; j < 4; j++)
            #pragma unroll
            for (int c = 0; c < 4; c++) acc[i][j][c] = 0.f;

    auto loadStage = [&](int it) {
        int s = it % NSTG;
        uint32_t sb = smb + (uint32_t)s * STGB;
        int k0 = it << 5;
        #pragma unroll
        for (int i = 0; i < 8; i++) {
            int cid = (i << 8) + tid;
            int tile = cid >> 10;
            int rc = cid & 1023;
            int r = rc >> 3, c = rc & 7;
            if (NTERMS == 2 && tile == 1 && c >= 4) continue;
            int ko = k0 + ((c & 3) << 3);
            const h16* gp;
            if (tile == 0) {
                gp = ((c < 4) ? Ahi : Alo) + (size_t)(bm + r) * lda + ko;
            } else {
                int gn = bn + r; if (gn >= N) gn = N - 1;
                gp = ((c < 4) ? Bhi : Blo) + (size_t)gn * ldb + ko;
            }
            uint32_t sa = sb + ((uint32_t)tile << 14)
                        + (uint32_t)(r * 128 + ((c ^ (r & 7)) << 4));
            cp_async16(sa, gp);
        }
        asm volatile("cp.async.commit_group;" ::: "memory");
    };

    int npro = niter < (NSTG - 1) ? niter : (NSTG - 1);
    for (int p = 0; p < npro; p++) loadStage(p);

    const uint32_t aRow = (uint32_t)(warp_m + (lane & 15)) * 128;
    const uint32_t bRow = (uint32_t)(warp_n + ((lane >> 4) << 3) + (lane & 7)) * 128;
    const uint32_t aCs = (uint32_t)(lane >> 4);
    const uint32_t bCs = (uint32_t)((lane >> 3) & 1);
    const uint32_t xm = (uint32_t)(lane & 7);

    for (int it = 0; it < niter; it++) {
        int allow = niter - it - 1;
        if (allow > NSTG - 2) allow = NSTG - 2;
        if (allow == 0)      asm volatile("cp.async.wait_group 0;" ::: "memory");
        else                 asm volatile("cp.async.wait_group 1;" ::: "memory");
        __syncthreads();

        if (it + NSTG - 1 < niter) loadStage(it + NSTG - 1);

        uint32_t sA = smb + (uint32_t)(it % NSTG) * STGB;
        uint32_t sB = sA + 16384;

        #pragma unroll
        for (int ch = 0; ch < 2; ch++) {
            uint32_t ah[4][4], al[4][4], bh[4][2], bl[4][2];
            uint32_t ca = (uint32_t)(ch << 1) + aCs;
            uint32_t cb = (uint32_t)(ch << 1) + bCs;
            #pragma unroll
            for (int mt = 0; mt < 4; mt++) {
                uint32_t base = sA + aRow + (uint32_t)(mt * 2048);
                LDSM4(ah[mt][0], ah[mt][1], ah[mt][2], ah[mt][3],
                      base + ((ca ^ xm) << 4));
                LDSM4(al[mt][0], al[mt][1], al[mt][2], al[mt][3],
                      base + (((ca + 4) ^ xm) << 4));
            }
            #pragma unroll
            for (int ntp = 0; ntp < 2; ntp++) {
                uint32_t base = sB + bRow + (uint32_t)(ntp * 2048);
                LDSM4(bh[2 * ntp][0], bh[2 * ntp][1],
                      bh[2 * ntp + 1][0], bh[2 * ntp + 1][1],
                      base + ((cb ^ xm) << 4));
                if (NTERMS == 3) {
                    LDSM4(bl[2 * ntp][0], bl[2 * ntp][1],
                          bl[2 * ntp + 1][0], bl[2 * ntp + 1][1],
                          base + (((cb + 4) ^ xm) << 4));
                }
            }
            #pragma unroll
            for (int mt = 0; mt < 4; mt++)
                #pragma unroll
                for (int nt = 0; nt < 4; nt++) {
                    mma_f16(acc[mt][nt][0], acc[mt][nt][1],
                            acc[mt][nt][2], acc[mt][nt][3],
                            al[mt][0], al[mt][1], al[mt][2], al[mt][3],
                            bh[nt][0], bh[nt][1]);
                    if (NTERMS == 3) {
                        mma_f16(acc[mt][nt][0], acc[mt][nt][1],
                                acc[mt][nt][2], acc[mt][nt][3],
                                ah[mt][0], ah[mt][1], ah[mt][2], ah[mt][3],
                                bl[nt][0], bl[nt][1]);
                    }
                    mma_f16(acc[mt][nt][0], acc[mt][nt][1],
                            acc[mt][nt][2], acc[mt][nt][3],
                            ah[mt][0], ah[mt][1], ah[mt][2], ah[mt][3],
                            bh[nt][0], bh[nt][1]);
                }
        }
    }

    #pragma unroll
    for (int mt = 0; mt < 4; mt++) {
        #pragma unroll
        for (int nt = 0; nt < 4; nt++) {
            int col = bn + warp_n + (nt << 3) + (t << 1);
            if (col >= N) continue;
            #pragma unroll
            for (int half = 0; half < 2; half++) {
                int row = bm + warp_m + (mt << 4) + g + half * 8;
                float v0 = acc[mt][nt][half * 2];
                float v1 = acc[mt][nt][half * 2 + 1];
                size_t idx = (size_t)row * ldc + col;
                if (EPI == 0) {
                    C[idx] = v0; C[idx + 1] = v1;
                } else if (EPI == 1) {
                    C[idx] += v0; C[idx + 1] += v1;
                } else if (EPI == 2) {
                    v0 = fmaxf(v0 + bias[col], 0.f);
                    v1 = fmaxf(v1 + bias[col + 1], 0.f);
                    h16 h0, l0, h1, l1;
                    hsplit(v0, h0, l0); hsplit(v1, h1, l1);
                    Chi[idx] = h0; Chi[idx + 1] = h1;
                    Clo[idx] = l0; Clo[idx + 1] = l1;
                } else if (EPI == 3) {
                    v0 += bias[col]; v1 += bias[col + 1];
                    v0 = (v0 > 20.f) ? v0 : log1pf(__expf(v0));
                    v1 = (v1 > 20.f) ? v1 : log1pf(__expf(v1));
                    C[idx] = v0; C[idx + 1] = v1;
                } else if (EPI == 4) {
                    C[idx] = v0 + bias[col]; C[idx + 1] = v1 + bias[col + 1];
                } else {
                    C[idx] = v0; C[idx + 1] = v1;
                    h16 h0, l0, h1, l1;
                    hsplit(v0, h0, l0); hsplit(v1, h1, l1);
                    Chi[idx] = h0; Chi[idx + 1] = h1;
                    Clo[idx] = l0; Clo[idx + 1] = l1;
                }
            }
        }
    }
}

// ---------------------------------------------------------------------------
// ILP-4 split kernels (4 independent float4 loads per thread)
// ---------------------------------------------------------------------------
__global__ void split_kernel(const float4* __restrict__ src,
                             h162* __restrict__ hi2, h162* __restrict__ lo2, int n4) {
    int base = blockIdx.x * (blockDim.x * 4) + threadIdx.x;
    int bd = blockDim.x;
    float4 v[4];
    #pragma unroll
    for (int j = 0; j < 4; j++) {
        int i = base + j * bd;
        if (i < n4) v[j] = src[i];
    }
    #pragma unroll
    for (int j = 0; j < 4; j++) {
        int i = base + j * bd;
        if (i >= n4) continue;
        h16 h0, l0, h1, l1, h2, l2, h3, l3;
        hsplit(v[j].x, h0, l0); hsplit(v[j].y, h1, l1);
        hsplit(v[j].z, h2, l2); hsplit(v[j].w, h3, l3);
        h162 a; a.x = h0; a.y = h1;
        h162 b; b.x = h2; b.y = h3;
        h162 c; c.x = l0; c.y = l1;
        h162 d; d.x = l2; d.y = l3;
        hi2[i * 2] = a; hi2[i * 2 + 1] = b;
        lo2[i * 2] = c; lo2[i * 2 + 1] = d;
    }
}

// hi-only variant for 2-term weight operands (lo never read by GEMM)
__global__ void split_hi_kernel(const float4* __restrict__ src,
                                h162* __restrict__ hi2, int n4) {
    int base = blockIdx.x * (blockDim.x * 4) + threadIdx.x;
    int bd = blockDim.x;
    float4 v[4];
    #pragma unroll
    for (int j = 0; j < 4; j++) {
        int i = base + j * bd;
        if (i < n4) v[j] = src[i];
    }
    #pragma unroll
    for (int j = 0; j < 4; j++) {
        int i = base + j * bd;
        if (i >= n4) continue;
        h162 a; a.x = __float2half(v[j].x); a.y = __float2half(v[j].y);
        h162 b; b.x = __float2half(v[j].z); b.y = __float2half(v[j].w);
        hi2[i * 2] = a; hi2[i * 2 + 1] = b;
    }
}

__global__ void embed_kernel(const int* __restrict__ x, const float* __restrict__ emb,
                             const float* __restrict__ pos, float* __restrict__ out) {
    int idx = blockIdx.x * blockDim.x + threadIdx.x;
    if (idx >= ROWS * D_MODEL) return;
    int d = idx & (D_MODEL - 1), r = idx >> 10, l = r & (SEQLEN - 1);
    out[idx] = emb[x[r] * D_MODEL + d] + pos[l * D_MODEL + d];
}

// Vectorized rmsnorm: 256 threads x float4 = 1024 elements, single pass
__global__ void rmsnorm_kernel(const float* __restrict__ h, const float* __restrict__ w,
                               h16* __restrict__ oh, h16* __restrict__ ol) {
    int r = blockIdx.x, tid = threadIdx.x;
    float4 v = ((const float4*)(h + (size_t)r * D_MODEL))[tid];
    float s = v.x * v.x + v.y * v.y + v.z * v.z + v.w * v.w;
    __shared__ float red[8];
    #pragma unroll
    for (int o = 16; o > 0; o >>= 1) s += __shfl_down_sync(0xffffffffu, s, o);
    if ((tid & 31) == 0) red[tid >> 5] = s;
    __syncthreads();
    __shared__ float scale;
    if (tid == 0) {
        float tt = 0.f;
        #pragma unroll
        for (int i = 0; i < 8; i++) tt += red[i];
        scale = rsqrtf(tt * (1.0f / D_MODEL) + 1e-5f);
    }
    __syncthreads();
    float sc = scale;
    float4 wv = ((const float4*)w)[tid];
    h16 h0, l0, h1, l1, h2, l2, h3, l3;
    hsplit(v.x * sc * wv.x, h0, l0);
    hsplit(v.y * sc * wv.y, h1, l1);
    hsplit(v.z * sc * wv.z, h2, l2);
    hsplit(v.w * sc * wv.w, h3, l3);
    h162* ohp = (h162*)(oh + (size_t)r * D_MODEL) + tid * 2;
    h162* olp = (h162*)(ol + (size_t)r * D_MODEL) + tid * 2;
    h162 a; a.x = h0; a.y = h1;
    h162 b; b.x = h2; b.y = h3;
    h162 c; c.x = l0; c.y = l1;
    h162 d; d.x = l2; d.y = l3;
    ohp[0] = a; ohp[1] = b;
    olp[0] = c; olp[1] = d;
}

__global__ void conv_silu_kernel(const float* __restrict__ xz, const float* __restrict__ cw,
                                 const float* __restrict__ cb, float* __restrict__ xc,
                                 h16* __restrict__ xch, h16* __restrict__ xcl) {
    int idx = blockIdx.x * blockDim.x + threadIdx.x;
    if (idx >= ROWS * D_INNER / 4) return;
    int d4 = (idx & (D_INNER / 4 - 1)) << 2;
    int r = idx >> 9, l = r & (SEQLEN - 1);
    float4 wa = *(const float4*)(cw + d4 * 4);
    float4 wb = *(const float4*)(cw + d4 * 4 + 4);
    float4 wc = *(const float4*)(cw + d4 * 4 + 8);
    float4 wd = *(const float4*)(cw + d4 * 4 + 12);
    float4 acc = *(const float4*)(cb + d4);
    const float* base = xz + (size_t)r * (2 * D_INNER) + d4;
    if (l >= 3) { float4 x = *(const float4*)(base - 3 * 2 * D_INNER);
        acc.x = fmaf(x.x, wa.x, acc.x); acc.y = fmaf(x.y, wb.x, acc.y);
        acc.z = fmaf(x.z, wc.x, acc.z); acc.w = fmaf(x.w, wd.x, acc.w); }
    if (l >= 2) { float4 x = *(const float4*)(base - 2 * 2 * D_INNER);
        acc.x = fmaf(x.x, wa.y, acc.x); acc.y = fmaf(x.y, wb.y, acc.y);
        acc.z = fmaf(x.z, wc.y, acc.z); acc.w = fmaf(x.w, wd.y, acc.w); }
    if (l >= 1) { float4 x = *(const float4*)(base - 2 * D_INNER);
        acc.x = fmaf(x.x, wa.z, acc.x); acc.y = fmaf(x.y, wb.z, acc.y);
        acc.z = fmaf(x.z, wc.z, acc.z); acc.w = fmaf(x.w, wd.z, acc.w); }
    { float4 x = *(const float4*)(base);
        acc.x = fmaf(x.x, wa.w, acc.x); acc.y = fmaf(x.y, wb.w, acc.y);
        acc.z = fmaf(x.z, wc.w, acc.z); acc.w = fmaf(x.w, wd.w, acc.w); }
    acc.x = acc.x / (1.f + __expf(-acc.x));
    acc.y = acc.y / (1.f + __expf(-acc.y));
    acc.z = acc.z / (1.f + __expf(-acc.z));
    acc.w = acc.w / (1.f + __expf(-acc.w));
    size_t o = (size_t)r * D_INNER + d4;
    *(float4*)(xc + o) = acc;
    h16 h0, l0, h1, l1, h2, l2, h3, l3;
    hsplit(acc.x, h0, l0); hsplit(acc.y, h1, l1);
    hsplit(acc.z, h2, l2); hsplit(acc.w, h3, l3);
    h162 ph0; ph0.x = h0; ph0.y = h1;
    h162 ph1; ph1.x = h2; ph1.y = h3;
    h162 pl0; pl0.x = l0; pl0.y = l1;
    h162 pl1; pl1.x = l2; pl1.y = l3;
    *(h162*)(xch + o) = ph0; *(h162*)(xch + o + 2) = ph1;
    *(h162*)(xcl + o) = pl0; *(h162*)(xcl + o + 2) = pl1;
}

// Scan with software-pipelined loads (prefetch l+1 before computing l)
__global__ void scan_kernel(const float* __restrict__ delta, const float* __restrict__ xc,
                            const float* __restrict__ dbc, const float* __restrict__ xz,
                            const float* __restrict__ A_log, const float* __restrict__ Dp,
                            h16* __restrict__ yh, h16* __restrict__ yl) {
    int gwarp = (blockIdx.x * blockDim.x + threadIdx.x) >> 5;
    int lane = threadIdx.x & 31, n = lane & 15;
    int pair = gwarp * 2 + (lane >> 4);
    int b = pair >> 11, d = pair & (D_INNER - 1);
    if (b >= BATCH) return;
    float An = -__expf(A_log[d * D_STATE + n]);
    float Dv = Dp[d], hst = 0.f;
    size_t rbase = (size_t)b * SEQLEN;

    float dlt = delta[rbase * D_INNER + d];
    float xcv = xc[rbase * D_INNER + d];
    float Bv  = dbc[rbase * 96 + DT_RANK + n];
    float Cv  = dbc[rbase * 96 + DT_RANK + D_STATE + n];

    for (int l = 0; l < SEQLEN; l++) {
        float ndlt = 0.f, nxcv = 0.f, nBv = 0.f, nCv = 0.f;
        if (l + 1 < SEQLEN) {
            size_t rn = rbase + l + 1;
            ndlt = delta[rn * D_INNER + d];
            nxcv = xc[rn * D_INNER + d];
            nBv  = dbc[rn * 96 + DT_RANK + n];
            nCv  = dbc[rn * 96 + DT_RANK + D_STATE + n];
        }
        float dA = __expf(dlt * An);
        hst = fmaf(dA, hst, dlt * xcv * Bv);
        float y = hst * Cv;
        y += __shfl_xor_sync(0xffffffffu, y, 1);
        y += __shfl_xor_sync(0xffffffffu, y, 2);
        y += __shfl_xor_sync(0xffffffffu, y, 4);
        y += __shfl_xor_sync(0xffffffffu, y, 8);
        if (n == 0) {
            size_t r = rbase + l;
            float zv = xz[r * (2 * D_INNER) + D_INNER + d];
            float sz = zv / (1.f + __expf(-zv));
            h16 hh, ll;
            hsplit((y + Dv * xcv) * sz, hh, ll);
            yh[r * D_INNER + d] = hh;
            yl[r * D_INNER + d] = ll;
        }
        dlt = ndlt; xcv = nxcv; Bv = nBv; Cv = nCv;
    }
}

__global__ void cls_kernel(const float* __restrict__ h,
                           const float* __restrict__ w1, const float* __restrict__ b1,
                           const float* __restrict__ w2, const float* __restrict__ b2,
                           float* __restrict__ out) {
    __shared__ float sh[D_MODEL];
    __shared__ float t1[D_MODEL];
    __shared__ float red[256];
    int b = blockIdx.x, tid = threadIdx.x;
    const float* row = h + ((size_t)b * SEQLEN + (SEQLEN - 1)) * D_MODEL;
    for (int i = tid; i < D_MODEL; i += 256) sh[i] = row[i];
    __syncthreads();
    for (int e = tid; e < D_MODEL; e += 256) {
        const float* wr = w1 + (size_t)e * D_MODEL;
        float acc = b1[e];
        #pragma unroll 4
        for (int k = 0; k < D_MODEL; k += 4) {
            float4 w4 = *(const float4*)(wr + k);
            acc = fmaf(sh[k], w4.x, acc); acc = fmaf(sh[k + 1], w4.y, acc);
            acc = fmaf(sh[k + 2], w4.z, acc); acc = fmaf(sh[k + 3], w4.w, acc);
        }
        t1[e] = acc > 0.f ? acc : 0.f;
    }
    __syncthreads();
    for (int c = 0; c < NUM_CLS; c++) {
        float p = 0.f;
        for (int k = tid; k < D_MODEL; k += 256) p = fmaf(t1[k], w2[c * D_MODEL + k], p);
        red[tid] = p;
        __syncthreads();
        for (int s = 128; s > 0; s >>= 1) { if (tid < s) red[tid] += red[tid + s]; __syncthreads(); }
        if (tid == 0) out[b * NUM_CLS + c] = red[0] + b2[c];
        __syncthreads();
    }
}

// ---------------------------------------------------------------------------
// Launch
// ---------------------------------------------------------------------------
#define MMA_SMEM (NSTG * STGB)

extern "C" void kernel_launch(void* const* d_in, const int* in_sizes, int n_in,
                              void* d_out, int out_size)
{
    const int*   x_tok      = (const int*)d_in[0];
    const float* embedding  = (const float*)d_in[1];
    const float* pos_enc    = (const float*)d_in[2];
    const float* norm_w     = (const float*)d_in[3];
    const float* in_proj_w  = (const float*)d_in[4];
    const float* conv_w     = (const float*)d_in[5];
    const float* conv_b     = (const float*)d_in[6];
    const float* x_proj_w   = (const float*)d_in[7];
    const float* dt_proj_w  = (const float*)d_in[8];
    const float* dt_proj_b  = (const float*)d_in[9];
    const float* A_log      = (const float*)d_in[10];
    const float* Dp         = (const float*)d_in[11];
    const float* out_proj_w = (const float*)d_in[12];
    const float* cls_fc1_w  = (const float*)d_in[13];
    const float* cls_fc1_b  = (const float*)d_in[14];
    const float* cls_fc2_w  = (const float*)d_in[15];
    const float* cls_fc2_b  = (const float*)d_in[16];
    const float* dec_fc1_w  = (const float*)d_in[17];
    const float* dec_fc1_b  = (const float*)d_in[18];
    const float* dec_fc2_w  = (const float*)d_in[19];
    const float* dec_fc2_b  = (const float*)d_in[20];

    float *h, *xz, *xc, *dbc, *delta;
    h16 *xn_h, *xn_l, *xc_h, *xc_l, *dbc_h, *dbc_l, *y_h, *y_l, *hs_h, *hs_l, *t_h, *t_l;
    h16 *win_h, *win_l, *wout_h, *wout_l, *wxp_h, *wxp_l, *wdt_h, *wdt_l, *wd1_h, *wd1_l, *wd2_h, *wd2_l;
    cudaGetSymbolAddress((void**)&h, g_h);
    cudaGetSymbolAddress((void**)&xz, g_xz);
    cudaGetSymbolAddress((void**)&xc, g_xc);
    cudaGetSymbolAddress((void**)&dbc, g_dbc);
    cudaGetSymbolAddress((void**)&delta, g_delta);
    cudaGetSymbolAddress((void**)&xn_h, g_xn_h);  cudaGetSymbolAddress((void**)&xn_l, g_xn_l);
    cudaGetSymbolAddress((void**)&xc_h, g_xc_h);  cudaGetSymbolAddress((void**)&xc_l, g_xc_l);
    cudaGetSymbolAddress((void**)&dbc_h, g_dbc_h); cudaGetSymbolAddress((void**)&dbc_l, g_dbc_l);
    cudaGetSymbolAddress((void**)&y_h, g_y_h);    cudaGetSymbolAddress((void**)&y_l, g_y_l);
    cudaGetSymbolAddress((void**)&hs_h, g_hs_h);  cudaGetSymbolAddress((void**)&hs_l, g_hs_l);
    cudaGetSymbolAddress((void**)&t_h, g_t_h);    cudaGetSymbolAddress((void**)&t_l, g_t_l);
    cudaGetSymbolAddress((void**)&win_h, g_win_h);   cudaGetSymbolAddress((void**)&win_l, g_win_l);
    cudaGetSymbolAddress((void**)&wout_h, g_wout_h); cudaGetSymbolAddress((void**)&wout_l, g_wout_l);
    cudaGetSymbolAddress((void**)&wxp_h, g_wxp_h);   cudaGetSymbolAddress((void**)&wxp_l, g_wxp_l);
    cudaGetSymbolAddress((void**)&wdt_h, g_wdt_h);   cudaGetSymbolAddress((void**)&wdt_l, g_wdt_l);
    cudaGetSymbolAddress((void**)&wd1_h, g_wd1_h);   cudaGetSymbolAddress((void**)&wd1_l, g_wd1_l);
    cudaGetSymbolAddress((void**)&wd2_h, g_wd2_h);   cudaGetSymbolAddress((void**)&wd2_l, g_wd2_l);

    cudaFuncSetAttribute(mma_gemm<0, 2>, cudaFuncAttributeMaxDynamicSharedMemorySize, MMA_SMEM);
    cudaFuncSetAttribute(mma_gemm<1, 2>, cudaFuncAttributeMaxDynamicSharedMemorySize, MMA_SMEM);
    cudaFuncSetAttribute(mma_gemm<2, 2>, cudaFuncAttributeMaxDynamicSharedMemorySize, MMA_SMEM);
    cudaFuncSetAttribute(mma_gemm<5, 3>, cudaFuncAttributeMaxDynamicSharedMemorySize, MMA_SMEM);
    cudaFuncSetAttribute(mma_gemm<3, 3>, cudaFuncAttributeMaxDynamicSharedMemorySize, MMA_SMEM);
    cudaFuncSetAttribute(mma_gemm<4, 3>, cudaFuncAttributeMaxDynamicSharedMemorySize, MMA_SMEM);

    float* out_dec = (float*)d_out;
    float* out_cls = (float*)d_out + ROWS * VOCAB;

    // Weight preprocessing: hi-only for 2-term operands, full split for 3-term
    int n;
    n = N_LAYERS * 2 * D_INNER * D_MODEL / 4;
    split_hi_kernel<<<(n + 1023) / 1024, 256>>>((const float4*)in_proj_w, (h162*)win_h, n);
    n = N_LAYERS * D_MODEL * D_INNER / 4;
    split_hi_kernel<<<(n + 1023) / 1024, 256>>>((const float4*)out_proj_w, (h162*)wout_h, n);
    n = D_MODEL * D_MODEL / 4;
    split_hi_kernel<<<(n + 1023) / 1024, 256>>>((const float4*)dec_fc1_w, (h162*)wd1_h, n);
    n = N_LAYERS * 96 * D_INNER / 4;
    split_kernel<<<(n + 1023) / 1024, 256>>>((const float4*)x_proj_w, (h162*)wxp_h, (h162*)wxp_l, n);
    n = N_LAYERS * D_INNER * DT_RANK / 4;
    split_kernel<<<(n + 1023) / 1024, 256>>>((const float4*)dt_proj_w, (h162*)wdt_h, (h162*)wdt_l, n);
    n = VOCAB * D_MODEL / 4;
    split_kernel<<<(n + 1023) / 1024, 256>>>((const float4*)dec_fc2_w, (h162*)wd2_h, (h162*)wd2_l, n);

    embed_kernel<<<(ROWS * D_MODEL + 255) / 256, 256>>>(x_tok, embedding, pos_enc, h);

    for (int l = 0; l < N_LAYERS; l++) {
        const h16* inw_h = win_h + (size_t)l * 2 * D_INNER * D_MODEL;
        const h16* inw_l = win_l + (size_t)l * 2 * D_INNER * D_MODEL;
        const float* cw  = conv_w + (size_t)l * D_INNER * 4;
        const float* cb  = conv_b + (size_t)l * D_INNER;
        const h16* xpw_h = wxp_h + (size_t)l * 96 * D_INNER;
        const h16* xpw_l = wxp_l + (size_t)l * 96 * D_INNER;
        const h16* dtw_h = wdt_h + (size_t)l * D_INNER * DT_RANK;
        const h16* dtw_l = wdt_l + (size_t)l * D_INNER * DT_RANK;
        const float* dtb = dt_proj_b + (size_t)l * D_INNER;
        const float* al  = A_log + (size_t)l * D_INNER * D_STATE;
        const float* dp  = Dp + (size_t)l * D_INNER;
        const h16* ow_h = wout_h + (size_t)l * D_MODEL * D_INNER;
        const h16* ow_l = wout_l + (size_t)l * D_MODEL * D_INNER;
        const float* nw  = norm_w + (size_t)l * D_MODEL;

        rmsnorm_kernel<<<ROWS, 256>>>(h, nw, xn_h, xn_l);
        // xz = xn @ in_w^T      (4096 x 4096 x 1024)  2-term
        mma_gemm<0, 2><<<dim3(2 * D_INNER / 128, ROWS / 128), 256, MMA_SMEM>>>(
            xn_h, xn_l, D_MODEL, inw_h, inw_l, D_MODEL,
            xz, nullptr, nullptr, 2 * D_INNER, 2 * D_INNER, D_MODEL, nullptr);
        conv_silu_kernel<<<(ROWS * D_INNER / 4 + 255) / 256, 256>>>(xz, cw, cb, xc, xc_h, xc_l);
        // dbc = xc @ xp_w^T     (4096 x 96 x 2048) -> fp32 + split  3-term
        mma_gemm<5, 3><<<dim3(1, ROWS / 128), 256, MMA_SMEM>>>(
            xc_h, xc_l, D_INNER, xpw_h, xpw_l, D_INNER,
            dbc, dbc_h, dbc_l, 96, 96, D_INNER, nullptr);
        // delta = softplus(dbc[:, :64] @ dt_w^T + dtb)   (4096 x 2048 x 64)  3-term
        mma_gemm<3, 3><<<dim3(D_INNER / 128, ROWS / 128), 256, MMA_SMEM>>>(
            dbc_h, dbc_l, 96, dtw_h, dtw_l, DT_RANK,
            delta, nullptr, nullptr, D_INNER, D_INNER, DT_RANK, dtb);
        scan_kernel<<<(BATCH * D_INNER / 2) / 8, 256>>>(delta, xc, dbc, xz, al, dp, y_h, y_l);
        // h += y @ out_w^T      (4096 x 1024 x 2048)  2-term
        mma_gemm<1, 2><<<dim3(D_MODEL / 128, ROWS / 128), 256, MMA_SMEM>>>(
            y_h, y_l, D_INNER, ow_h, ow_l, D_INNER,
            h, nullptr, nullptr, D_MODEL, D_MODEL, D_INNER, nullptr);
    }

    // dec MLP: split h, fc1 (relu+bias -> split, 2-term), fc2 (+bias, 3-term)
    n = ROWS * D_MODEL / 4;
    split_kernel<<<(n + 1023) / 1024, 256>>>((const float4*)h, (h162*)hs_h, (h162*)hs_l, n);
    mma_gemm<2, 2><<<dim3(D_MODEL / 128, ROWS / 128), 256, MMA_SMEM>>>(
        hs_h, hs_l, D_MODEL, wd1_h, wd1_l, D_MODEL,
        nullptr, t_h, t_l, D_MODEL, D_MODEL, D_MODEL, dec_fc1_b);
    mma_gemm<4, 3><<<dim3(1, ROWS / 128), 256, MMA_SMEM>>>(
        t_h, t_l, D_MODEL, wd2_h, wd2_l, D_MODEL,
        out_dec, nullptr, nullptr, VOCAB, VOCAB, D_MODEL, dec_fc2_b);

    cls_kernel<<<BATCH, 256>>>(h, cls_fc1_w, cls_fc1_b, cls_fc2_w, cls_fc2_b, out_cls);
}